// round 6
// baseline (speedup 1.0000x reference)
#include <cuda_runtime.h>
#include <math.h>

#define Nn 10000
#define Ee 160000
#define Gg 100
#define Ll 5
#define NTILES 2500

typedef unsigned long long u64;

// ---------------- scratch (device globals) ----------------
__device__ float g_feat [Nn*128];
__device__ float g_featA[Nn*128];
__device__ float g_featB[Nn*128];
__device__ float g_sh   [Nn*9];
__device__ float g_pos  [Nn*3];
__device__ float g_msum [Nn*128];
__device__ float g_psum [Nn*3];
__device__ float g_ssum [Nn*9];
__device__ float g_deg  [Nn];
__device__ float g_com  [Gg*3];
__device__ float g_cnt  [Gg];
__device__ float g_P1   [10*128];
__device__ float g_P2   [10*128];
__device__ float g_cmsg [10];
__device__ float g_pool [Gg*140];
__device__ float g_m    [(size_t)Ee*128];
__device__ int   g_off  [Nn];
__device__ int   g_cursor[Nn];
__device__ int   g_er   [Ee];
__device__ int   g_ec   [Ee];

__device__ __forceinline__ float silu_f(float x) { return x / (1.0f + __expf(-x)); }

__device__ __forceinline__ void sph2(float vx, float vy, float vz, float* o) {
    const float S3  = 1.7320508075688772f;
    const float HS3 = 0.8660254037844386f;
    float r = sqrtf(vx*vx + vy*vy + vz*vz);
    float inv = 1.0f / fmaxf(r, 1e-12f);
    float x = vx*inv, y = vy*inv, z = vz*inv;
    o[0] = S3*x*z;
    o[1] = S3*x*y;
    o[2] = y*y - 0.5f*(x*x + z*z);
    o[3] = S3*y*z;
    o[4] = HS3*(z*z - x*x);
}

// ---------------- packed f32x2 primitives ----------------
__device__ __forceinline__ u64 fma2(u64 a, u64 b, u64 c) {
    u64 d;
    asm("fma.rn.f32x2 %0, %1, %2, %3;" : "=l"(d) : "l"(a), "l"(b), "l"(c));
    return d;
}
__device__ __forceinline__ u64 pk2(float x) {
    u64 d;
    asm("mov.b64 %0, {%1, %1};" : "=l"(d) : "r"(__float_as_uint(x)));
    return d;
}
__device__ __forceinline__ float2 up2(u64 v) {
    float2 f;
    asm("mov.b64 {%0, %1}, %2;" : "=f"(f.x), "=f"(f.y) : "l"(v));
    return f;
}

// ---- GEMM core: RPW rows (broadcast a), 4 cols/thread, stride 128, no-zero acc ----
template<int RPW>
__device__ __forceinline__ void mmk(const float* __restrict__ As,
                                    const float* __restrict__ Ws,
                                    int r0, int c0, u64 acc[RPW][2]) {
    const float* ap = As + r0*128;
    const float* wp = Ws + c0;
    #pragma unroll 4
    for (int k0 = 0; k0 < 128; k0 += 2) {
        float2 a2[RPW];
        #pragma unroll
        for (int i = 0; i < RPW; i++)
            a2[i] = *(const float2*)(ap + i*128 + k0);
        ulonglong2 p0 = *(const ulonglong2*)(wp + k0*128);
        ulonglong2 q0 = *(const ulonglong2*)(wp + (k0+1)*128);
        #pragma unroll
        for (int i = 0; i < RPW; i++) {
            u64 ax = pk2(a2[i].x);
            acc[i][0] = fma2(ax, p0.x, acc[i][0]);
            acc[i][1] = fma2(ax, p0.y, acc[i][1]);
        }
        #pragma unroll
        for (int i = 0; i < RPW; i++) {
            u64 ay = pk2(a2[i].y);
            acc[i][0] = fma2(ay, q0.x, acc[i][0]);
            acc[i][1] = fma2(ay, q0.y, acc[i][1]);
        }
    }
}

// ---------------- init kernels ----------------
__global__ void node_init_kernel(const int* __restrict__ atoms, const float* __restrict__ emb) {
    int idx = blockIdx.x*256 + threadIdx.x;
    int i = idx >> 7, d = idx & 127;
    g_feat[idx] = emb[atoms[i]*128 + d];
}

__global__ void com_kernel(const int* __restrict__ batch) {
    int i = blockIdx.x*256 + threadIdx.x;
    if (i >= Nn) return;
    int b = batch[i];
    atomicAdd(&g_com[b*3+0], g_pos[i*3+0]);
    atomicAdd(&g_com[b*3+1], g_pos[i*3+1]);
    atomicAdd(&g_com[b*3+2], g_pos[i*3+2]);
    atomicAdd(&g_cnt[b], 1.0f);
}

__global__ void deg_kernel(const int* __restrict__ ei) {
    int e = blockIdx.x*256 + threadIdx.x;
    if (e >= Ee) return;
    atomicAdd(&g_deg[ei[e]], 1.0f);
}

// exclusive prefix scan of deg -> g_off (single block)
__global__ void scan_kernel() {
    __shared__ int part[256];
    int tid = threadIdx.x;
    int lo = tid*40, hi = (lo + 40 < Nn) ? lo + 40 : Nn;
    int s = 0;
    for (int i = lo; i < hi; i++) s += (int)g_deg[i];
    part[tid] = s;
    __syncthreads();
    for (int off = 1; off < 256; off <<= 1) {
        int v = part[tid] + ((tid >= off) ? part[tid - off] : 0);
        __syncthreads();
        part[tid] = v;
        __syncthreads();
    }
    int base = (tid > 0) ? part[tid - 1] : 0;
    for (int i = lo; i < hi; i++) {
        g_off[i] = base;
        base += (int)g_deg[i];
    }
}

__global__ void sortscatter_kernel(const int* __restrict__ ei) {
    int e = blockIdx.x*256 + threadIdx.x;
    if (e >= Ee) return;
    int r = ei[e], c = ei[Ee + e];
    int p = g_off[r] + atomicAdd(&g_cursor[r], 1);
    g_er[p] = r;
    g_ec[p] = c;
}

__global__ void vocab_kernel(const float* __restrict__ emb, const float* __restrict__ Wsi1,
                             const float* __restrict__ WsiC1, const float* __restrict__ bsiC1,
                             const float* __restrict__ WsiC2, const float* __restrict__ bsiC2) {
    __shared__ float es[128];
    __shared__ float redv[128];
    int v = blockIdx.x, j = threadIdx.x;
    es[j] = emb[v*128 + j];
    __syncthreads();
    float p1 = 0.f, p2 = 0.f, hc = 0.f;
    for (int k = 0; k < 128; k++) {
        float e = es[k];
        p1 = fmaf(e, Wsi1[(1 + k)*128 + j], p1);
        p2 = fmaf(e, Wsi1[(129 + k)*128 + j], p2);
        hc = fmaf(e, WsiC1[k*128 + j], hc);
    }
    g_P1[v*128 + j] = p1;
    g_P2[v*128 + j] = p2;
    hc = silu_f(hc + bsiC1[j]);
    redv[j] = hc * WsiC2[j*3 + 2];
    __syncthreads();
    for (int s = 64; s > 0; s >>= 1) {
        if (j < s) redv[j] += redv[j + s];
        __syncthreads();
    }
    if (j == 0) g_cmsg[v] = redv[0] + bsiC2[2];
}

__global__ void edge_init_kernel(const int* __restrict__ atoms,
                                 const float* __restrict__ Wsi1, const float* __restrict__ bsi1,
                                 const float* __restrict__ Wsi2, const float* __restrict__ bsi2) {
    int e = blockIdx.x*8 + (threadIdx.x >> 5);
    int lane = threadIdx.x & 31;
    int r = g_er[e], c = g_ec[e];
    float dp0 = g_pos[r*3+0] - g_pos[c*3+0];
    float dp1 = g_pos[r*3+1] - g_pos[c*3+1];
    float dp2 = g_pos[r*3+2] - g_pos[c*3+2];
    float dist = sqrtf(dp0*dp0 + dp1*dp1 + dp2*dp2);
    int ar = atoms[r], ac = atoms[c];
    float partial = 0.f;
    #pragma unroll
    for (int q = 0; q < 4; q++) {
        int d = lane + q*32;
        float h = silu_f(dist*Wsi1[d] + g_P1[ar*128 + d] + g_P2[ac*128 + d] + bsi1[d]);
        partial = fmaf(h, Wsi2[d*3 + 2], partial);
    }
    #pragma unroll
    for (int off = 16; off > 0; off >>= 1)
        partial += __shfl_xor_sync(0xffffffffu, partial, off);
    if (lane == 0) {
        float msg2 = partial + bsi2[2];
        float y2[5];
        sph2(dp0, dp1, dp2, y2);
        #pragma unroll
        for (int q = 0; q < 5; q++)
            atomicAdd(&g_ssum[r*9 + 4 + q], y2[q]*msg2);
    }
}

__global__ void sh_init_kernel(const int* __restrict__ atoms, const int* __restrict__ batch) {
    int i = blockIdx.x*256 + threadIdx.x;
    if (i >= Nn) return;
    float dg = fmaxf(g_deg[i], 1.0f);
    int b = batch[i];
    float cn = fmaxf(g_cnt[b], 1.0f);
    float vx = g_pos[i*3+0] - g_com[b*3+0]/cn;
    float vy = g_pos[i*3+1] - g_com[b*3+1]/cn;
    float vz = g_pos[i*3+2] - g_com[b*3+2]/cn;
    float y2[5];
    sph2(vx, vy, vz, y2);
    float cm = g_cmsg[atoms[i]];
    #pragma unroll
    for (int q = 0; q < 4; q++) g_sh[i*9 + q] = 0.0f;
    #pragma unroll
    for (int q = 0; q < 5; q++)
        g_sh[i*9 + 4 + q] = g_ssum[i*9 + 4 + q]/dg + cm*y2[q];
}

// ============ featAB: featA = feat@Wa, featB = feat@Wb (shared A tile) =======
// smem: As 64*128 + Wa 128*128 + Wb 128*128 = 40960 floats = 160KB
#define FAB_SMEM ((64*128 + 2*128*128)*4)
__global__ void __launch_bounds__(256)
featab_kernel(const float* __restrict__ Wa, const float* __restrict__ Wb) {
    extern __shared__ float sm[];
    float* As  = sm;
    float* Was = As + 64*128;
    float* Wbs = Was + 128*128;
    int tid = threadIdx.x;
    int row0 = blockIdx.x * 64;

    for (int idx = tid; idx < 64*32; idx += 256) {
        int r = idx >> 5, c4 = (idx & 31) * 4;
        float4 v = make_float4(0.f, 0.f, 0.f, 0.f);
        if (row0 + r < Nn) v = *(const float4*)(g_feat + (size_t)(row0 + r)*128 + c4);
        *(float4*)(As + r*128 + c4) = v;
    }
    for (int idx = tid; idx < 128*32; idx += 256) {
        *(float4*)(Was + idx*4) = *(const float4*)(Wa + (size_t)idx*4);
        *(float4*)(Wbs + idx*4) = *(const float4*)(Wb + (size_t)idx*4);
    }
    __syncthreads();

    int ty = tid >> 5, tx = tid & 31;
    int r0 = ty*8, c0 = tx*4;
    u64 acc[8][2];
    #pragma unroll
    for (int i = 0; i < 8; i++) { acc[i][0] = 0ull; acc[i][1] = 0ull; }
    mmk<8>(As, Was, r0, c0, acc);
    #pragma unroll
    for (int i = 0; i < 8; i++) {
        int r = row0 + r0 + i;
        if (r >= Nn) continue;
        float2 f0 = up2(acc[i][0]), f1 = up2(acc[i][1]);
        *(float4*)(g_featA + (size_t)r*128 + c0) = make_float4(f0.x, f0.y, f1.x, f1.y);
    }
    #pragma unroll
    for (int i = 0; i < 8; i++) { acc[i][0] = 0ull; acc[i][1] = 0ull; }
    mmk<8>(As, Wbs, r0, c0, acc);
    #pragma unroll
    for (int i = 0; i < 8; i++) {
        int r = row0 + r0 + i;
        if (r >= Nn) continue;
        float2 f0 = up2(acc[i][0]), f1 = up2(acc[i][1]);
        *(float4*)(g_featB + (size_t)r*128 + c0) = make_float4(f0.x, f0.y, f1.x, f1.y);
    }
}

// ============ node update: feat = silu(feat@W5 + (msum/deg)@W6 + b1)@W7 + b2 =
// smem: A1 32K + A2 32K + Wx 64K + Wy 64K + biases = 192K+
#define NU_SMEM ((2*64*128 + 2*128*128 + 256)*4)
__global__ void __launch_bounds__(256)
nodeup_kernel(const float* __restrict__ W5, const float* __restrict__ W6,
              const float* __restrict__ W7,
              const float* __restrict__ b1, const float* __restrict__ b2) {
    extern __shared__ float sm[];
    float* A1  = sm;                 // 64*128 (feat, later H)
    float* A2  = A1 + 64*128;        // 64*128 (msum/deg)
    float* Wx  = A2 + 64*128;        // 128*128 (W5, later W7)
    float* Wy  = Wx + 128*128;       // 128*128 (W6)
    float* bb  = Wy + 128*128;       // 256
    int tid = threadIdx.x;
    int row0 = blockIdx.x * 64;

    for (int idx = tid; idx < 64*32; idx += 256) {
        int r = idx >> 5, c4 = (idx & 31) * 4;
        float4 v1 = make_float4(0.f,0.f,0.f,0.f), v2 = v1;
        if (row0 + r < Nn) {
            v1 = *(const float4*)(g_feat + (size_t)(row0 + r)*128 + c4);
            v2 = *(const float4*)(g_msum + (size_t)(row0 + r)*128 + c4);
            float inv = 1.0f / fmaxf(g_deg[row0 + r], 1.0f);
            v2.x *= inv; v2.y *= inv; v2.z *= inv; v2.w *= inv;
        }
        *(float4*)(A1 + r*128 + c4) = v1;
        *(float4*)(A2 + r*128 + c4) = v2;
    }
    for (int idx = tid; idx < 128*32; idx += 256) {
        *(float4*)(Wx + idx*4) = *(const float4*)(W5 + (size_t)idx*4);
        *(float4*)(Wy + idx*4) = *(const float4*)(W6 + (size_t)idx*4);
    }
    if (tid < 128) { bb[tid] = b1[tid]; bb[128 + tid] = b2[tid]; }
    __syncthreads();

    int ty = tid >> 5, tx = tid & 31;
    int r0 = ty*8, c0 = tx*4;
    u64 acc[8][2];
    #pragma unroll
    for (int i = 0; i < 8; i++) { acc[i][0] = 0ull; acc[i][1] = 0ull; }
    mmk<8>(A1, Wx, r0, c0, acc);
    mmk<8>(A2, Wy, r0, c0, acc);
    __syncthreads();   // done reading A1
    #pragma unroll
    for (int i = 0; i < 8; i++) {
        float2 f0 = up2(acc[i][0]), f1 = up2(acc[i][1]);
        A1[(r0 + i)*128 + c0 + 0] = silu_f(f0.x + bb[c0]);
        A1[(r0 + i)*128 + c0 + 1] = silu_f(f0.y + bb[c0+1]);
        A1[(r0 + i)*128 + c0 + 2] = silu_f(f1.x + bb[c0+2]);
        A1[(r0 + i)*128 + c0 + 3] = silu_f(f1.y + bb[c0+3]);
    }
    for (int idx = tid; idx < 128*32; idx += 256)
        *(float4*)(Wx + idx*4) = *(const float4*)(W7 + (size_t)idx*4);
    __syncthreads();

    #pragma unroll
    for (int i = 0; i < 8; i++) { acc[i][0] = 0ull; acc[i][1] = 0ull; }
    mmk<8>(A1, Wx, r0, c0, acc);
    #pragma unroll
    for (int i = 0; i < 8; i++) {
        int r = row0 + r0 + i;
        if (r >= Nn) continue;
        float2 f0 = up2(acc[i][0]), f1 = up2(acc[i][1]);
        *(float4*)(g_feat + (size_t)r*128 + c0) =
            make_float4(f0.x + bb[128+c0], f0.y + bb[128+c0+1],
                        f1.x + bb[128+c0+2], f1.y + bb[128+c0+3]);
    }
}

// ============ E1: persistent h-build + m-GEMM (sorted edges) =================
// smem: Wm2 64K + h 32K + wtl 2.5K + scal 1K + bh 0.5K + idx 0.5K ≈ 100.7K → 2 blocks/SM
#define E1_SMEM ((128*128 + 64*128 + 640 + 256 + 128)*4 + 128*4)
__global__ void __launch_bounds__(256)
edge_hm_kernel(const float* __restrict__ Wm2, const float* __restrict__ bm2l,
               const float* __restrict__ Wm1tail, const float* __restrict__ bm1l) {
    extern __shared__ float sm[];
    float* Wt   = sm;                 // 128*128
    float* h_s  = Wt + 128*128;       // 64*128
    float* wtl  = h_s + 64*128;       // 640
    float* scal = wtl + 640;          // 256
    float* bh   = scal + 256;         // 128
    int*   ridx = (int*)(bh + 128);   // 64
    int*   cidx = ridx + 64;          // 64

    int tid = threadIdx.x;
    for (int idx = tid; idx < 128*32; idx += 256)
        *(float4*)(Wt + idx*4) = *(const float4*)(Wm2 + (size_t)idx*4);
    if (tid < 128) bh[tid] = bm2l[tid];
    for (int idx = tid; idx < 640; idx += 256)
        wtl[idx] = (idx < 512) ? Wm1tail[idx] : bm1l[idx - 512];

    int ty = tid >> 5, tx = tid & 31;
    int r0 = ty*8, c0 = tx*4;

    for (int t = blockIdx.x; t < NTILES; t += gridDim.x) {
        int e0 = t*64;
        __syncthreads();
        if (tid < 64) {
            int r = g_er[e0 + tid], c = g_ec[e0 + tid];
            ridx[tid] = r; cidx[tid] = c;
            float dp0 = g_pos[r*3+0] - g_pos[c*3+0];
            float dp1 = g_pos[r*3+1] - g_pos[c*3+1];
            float dp2 = g_pos[r*3+2] - g_pos[c*3+2];
            float d2 = dp0*dp0 + dp1*dp1 + dp2*dp2;
            float ip0 = g_sh[r*9+0]*g_sh[c*9+0];
            float ip1 = g_sh[r*9+1]*g_sh[c*9+1] + g_sh[r*9+2]*g_sh[c*9+2] + g_sh[r*9+3]*g_sh[c*9+3];
            float ip2 = 0.f;
            #pragma unroll
            for (int q = 4; q < 9; q++) ip2 += g_sh[r*9+q]*g_sh[c*9+q];
            scal[tid*4+0] = d2; scal[tid*4+1] = ip0; scal[tid*4+2] = ip1; scal[tid*4+3] = ip2;
        }
        __syncthreads();
        // h-build: batch loads first (MLP), then compute
        {
            float4 fa[8], fb[8];
            #pragma unroll
            for (int q = 0; q < 8; q++) {
                int idx = tid + q*256;
                int e = idx >> 5, c4 = (idx & 31) * 4;
                fa[q] = *(const float4*)(g_featA + (size_t)ridx[e]*128 + c4);
                fb[q] = *(const float4*)(g_featB + (size_t)cidx[e]*128 + c4);
            }
            #pragma unroll
            for (int q = 0; q < 8; q++) {
                int idx = tid + q*256;
                int e = idx >> 5, c4 = (idx & 31) * 4;
                float d2 = scal[e*4+0], i0 = scal[e*4+1], i1 = scal[e*4+2], i2 = scal[e*4+3];
                float4 o;
                o.x = silu_f(fa[q].x + fb[q].x + d2*wtl[c4+0] + i0*wtl[128+c4+0] + i1*wtl[256+c4+0] + i2*wtl[384+c4+0] + wtl[512+c4+0]);
                o.y = silu_f(fa[q].y + fb[q].y + d2*wtl[c4+1] + i0*wtl[128+c4+1] + i1*wtl[256+c4+1] + i2*wtl[384+c4+1] + wtl[512+c4+1]);
                o.z = silu_f(fa[q].z + fb[q].z + d2*wtl[c4+2] + i0*wtl[128+c4+2] + i1*wtl[256+c4+2] + i2*wtl[384+c4+2] + wtl[512+c4+2]);
                o.w = silu_f(fa[q].w + fb[q].w + d2*wtl[c4+3] + i0*wtl[128+c4+3] + i1*wtl[256+c4+3] + i2*wtl[384+c4+3] + wtl[512+c4+3]);
                *(float4*)(h_s + e*128 + c4) = o;
            }
        }
        __syncthreads();
        u64 acc[8][2];
        #pragma unroll
        for (int i = 0; i < 8; i++) { acc[i][0] = 0ull; acc[i][1] = 0ull; }
        mmk<8>(h_s, Wt, r0, c0, acc);
        // store m + segmented RED into msum (sorted rows)
        float4 aggv = make_float4(0.f, 0.f, 0.f, 0.f);
        int agg_r = ridx[r0];
        #pragma unroll
        for (int i = 0; i < 8; i++) {
            int e = r0 + i;
            float2 f0 = up2(acc[i][0]);
            float2 f1 = up2(acc[i][1]);
            float4 mv;
            mv.x = silu_f(f0.x + bh[c0]);
            mv.y = silu_f(f0.y + bh[c0+1]);
            mv.z = silu_f(f1.x + bh[c0+2]);
            mv.w = silu_f(f1.y + bh[c0+3]);
            *(float4*)(g_m + (size_t)(e0 + e)*128 + c0) = mv;
            int r = ridx[e];
            if (r != agg_r) {
                float* dst = g_msum + (size_t)agg_r*128 + c0;
                asm volatile("red.global.add.v4.f32 [%0], {%1, %2, %3, %4};"
                             :: "l"(dst), "f"(aggv.x), "f"(aggv.y), "f"(aggv.z), "f"(aggv.w)
                             : "memory");
                aggv = mv; agg_r = r;
            } else {
                aggv.x += mv.x; aggv.y += mv.y; aggv.z += mv.z; aggv.w += mv.w;
            }
        }
        {
            float* dst = g_msum + (size_t)agg_r*128 + c0;
            asm volatile("red.global.add.v4.f32 [%0], {%1, %2, %3, %4};"
                         :: "l"(dst), "f"(aggv.x), "f"(aggv.y), "f"(aggv.z), "f"(aggv.w)
                         : "memory");
        }
    }
}

// ============ E2: persistent p+s GEMMs (512 threads, double-buffered m) ======
// smem: Wp 64K + Ws 64K + mb 2*32K + misc ≈ 195K → 1 block/SM
#define E2_SMEM ((2*128*128 + 2*64*128 + 768)*4)
__global__ void __launch_bounds__(512)
edge_ps_kernel(const float* __restrict__ Wk_p1, const float* __restrict__ bp1l,
               const float* __restrict__ Wp2l,  const float* __restrict__ bp2l,
               const float* __restrict__ Wk_s1, const float* __restrict__ bs1l,
               const float* __restrict__ Ws2l,  const float* __restrict__ bs2l) {
    extern __shared__ float sm[];
    float* Wp  = sm;                 // 128*128
    float* Ws  = Wp + 128*128;       // 128*128
    float* mb  = Ws + 128*128;       // 2*64*128
    float* bhp = mb + 2*64*128;      // 128
    float* bhs = bhp + 128;          // 128
    float* w2p = bhs + 128;          // 128
    float* w2s = w2p + 128;          // 384

    int tid = threadIdx.x;
    for (int idx = tid; idx < 128*32; idx += 512) {
        *(float4*)(Wp + idx*4) = *(const float4*)(Wk_p1 + (size_t)idx*4);
        *(float4*)(Ws + idx*4) = *(const float4*)(Wk_s1 + (size_t)idx*4);
    }
    if (tid < 128) {
        bhp[tid] = bp1l[tid];
        bhs[tid] = bs1l[tid];
        w2p[tid] = Wp2l[tid];
        w2s[tid*3+0] = Ws2l[tid*3+0];
        w2s[tid*3+1] = Ws2l[tid*3+1];
        w2s[tid*3+2] = Ws2l[tid*3+2];
    }

    unsigned mb_u32 = (unsigned)__cvta_generic_to_shared(mb);
    int w = tid >> 5, tx = tid & 31;
    int r0 = w*4, c0 = tx*4;
    int stride = gridDim.x;
    int t0 = blockIdx.x;

    if (t0 < NTILES) {
        int e0 = t0*64;
        #pragma unroll
        for (int q = 0; q < 4; q++) {
            int chunk = tid + q*512;
            const float* src = g_m + (size_t)e0*128 + chunk*4;
            unsigned dst = mb_u32 + (unsigned)chunk*16u;
            asm volatile("cp.async.cg.shared.global [%0], [%1], 16;" :: "r"(dst), "l"(src));
        }
        asm volatile("cp.async.commit_group;");
    }

    int it = 0;
    for (int t = t0; t < NTILES; t += stride, it++) {
        int buf = it & 1;
        bool pref = (t + stride < NTILES);
        if (pref) {
            int e0n = (t + stride)*64;
            unsigned base = mb_u32 + (unsigned)((buf ^ 1)*64*128)*4u;
            #pragma unroll
            for (int q = 0; q < 4; q++) {
                int chunk = tid + q*512;
                const float* src = g_m + (size_t)e0n*128 + chunk*4;
                unsigned dst = base + (unsigned)chunk*16u;
                asm volatile("cp.async.cg.shared.global [%0], [%1], 16;" :: "r"(dst), "l"(src));
            }
            asm volatile("cp.async.commit_group;");
            asm volatile("cp.async.wait_group 1;");
        } else {
            asm volatile("cp.async.wait_group 0;");
        }
        __syncthreads();

        const float* ms = mb + buf*64*128;
        int e0 = t*64;

        float pp[4];
        {
            u64 acc[4][2];
            #pragma unroll
            for (int i = 0; i < 4; i++) { acc[i][0] = 0ull; acc[i][1] = 0ull; }
            mmk<4>(ms, Wp, r0, c0, acc);
            #pragma unroll
            for (int i = 0; i < 4; i++) {
                float2 f0 = up2(acc[i][0]);
                float2 f1 = up2(acc[i][1]);
                pp[i] = silu_f(f0.x + bhp[c0])*w2p[c0]
                      + silu_f(f0.y + bhp[c0+1])*w2p[c0+1]
                      + silu_f(f1.x + bhp[c0+2])*w2p[c0+2]
                      + silu_f(f1.y + bhp[c0+3])*w2p[c0+3];
            }
        }
        float ps[4][3];
        {
            u64 acc[4][2];
            #pragma unroll
            for (int i = 0; i < 4; i++) { acc[i][0] = 0ull; acc[i][1] = 0ull; }
            mmk<4>(ms, Ws, r0, c0, acc);
            #pragma unroll
            for (int i = 0; i < 4; i++) {
                float2 f0 = up2(acc[i][0]);
                float2 f1 = up2(acc[i][1]);
                float h0 = silu_f(f0.x + bhs[c0]);
                float h1 = silu_f(f0.y + bhs[c0+1]);
                float h2 = silu_f(f1.x + bhs[c0+2]);
                float h3 = silu_f(f1.y + bhs[c0+3]);
                #pragma unroll
                for (int ch = 0; ch < 3; ch++)
                    ps[i][ch] = h0*w2s[c0*3+ch] + h1*w2s[(c0+1)*3+ch]
                              + h2*w2s[(c0+2)*3+ch] + h3*w2s[(c0+3)*3+ch];
            }
        }
        float my_p = 0.f, my_s0 = 0.f, my_s1 = 0.f, my_s2 = 0.f;
        #pragma unroll
        for (int i = 0; i < 4; i++) {
            float v0 = pp[i], v1 = ps[i][0], v2 = ps[i][1], v3 = ps[i][2];
            #pragma unroll
            for (int off = 16; off > 0; off >>= 1) {
                v0 += __shfl_xor_sync(0xffffffffu, v0, off);
                v1 += __shfl_xor_sync(0xffffffffu, v1, off);
                v2 += __shfl_xor_sync(0xffffffffu, v2, off);
                v3 += __shfl_xor_sync(0xffffffffu, v3, off);
            }
            if (tx == i) { my_p = v0; my_s0 = v1; my_s1 = v2; my_s2 = v3; }
        }
        if (tx < 4) {
            int e = e0 + r0 + tx;
            int r = g_er[e], c = g_ec[e];
            float psc = my_p + bp2l[0];
            float s0 = my_s0 + bs2l[0];
            float s1 = my_s1 + bs2l[1];
            float s2 = my_s2 + bs2l[2];
            float dp0 = g_pos[r*3+0] - g_pos[c*3+0];
            float dp1 = g_pos[r*3+1] - g_pos[c*3+1];
            float dp2 = g_pos[r*3+2] - g_pos[c*3+2];
            atomicAdd(&g_psum[r*3+0], dp0*psc);
            atomicAdd(&g_psum[r*3+1], dp1*psc);
            atomicAdd(&g_psum[r*3+2], dp2*psc);
            #pragma unroll
            for (int q = 0; q < 9; q++) {
                float diff = g_sh[r*9 + q] - g_sh[c*9 + q];
                float wq = (q == 0) ? s0 : (q < 4) ? s1 : s2;
                atomicAdd(&g_ssum[r*9 + q], diff*wq);
            }
        }
        __syncthreads();
    }
}

__global__ void posh_kernel() {
    int i = blockIdx.x*256 + threadIdx.x;
    if (i >= Nn) return;
    float inv = 1.0f / fmaxf(g_deg[i], 1.0f);
    #pragma unroll
    for (int q = 0; q < 3; q++) g_pos[i*3 + q] += g_psum[i*3 + q]*inv;
    #pragma unroll
    for (int q = 0; q < 9; q++) g_sh[i*9 + q] += g_ssum[i*9 + q]*inv;
}

// ---------------- readout ----------------
__global__ void pool_kernel(const int* __restrict__ batch) {
    int idx = blockIdx.x*256 + threadIdx.x;
    if (idx >= Nn*140) return;
    int i = idx / 140, c = idx % 140;
    float v;
    if (c < 128)      v = g_feat[(size_t)i*128 + c];
    else if (c < 131) v = g_pos[i*3 + (c - 128)];
    else              v = g_sh[i*9 + (c - 131)];
    atomicAdd(&g_pool[batch[i]*140 + c], v);
}

__global__ void pred_kernel(const float* __restrict__ Wpred, const float* __restrict__ bpred,
                            float* __restrict__ out) {
    int g = blockIdx.x, lane = threadIdx.x;
    float s = 0.f;
    for (int c = lane; c < 140; c += 32)
        s = fmaf(g_pool[g*140 + c], Wpred[c], s);
    #pragma unroll
    for (int off = 16; off > 0; off >>= 1)
        s += __shfl_xor_sync(0xffffffffu, s, off);
    if (lane == 0) out[g] = s + bpred[0];
}

// ---------------- host ----------------
extern "C" void kernel_launch(void* const* d_in, const int* in_sizes, int n_in,
                              void* d_out, int out_size) {
    const int*   atoms = (const int*)d_in[0];
    const int*   ei    = (const int*)d_in[1];
    const int*   batch = (const int*)d_in[2];
    const float* pos   = (const float*)d_in[3];
    const float* emb   = (const float*)d_in[4];
    const float* Wsi1  = (const float*)d_in[5];  const float* bsi1  = (const float*)d_in[6];
    const float* Wsi2  = (const float*)d_in[7];  const float* bsi2  = (const float*)d_in[8];
    const float* WsiC1 = (const float*)d_in[9];  const float* bsiC1 = (const float*)d_in[10];
    const float* WsiC2 = (const float*)d_in[11]; const float* bsiC2 = (const float*)d_in[12];
    const float* Wm1   = (const float*)d_in[13]; const float* bm1   = (const float*)d_in[14];
    const float* Wm2   = (const float*)d_in[15]; const float* bm2   = (const float*)d_in[16];
    const float* Wp1   = (const float*)d_in[17]; const float* bp1   = (const float*)d_in[18];
    const float* Wp2   = (const float*)d_in[19]; const float* bp2   = (const float*)d_in[20];
    const float* Wn1   = (const float*)d_in[21]; const float* bn1   = (const float*)d_in[22];
    const float* Wn2   = (const float*)d_in[23]; const float* bn2   = (const float*)d_in[24];
    const float* Ws1   = (const float*)d_in[25]; const float* bs1   = (const float*)d_in[26];
    const float* Ws2   = (const float*)d_in[27]; const float* bs2   = (const float*)d_in[28];
    const float* Wpred = (const float*)d_in[29]; const float* bpred = (const float*)d_in[30];
    float* out = (float*)d_out;

    cudaFuncSetAttribute(featab_kernel, cudaFuncAttributeMaxDynamicSharedMemorySize, FAB_SMEM);
    cudaFuncSetAttribute(nodeup_kernel, cudaFuncAttributeMaxDynamicSharedMemorySize, NU_SMEM);
    cudaFuncSetAttribute(edge_hm_kernel, cudaFuncAttributeMaxDynamicSharedMemorySize, E1_SMEM);
    cudaFuncSetAttribute(edge_ps_kernel, cudaFuncAttributeMaxDynamicSharedMemorySize, E2_SMEM);

    void *p_msum, *p_psum, *p_ssum, *p_deg, *p_com, *p_cnt, *p_pool, *p_pos, *p_cur;
    cudaGetSymbolAddress(&p_msum, g_msum);
    cudaGetSymbolAddress(&p_psum, g_psum);
    cudaGetSymbolAddress(&p_ssum, g_ssum);
    cudaGetSymbolAddress(&p_deg,  g_deg);
    cudaGetSymbolAddress(&p_com,  g_com);
    cudaGetSymbolAddress(&p_cnt,  g_cnt);
    cudaGetSymbolAddress(&p_pool, g_pool);
    cudaGetSymbolAddress(&p_pos,  g_pos);
    cudaGetSymbolAddress(&p_cur,  g_cursor);

    cudaMemsetAsync(p_deg,  0, Nn*4, 0);
    cudaMemsetAsync(p_com,  0, Gg*3*4, 0);
    cudaMemsetAsync(p_cnt,  0, Gg*4, 0);
    cudaMemsetAsync(p_ssum, 0, Nn*9*4, 0);
    cudaMemsetAsync(p_pool, 0, Gg*140*4, 0);
    cudaMemsetAsync(p_cur,  0, Nn*4, 0);
    cudaMemcpyAsync(p_pos, pos, Nn*3*4, cudaMemcpyDeviceToDevice, 0);

    node_init_kernel<<<(Nn*128)/256, 256>>>(atoms, emb);
    com_kernel<<<(Nn + 255)/256, 256>>>(batch);
    deg_kernel<<<(Ee + 255)/256, 256>>>(ei);
    scan_kernel<<<1, 256>>>();
    sortscatter_kernel<<<(Ee + 255)/256, 256>>>(ei);
    vocab_kernel<<<10, 128>>>(emb, Wsi1, WsiC1, bsiC1, WsiC2, bsiC2);
    edge_init_kernel<<<Ee/8, 256>>>(atoms, Wsi1, bsi1, Wsi2, bsi2);
    sh_init_kernel<<<(Nn + 255)/256, 256>>>(atoms, batch);

    int gridN = (Nn + 63)/64;   // 157

    for (int l = 0; l < Ll; l++) {
        cudaMemsetAsync(p_msum, 0, (size_t)Nn*128*4, 0);
        cudaMemsetAsync(p_psum, 0, Nn*3*4, 0);
        cudaMemsetAsync(p_ssum, 0, Nn*9*4, 0);

        featab_kernel<<<gridN, 256, FAB_SMEM>>>(
            Wm1 + (size_t)l*260*128, Wm1 + ((size_t)l*260 + 128)*128);

        edge_hm_kernel<<<296, 256, E1_SMEM>>>(
            Wm2 + (size_t)l*128*128, bm2 + l*128,
            Wm1 + ((size_t)l*260 + 256)*128, bm1 + l*128);

        edge_ps_kernel<<<148, 512, E2_SMEM>>>(
            Wp1 + (size_t)l*128*128, bp1 + l*128, Wp2 + l*128, bp2 + l,
            Ws1 + (size_t)l*128*128, bs1 + l*128, Ws2 + l*384, bs2 + l*3);

        posh_kernel<<<(Nn + 255)/256, 256>>>();

        nodeup_kernel<<<gridN, 256, NU_SMEM>>>(
            Wn1 + (size_t)l*256*128, Wn1 + ((size_t)l*256 + 128)*128,
            Wn2 + (size_t)l*128*128, bn1 + l*128, bn2 + l*128);
    }

    pool_kernel<<<(Nn*140 + 255)/256, 256>>>(batch);
    pred_kernel<<<Gg, 32>>>(Wpred, bpred, out);
}

// round 9
// speedup vs baseline: 1.1570x; 1.1570x over previous
#include <cuda_runtime.h>
#include <cuda_bf16.h>
#include <cstdint>
#include <math.h>

#define Nn 10000
#define Ee 160000
#define Gg 100
#define Ll 5
#define NT 2500   // 64-edge tiles

typedef unsigned long long u64;
typedef unsigned short ush;

__device__ float g_feat [Nn*128];
__device__ float g_featA[Nn*128];
__device__ float g_featB[Nn*128];
__device__ float g_sh   [Nn*9];
__device__ float g_pos  [Nn*3];
__device__ float g_msum [Nn*128];
__device__ float g_psum [Nn*3];
__device__ float g_ssum [Nn*9];
__device__ float g_deg  [Nn];
__device__ float g_com  [Gg*3];
__device__ float g_cnt  [Gg];
__device__ float g_P1   [10*128];
__device__ float g_P2   [10*128];
__device__ float g_cmsg [10];
__device__ float g_pool [Gg*140];
__device__ int   g_off  [Nn];
__device__ int   g_cursor[Nn];
__device__ int   g_er   [Ee];
__device__ int   g_ec   [Ee];
__device__ ush   g_mh  [(size_t)NT*8192];   // m hi-bf16, [tile][64][128]
__device__ ush   g_ml  [(size_t)NT*8192];   // m lo-bf16
__device__ ush   g_Wbh [15*17408];          // [slot][n*136+k] hi
__device__ ush   g_Wbl [15*17408];          // lo

__device__ __forceinline__ float silu_f(float x) { return x / (1.0f + __expf(-x)); }

__device__ __forceinline__ void sph2(float vx, float vy, float vz, float* o) {
    const float S3 = 1.7320508075688772f, HS3 = 0.8660254037844386f;
    float r = sqrtf(vx*vx + vy*vy + vz*vz);
    float inv = 1.0f / fmaxf(r, 1e-12f);
    float x = vx*inv, y = vy*inv, z = vz*inv;
    o[0] = S3*x*z; o[1] = S3*x*y; o[2] = y*y - 0.5f*(x*x + z*z);
    o[3] = S3*y*z; o[4] = HS3*(z*z - x*x);
}

// ---- packed f32x2 (node GEMMs, proven) ----
__device__ __forceinline__ u64 fma2(u64 a, u64 b, u64 c) {
    u64 d; asm("fma.rn.f32x2 %0, %1, %2, %3;" : "=l"(d) : "l"(a), "l"(b), "l"(c)); return d;
}
__device__ __forceinline__ u64 pk2(float x) {
    u64 d; asm("mov.b64 %0, {%1, %1};" : "=l"(d) : "r"(__float_as_uint(x))); return d;
}
__device__ __forceinline__ float2 up2(u64 v) {
    float2 f; asm("mov.b64 {%0, %1}, %2;" : "=f"(f.x), "=f"(f.y) : "l"(v)); return f;
}
template<int RPW>
__device__ __forceinline__ void mmk(const float* __restrict__ As, const float* __restrict__ Ws,
                                    int r0, int c0, u64 acc[RPW][2]) {
    const float* ap = As + r0*128;
    const float* wp = Ws + c0;
    #pragma unroll 4
    for (int k0 = 0; k0 < 128; k0 += 2) {
        float2 a2[RPW];
        #pragma unroll
        for (int i = 0; i < RPW; i++) a2[i] = *(const float2*)(ap + i*128 + k0);
        ulonglong2 p0 = *(const ulonglong2*)(wp + k0*128);
        ulonglong2 q0 = *(const ulonglong2*)(wp + (k0+1)*128);
        #pragma unroll
        for (int i = 0; i < RPW; i++) {
            u64 ax = pk2(a2[i].x);
            acc[i][0] = fma2(ax, p0.x, acc[i][0]);
            acc[i][1] = fma2(ax, p0.y, acc[i][1]);
        }
        #pragma unroll
        for (int i = 0; i < RPW; i++) {
            u64 ay = pk2(a2[i].y);
            acc[i][0] = fma2(ay, q0.x, acc[i][0]);
            acc[i][1] = fma2(ay, q0.y, acc[i][1]);
        }
    }
}

// ---- HMMA helpers (baseline PTX: ldmatrix + mma.sync bf16) ----
__device__ __forceinline__ unsigned smem_u32(const void* p) {
    unsigned a; asm("{ .reg .u64 t; cvta.to.shared.u64 t, %1; cvt.u32.u64 %0, t; }" : "=r"(a) : "l"(p));
    return a;
}
__device__ __forceinline__ void ldsm4(unsigned addr, unsigned* r) {
    asm volatile("ldmatrix.sync.aligned.m8n8.x4.shared.b16 {%0,%1,%2,%3}, [%4];"
        : "=r"(r[0]), "=r"(r[1]), "=r"(r[2]), "=r"(r[3]) : "r"(addr));
}
__device__ __forceinline__ void mma_bf16(float* d, const unsigned* a, unsigned b0, unsigned b1) {
    asm volatile("mma.sync.aligned.m16n8k16.row.col.f32.bf16.bf16.f32 "
        "{%0,%1,%2,%3},{%4,%5,%6,%7},{%8,%9},{%0,%1,%2,%3};"
        : "+f"(d[0]), "+f"(d[1]), "+f"(d[2]), "+f"(d[3])
        : "r"(a[0]), "r"(a[1]), "r"(a[2]), "r"(a[3]), "r"(b0), "r"(b1));
}
__device__ __forceinline__ void split_bf16(float v, unsigned& h, unsigned& l) {
    __nv_bfloat16 hb = __float2bfloat16(v);
    h = (unsigned)__bfloat16_as_ushort(hb);
    l = (unsigned)__bfloat16_as_ushort(__float2bfloat16(v - __bfloat162float(hb)));
}

// split-bf16 GEMM core: rows m0..m0+15 x cols n0..n0+63, K=128.
// A (hi/lo) row-major [64][136] ush; B (hi/lo) [n][136] ush. acc[8][4].
__device__ __forceinline__ void hmma_gemm(unsigned aH, unsigned aL, unsigned bH, unsigned bL,
                                          int m0, int n0, int lane, float acc[8][4]) {
    unsigned aoff = (unsigned)((m0 + (lane & 15))*272 + (lane >> 4)*16);
    unsigned boff = (unsigned)((n0 + (lane & 15))*272 + (lane >> 4)*16);
    #pragma unroll
    for (int kk = 0; kk < 8; kk++) {
        unsigned kb = kk*32;
        unsigned Ah[4], Al[4];
        ldsm4(aH + aoff + kb, Ah);
        ldsm4(aL + aoff + kb, Al);
        #pragma unroll
        for (int t = 0; t < 4; t++) {
            unsigned bo = boff + t*16*272 + kb;
            unsigned Bh[4], Bl[4];
            ldsm4(bH + bo, Bh);
            ldsm4(bL + bo, Bl);
            mma_bf16(acc[2*t],   Ah, Bh[0], Bh[2]);
            mma_bf16(acc[2*t],   Ah, Bl[0], Bl[2]);
            mma_bf16(acc[2*t],   Al, Bh[0], Bh[2]);
            mma_bf16(acc[2*t+1], Ah, Bh[1], Bh[3]);
            mma_bf16(acc[2*t+1], Ah, Bl[1], Bl[3]);
            mma_bf16(acc[2*t+1], Al, Bh[1], Bh[3]);
        }
    }
}

// weights -> split-bf16 [n][k] stride-136 tiles; slot: l*3 + {0:Wm2,1:Wp1,2:Ws1}
__global__ void wprep_kernel(const float* __restrict__ Wm2, const float* __restrict__ Wp1,
                             const float* __restrict__ Ws1) {
    int bid = blockIdx.x, l = bid / 3, slot = bid % 3;
    const float* src = (slot == 0 ? Wm2 : (slot == 1 ? Wp1 : Ws1)) + (size_t)l*16384;
    ush* dh = g_Wbh + (size_t)bid*17408;
    ush* dl = g_Wbl + (size_t)bid*17408;
    for (int o = threadIdx.x; o < 16384; o += 256) {
        int k = o >> 7, n = o & 127;
        unsigned h, lo;
        split_bf16(src[k*128 + n], h, lo);
        dh[n*136 + k] = (ush)h;
        dl[n*136 + k] = (ush)lo;
    }
}

// ---- init kernels ----
__global__ void node_init_kernel(const int* __restrict__ atoms, const float* __restrict__ emb) {
    int idx = blockIdx.x*256 + threadIdx.x;
    g_feat[idx] = emb[atoms[idx >> 7]*128 + (idx & 127)];
}
__global__ void com_kernel(const int* __restrict__ batch) {
    int i = blockIdx.x*256 + threadIdx.x;
    if (i >= Nn) return;
    int b = batch[i];
    atomicAdd(&g_com[b*3+0], g_pos[i*3+0]);
    atomicAdd(&g_com[b*3+1], g_pos[i*3+1]);
    atomicAdd(&g_com[b*3+2], g_pos[i*3+2]);
    atomicAdd(&g_cnt[b], 1.0f);
}
__global__ void deg_kernel(const int* __restrict__ ei) {
    int e = blockIdx.x*256 + threadIdx.x;
    if (e < Ee) atomicAdd(&g_deg[ei[e]], 1.0f);
}
__global__ void scan_kernel() {
    __shared__ int part[256];
    int tid = threadIdx.x;
    int lo = tid*40, hi = (lo + 40 < Nn) ? lo + 40 : Nn;
    int s = 0;
    for (int i = lo; i < hi; i++) s += (int)g_deg[i];
    part[tid] = s;
    __syncthreads();
    for (int off = 1; off < 256; off <<= 1) {
        int v = part[tid] + ((tid >= off) ? part[tid - off] : 0);
        __syncthreads(); part[tid] = v; __syncthreads();
    }
    int base = (tid > 0) ? part[tid - 1] : 0;
    for (int i = lo; i < hi; i++) { g_off[i] = base; base += (int)g_deg[i]; }
}
__global__ void sortscatter_kernel(const int* __restrict__ ei) {
    int e = blockIdx.x*256 + threadIdx.x;
    if (e >= Ee) return;
    int r = ei[e], c = ei[Ee + e];
    int p = g_off[r] + atomicAdd(&g_cursor[r], 1);
    g_er[p] = r; g_ec[p] = c;
}
__global__ void vocab_kernel(const float* __restrict__ emb, const float* __restrict__ Wsi1,
                             const float* __restrict__ WsiC1, const float* __restrict__ bsiC1,
                             const float* __restrict__ WsiC2, const float* __restrict__ bsiC2) {
    __shared__ float es[128], redv[128];
    int v = blockIdx.x, j = threadIdx.x;
    es[j] = emb[v*128 + j];
    __syncthreads();
    float p1 = 0.f, p2 = 0.f, hc = 0.f;
    for (int k = 0; k < 128; k++) {
        float e = es[k];
        p1 = fmaf(e, Wsi1[(1 + k)*128 + j], p1);
        p2 = fmaf(e, Wsi1[(129 + k)*128 + j], p2);
        hc = fmaf(e, WsiC1[k*128 + j], hc);
    }
    g_P1[v*128 + j] = p1; g_P2[v*128 + j] = p2;
    redv[j] = silu_f(hc + bsiC1[j]) * WsiC2[j*3 + 2];
    __syncthreads();
    for (int s = 64; s > 0; s >>= 1) {
        if (j < s) redv[j] += redv[j + s];
        __syncthreads();
    }
    if (j == 0) g_cmsg[v] = redv[0] + bsiC2[2];
}
__global__ void edge_init_kernel(const int* __restrict__ atoms,
                                 const float* __restrict__ Wsi1, const float* __restrict__ bsi1,
                                 const float* __restrict__ Wsi2, const float* __restrict__ bsi2) {
    int e = blockIdx.x*8 + (threadIdx.x >> 5);
    int lane = threadIdx.x & 31;
    int r = g_er[e], c = g_ec[e];
    float dp0 = g_pos[r*3+0] - g_pos[c*3+0];
    float dp1 = g_pos[r*3+1] - g_pos[c*3+1];
    float dp2 = g_pos[r*3+2] - g_pos[c*3+2];
    float dist = sqrtf(dp0*dp0 + dp1*dp1 + dp2*dp2);
    int ar = atoms[r], ac = atoms[c];
    float partial = 0.f;
    #pragma unroll
    for (int q = 0; q < 4; q++) {
        int d = lane + q*32;
        partial = fmaf(silu_f(dist*Wsi1[d] + g_P1[ar*128 + d] + g_P2[ac*128 + d] + bsi1[d]),
                       Wsi2[d*3 + 2], partial);
    }
    #pragma unroll
    for (int off = 16; off > 0; off >>= 1)
        partial += __shfl_xor_sync(0xffffffffu, partial, off);
    if (lane == 0) {
        float msg2 = partial + bsi2[2];
        float y2[5];
        sph2(dp0, dp1, dp2, y2);
        #pragma unroll
        for (int q = 0; q < 5; q++)
            atomicAdd(&g_ssum[r*9 + 4 + q], y2[q]*msg2);
    }
}
__global__ void sh_init_kernel(const int* __restrict__ atoms, const int* __restrict__ batch) {
    int i = blockIdx.x*256 + threadIdx.x;
    if (i >= Nn) return;
    float dg = fmaxf(g_deg[i], 1.0f);
    int b = batch[i];
    float cn = fmaxf(g_cnt[b], 1.0f);
    float y2[5];
    sph2(g_pos[i*3+0] - g_com[b*3+0]/cn, g_pos[i*3+1] - g_com[b*3+1]/cn,
         g_pos[i*3+2] - g_com[b*3+2]/cn, y2);
    float cm = g_cmsg[atoms[i]];
    #pragma unroll
    for (int q = 0; q < 4; q++) g_sh[i*9 + q] = 0.0f;
    #pragma unroll
    for (int q = 0; q < 5; q++)
        g_sh[i*9 + 4 + q] = g_ssum[i*9 + 4 + q]/dg + cm*y2[q];
}

// ---- featAB (scalar, proven) ----
#define FAB_SMEM ((64*128 + 2*128*128)*4)
__global__ void __launch_bounds__(256)
featab_kernel(const float* __restrict__ Wa, const float* __restrict__ Wb) {
    extern __shared__ float sm[];
    float* As = sm;
    float* Was = As + 64*128;
    float* Wbs = Was + 128*128;
    int tid = threadIdx.x, row0 = blockIdx.x * 64;
    for (int idx = tid; idx < 64*32; idx += 256) {
        int r = idx >> 5, c4 = (idx & 31)*4;
        float4 v = make_float4(0.f,0.f,0.f,0.f);
        if (row0 + r < Nn) v = *(const float4*)(g_feat + (size_t)(row0 + r)*128 + c4);
        *(float4*)(As + r*128 + c4) = v;
    }
    for (int idx = tid; idx < 128*32; idx += 256) {
        *(float4*)(Was + idx*4) = *(const float4*)(Wa + (size_t)idx*4);
        *(float4*)(Wbs + idx*4) = *(const float4*)(Wb + (size_t)idx*4);
    }
    __syncthreads();
    int ty = tid >> 5, tx = tid & 31, r0 = ty*8, c0 = tx*4;
    u64 acc[8][2];
    #pragma unroll
    for (int i = 0; i < 8; i++) { acc[i][0] = 0; acc[i][1] = 0; }
    mmk<8>(As, Was, r0, c0, acc);
    #pragma unroll
    for (int i = 0; i < 8; i++) {
        int r = row0 + r0 + i;
        if (r >= Nn) continue;
        float2 f0 = up2(acc[i][0]), f1 = up2(acc[i][1]);
        *(float4*)(g_featA + (size_t)r*128 + c0) = make_float4(f0.x, f0.y, f1.x, f1.y);
    }
    #pragma unroll
    for (int i = 0; i < 8; i++) { acc[i][0] = 0; acc[i][1] = 0; }
    mmk<8>(As, Wbs, r0, c0, acc);
    #pragma unroll
    for (int i = 0; i < 8; i++) {
        int r = row0 + r0 + i;
        if (r >= Nn) continue;
        float2 f0 = up2(acc[i][0]), f1 = up2(acc[i][1]);
        *(float4*)(g_featB + (size_t)r*128 + c0) = make_float4(f0.x, f0.y, f1.x, f1.y);
    }
}

// ---- node update (scalar, proven) ----
#define NU_SMEM ((2*64*128 + 2*128*128 + 256)*4)
__global__ void __launch_bounds__(256)
nodeup_kernel(const float* __restrict__ W5, const float* __restrict__ W6,
              const float* __restrict__ W7,
              const float* __restrict__ b1, const float* __restrict__ b2) {
    extern __shared__ float sm[];
    float* A1 = sm;
    float* A2 = A1 + 64*128;
    float* Wx = A2 + 64*128;
    float* Wy = Wx + 128*128;
    float* bb = Wy + 128*128;
    int tid = threadIdx.x, row0 = blockIdx.x * 64;
    for (int idx = tid; idx < 64*32; idx += 256) {
        int r = idx >> 5, c4 = (idx & 31)*4;
        float4 v1 = make_float4(0.f,0.f,0.f,0.f), v2 = v1;
        if (row0 + r < Nn) {
            v1 = *(const float4*)(g_feat + (size_t)(row0 + r)*128 + c4);
            v2 = *(const float4*)(g_msum + (size_t)(row0 + r)*128 + c4);
            float inv = 1.0f / fmaxf(g_deg[row0 + r], 1.0f);
            v2.x *= inv; v2.y *= inv; v2.z *= inv; v2.w *= inv;
        }
        *(float4*)(A1 + r*128 + c4) = v1;
        *(float4*)(A2 + r*128 + c4) = v2;
    }
    for (int idx = tid; idx < 128*32; idx += 256) {
        *(float4*)(Wx + idx*4) = *(const float4*)(W5 + (size_t)idx*4);
        *(float4*)(Wy + idx*4) = *(const float4*)(W6 + (size_t)idx*4);
    }
    if (tid < 128) { bb[tid] = b1[tid]; bb[128 + tid] = b2[tid]; }
    __syncthreads();
    int ty = tid >> 5, tx = tid & 31, r0 = ty*8, c0 = tx*4;
    u64 acc[8][2];
    #pragma unroll
    for (int i = 0; i < 8; i++) { acc[i][0] = 0; acc[i][1] = 0; }
    mmk<8>(A1, Wx, r0, c0, acc);
    mmk<8>(A2, Wy, r0, c0, acc);
    __syncthreads();
    #pragma unroll
    for (int i = 0; i < 8; i++) {
        float2 f0 = up2(acc[i][0]), f1 = up2(acc[i][1]);
        A1[(r0+i)*128 + c0 + 0] = silu_f(f0.x + bb[c0]);
        A1[(r0+i)*128 + c0 + 1] = silu_f(f0.y + bb[c0+1]);
        A1[(r0+i)*128 + c0 + 2] = silu_f(f1.x + bb[c0+2]);
        A1[(r0+i)*128 + c0 + 3] = silu_f(f1.y + bb[c0+3]);
    }
    for (int idx = tid; idx < 128*32; idx += 256)
        *(float4*)(Wx + idx*4) = *(const float4*)(W7 + (size_t)idx*4);
    __syncthreads();
    #pragma unroll
    for (int i = 0; i < 8; i++) { acc[i][0] = 0; acc[i][1] = 0; }
    mmk<8>(A1, Wx, r0, c0, acc);
    #pragma unroll
    for (int i = 0; i < 8; i++) {
        int r = row0 + r0 + i;
        if (r >= Nn) continue;
        float2 f0 = up2(acc[i][0]), f1 = up2(acc[i][1]);
        *(float4*)(g_feat + (size_t)r*128 + c0) =
            make_float4(f0.x + bb[128+c0], f0.y + bb[128+c0+1],
                        f1.x + bb[128+c0+2], f1.y + bb[128+c0+3]);
    }
}

// ============ E1: HMMA h-build + m-GEMM (persistent) ============
// byte layout: Ah 0 | Al 17408 | Wh 34816 | Wl 69632 | m_s(f32) 104448 |
// scal 139264 | bh 140288 | wtl 140800 | ridx 143360 | cidx 143616
#define E1_SMEM 143872
__global__ void __launch_bounds__(256, 1)
edge_hm_mma(const float* __restrict__ bm2l, const float* __restrict__ Wm1tail,
            const float* __restrict__ bm1l, int layer) {
    extern __shared__ char smc[];
    unsigned sb = smem_u32(smc);
    float* m_s  = (float*)(smc + 104448);    // [64][136]
    float* scal = (float*)(smc + 139264);
    float* bh   = (float*)(smc + 140288);
    float* wtl  = (float*)(smc + 140800);
    int* ridx   = (int*)(smc + 143360);
    int* cidx   = (int*)(smc + 143616);
    int tid = threadIdx.x, w = tid >> 5, lane = tid & 31;

    // resident weight fill (hi/lo): 2176 16B-chunks each
    {
        const uint4* sh = (const uint4*)(g_Wbh + (size_t)(layer*3)*17408);
        const uint4* sl = (const uint4*)(g_Wbl + (size_t)(layer*3)*17408);
        uint4* dh = (uint4*)(smc + 34816);
        uint4* dl = (uint4*)(smc + 69632);
        for (int i = tid; i < 2176; i += 256) { dh[i] = sh[i]; dl[i] = sl[i]; }
    }
    if (tid < 128) bh[tid] = bm2l[tid];
    for (int i = tid; i < 640; i += 256)
        wtl[i] = (i < 512) ? Wm1tail[i] : bm1l[i - 512];

    int m0 = (w & 3)*16, n0 = (w >> 2)*64;

    for (int t = blockIdx.x; t < NT; t += gridDim.x) {
        int e0 = t*64;
        __syncthreads();
        if (tid < 64) {
            int r = g_er[e0 + tid], c = g_ec[e0 + tid];
            ridx[tid] = r; cidx[tid] = c;
            float dp0 = g_pos[r*3+0] - g_pos[c*3+0];
            float dp1 = g_pos[r*3+1] - g_pos[c*3+1];
            float dp2 = g_pos[r*3+2] - g_pos[c*3+2];
            float ip2 = 0.f;
            #pragma unroll
            for (int q = 4; q < 9; q++) ip2 += g_sh[r*9+q]*g_sh[c*9+q];
            scal[tid*4+0] = dp0*dp0 + dp1*dp1 + dp2*dp2;
            scal[tid*4+1] = g_sh[r*9+0]*g_sh[c*9+0];
            scal[tid*4+2] = g_sh[r*9+1]*g_sh[c*9+1] + g_sh[r*9+2]*g_sh[c*9+2] + g_sh[r*9+3]*g_sh[c*9+3];
            scal[tid*4+3] = ip2;
        }
        __syncthreads();
        // h-build -> split-bf16 A tiles
        #pragma unroll
        for (int q = 0; q < 8; q++) {
            int idx = tid + q*256;
            int e = idx >> 5, c4 = (idx & 31)*4;
            int r = ridx[e], c = cidx[e];
            float4 fa = *(const float4*)(g_featA + (size_t)r*128 + c4);
            float4 fb = *(const float4*)(g_featB + (size_t)c*128 + c4);
            float d2 = scal[e*4+0], i0 = scal[e*4+1], i1 = scal[e*4+2], i2 = scal[e*4+3];
            float hv[4];
            hv[0] = silu_f(fa.x + fb.x + d2*wtl[c4+0] + i0*wtl[128+c4+0] + i1*wtl[256+c4+0] + i2*wtl[384+c4+0] + wtl[512+c4+0]);
            hv[1] = silu_f(fa.y + fb.y + d2*wtl[c4+1] + i0*wtl[128+c4+1] + i1*wtl[256+c4+1] + i2*wtl[384+c4+1] + wtl[512+c4+1]);
            hv[2] = silu_f(fa.z + fb.z + d2*wtl[c4+2] + i0*wtl[128+c4+2] + i1*wtl[256+c4+2] + i2*wtl[384+c4+2] + wtl[512+c4+2]);
            hv[3] = silu_f(fa.w + fb.w + d2*wtl[c4+3] + i0*wtl[128+c4+3] + i1*wtl[256+c4+3] + i2*wtl[384+c4+3] + wtl[512+c4+3]);
            unsigned h[4], l[4];
            #pragma unroll
            for (int j = 0; j < 4; j++) split_bf16(hv[j], h[j], l[j]);
            unsigned off = (unsigned)(e*136 + c4)*2u;
            *(uint2*)(smc + off)         = make_uint2(h[0]|(h[1]<<16), h[2]|(h[3]<<16));
            *(uint2*)(smc + 17408 + off) = make_uint2(l[0]|(l[1]<<16), l[2]|(l[3]<<16));
        }
        __syncthreads();
        // GEMM
        float acc[8][4];
        #pragma unroll
        for (int i = 0; i < 8; i++)
            #pragma unroll
            for (int j = 0; j < 4; j++) acc[i][j] = 0.f;
        hmma_gemm(sb, sb + 17408, sb + 34816, sb + 69632, m0, n0, lane, acc);
        // epilogue: m = silu(D + bm2) -> m_s fp32
        {
            int r0 = m0 + (lane >> 2), r1 = r0 + 8;
            #pragma unroll
            for (int s = 0; s < 8; s++) {
                int col = n0 + s*8 + (lane & 3)*2;
                m_s[r0*136 + col]     = silu_f(acc[s][0] + bh[col]);
                m_s[r0*136 + col + 1] = silu_f(acc[s][1] + bh[col+1]);
                m_s[r1*136 + col]     = silu_f(acc[s][2] + bh[col]);
                m_s[r1*136 + col + 1] = silu_f(acc[s][3] + bh[col+1]);
            }
        }
        __syncthreads();
        // msum sorted-run RED (col per thread, half the edges each)
        {
            int c = tid & 127, half = tid >> 7;
            int eb = half*32;
            float agg = 0.f;
            int ar = ridx[eb];
            for (int e = eb; e < eb + 32; e++) {
                float v = m_s[e*136 + c];
                int r = ridx[e];
                if (r != ar) { atomicAdd(&g_msum[(size_t)ar*128 + c], agg); agg = v; ar = r; }
                else agg += v;
            }
            atomicAdd(&g_msum[(size_t)ar*128 + c], agg);
        }
        // m -> gmem split-bf16 (row-major [64][128])
        {
            unsigned* gh = (unsigned*)(g_mh + (size_t)t*8192);
            unsigned* gl = (unsigned*)(g_ml + (size_t)t*8192);
            #pragma unroll
            for (int q = 0; q < 16; q++) {
                int idx = tid + q*256;          // pair index 0..4095
                int e = idx >> 6, cp = idx & 63;
                float v0 = m_s[e*136 + cp*2], v1 = m_s[e*136 + cp*2 + 1];
                unsigned h0, l0, h1, l1;
                split_bf16(v0, h0, l0);
                split_bf16(v1, h1, l1);
                gh[idx] = h0 | (h1 << 16);
                gl[idx] = l0 | (l1 << 16);
            }
        }
    }
}

// ============ E2: HMMA p+s GEMMs (persistent) ============
// byte layout: Ah 0 | Al 17408 | Wph 34816 | Wpl 69632 | Wsh 104448 | Wsl 139264 |
// bhp 174080 | bhs 174592 | w2p 175104 | w2s 175616 | pd 177152 (2*64*4 f)
#define E2_SMEM 179200
__global__ void __launch_bounds__(256, 1)
edge_ps_mma(const float* __restrict__ bp1l, const float* __restrict__ Wp2l,
            const float* __restrict__ bp2l,
            const float* __restrict__ bs1l, const float* __restrict__ Ws2l,
            const float* __restrict__ bs2l, int layer) {
    extern __shared__ char smc[];
    unsigned sb = smem_u32(smc);
    float* bhp = (float*)(smc + 174080);
    float* bhs = (float*)(smc + 174592);
    float* w2p = (float*)(smc + 175104);
    float* w2s = (float*)(smc + 175616);
    float* pd  = (float*)(smc + 177152);     // [2][64][4]
    int tid = threadIdx.x, w = tid >> 5, lane = tid & 31;

    {
        const uint4* ph = (const uint4*)(g_Wbh + (size_t)(layer*3 + 1)*17408);
        const uint4* pl = (const uint4*)(g_Wbl + (size_t)(layer*3 + 1)*17408);
        const uint4* sh = (const uint4*)(g_Wbh + (size_t)(layer*3 + 2)*17408);
        const uint4* sl = (const uint4*)(g_Wbl + (size_t)(layer*3 + 2)*17408);
        uint4* dph = (uint4*)(smc + 34816);
        uint4* dpl = (uint4*)(smc + 69632);
        uint4* dsh = (uint4*)(smc + 104448);
        uint4* dsl = (uint4*)(smc + 139264);
        for (int i = tid; i < 2176; i += 256) {
            dph[i] = ph[i]; dpl[i] = pl[i]; dsh[i] = sh[i]; dsl[i] = sl[i];
        }
    }
    if (tid < 128) {
        bhp[tid] = bp1l[tid]; bhs[tid] = bs1l[tid]; w2p[tid] = Wp2l[tid];
        w2s[tid*3+0] = Ws2l[tid*3+0]; w2s[tid*3+1] = Ws2l[tid*3+1]; w2s[tid*3+2] = Ws2l[tid*3+2];
    }

    int m0 = (w & 3)*16, n0 = (w >> 2)*64;
    int chalf = w >> 2;

    for (int t = blockIdx.x; t < NT; t += gridDim.x) {
        __syncthreads();
        // load m tile (hi/lo) via cp.async into A (stride 136)
        {
            const char* srh = (const char*)(g_mh + (size_t)t*8192);
            const char* srl = (const char*)(g_ml + (size_t)t*8192);
            #pragma unroll
            for (int q = 0; q < 4; q++) {
                int ch = tid + q*256;             // 0..1023 chunks of 16B
                int e = ch >> 4, c16 = ch & 15;
                unsigned dof = (unsigned)(e*272 + c16*16);
                asm volatile("cp.async.cg.shared.global [%0], [%1], 16;"
                             :: "r"(sb + dof), "l"(srh + (size_t)ch*16) : "memory");
                asm volatile("cp.async.cg.shared.global [%0], [%1], 16;"
                             :: "r"(sb + 17408u + dof), "l"(srl + (size_t)ch*16) : "memory");
            }
            asm volatile("cp.async.commit_group;" ::: "memory");
            asm volatile("cp.async.wait_group 0;" ::: "memory");
        }
        __syncthreads();
        // two GEMMs sharing A fragments
        float accp[8][4], accs[8][4];
        #pragma unroll
        for (int i = 0; i < 8; i++)
            #pragma unroll
            for (int j = 0; j < 4; j++) { accp[i][j] = 0.f; accs[i][j] = 0.f; }
        {
            unsigned aoff = (unsigned)((m0 + (lane & 15))*272 + (lane >> 4)*16);
            unsigned boff = (unsigned)((n0 + (lane & 15))*272 + (lane >> 4)*16);
            #pragma unroll
            for (int kk = 0; kk < 8; kk++) {
                unsigned kb = kk*32;
                unsigned Ah[4], Al[4];
                ldsm4(sb + aoff + kb, Ah);
                ldsm4(sb + 17408u + aoff + kb, Al);
                #pragma unroll
                for (int tt = 0; tt < 4; tt++) {
                    unsigned bo = boff + tt*16*272 + kb;
                    unsigned Bh[4], Bl[4];
                    ldsm4(sb + 34816u + bo, Bh);
                    ldsm4(sb + 69632u + bo, Bl);
                    mma_bf16(accp[2*tt],   Ah, Bh[0], Bh[2]);
                    mma_bf16(accp[2*tt],   Ah, Bl[0], Bl[2]);
                    mma_bf16(accp[2*tt],   Al, Bh[0], Bh[2]);
                    mma_bf16(accp[2*tt+1], Ah, Bh[1], Bh[3]);
                    mma_bf16(accp[2*tt+1], Ah, Bl[1], Bl[3]);
                    mma_bf16(accp[2*tt+1], Al, Bh[1], Bh[3]);
                    ldsm4(sb + 104448u + bo, Bh);
                    ldsm4(sb + 139264u + bo, Bl);
                    mma_bf16(accs[2*tt],   Ah, Bh[0], Bh[2]);
                    mma_bf16(accs[2*tt],   Ah, Bl[0], Bl[2]);
                    mma_bf16(accs[2*tt],   Al, Bh[0], Bh[2]);
                    mma_bf16(accs[2*tt+1], Ah, Bh[1], Bh[3]);
                    mma_bf16(accs[2*tt+1], Ah, Bl[1], Bl[3]);
                    mma_bf16(accs[2*tt+1], Al, Bh[1], Bh[3]);
                }
            }
        }
        // epilogue: per-row dots + quad reduce
        {
            float pr0 = 0.f, pr1 = 0.f;
            float s0r0 = 0.f, s1r0 = 0.f, s2r0 = 0.f;
            float s0r1 = 0.f, s1r1 = 0.f, s2r1 = 0.f;
            #pragma unroll
            for (int s = 0; s < 8; s++) {
                int col = n0 + s*8 + (lane & 3)*2;
                float h00 = silu_f(accp[s][0] + bhp[col]);
                float h01 = silu_f(accp[s][1] + bhp[col+1]);
                float h10 = silu_f(accp[s][2] + bhp[col]);
                float h11 = silu_f(accp[s][3] + bhp[col+1]);
                pr0 = fmaf(h00, w2p[col], fmaf(h01, w2p[col+1], pr0));
                pr1 = fmaf(h10, w2p[col], fmaf(h11, w2p[col+1], pr1));
                float g00 = silu_f(accs[s][0] + bhs[col]);
                float g01 = silu_f(accs[s][1] + bhs[col+1]);
                float g10 = silu_f(accs[s][2] + bhs[col]);
                float g11 = silu_f(accs[s][3] + bhs[col+1]);
                s0r0 = fmaf(g00, w2s[col*3+0], fmaf(g01, w2s[(col+1)*3+0], s0r0));
                s1r0 = fmaf(g00, w2s[col*3+1], fmaf(g01, w2s[(col+1)*3+1], s1r0));
                s2r0 = fmaf(g00, w2s[col*3+2], fmaf(g01, w2s[(col+1)*3+2], s2r0));
                s0r1 = fmaf(g10, w2s[col*3+0], fmaf(g11, w2s[(col+1)*3+0], s0r1));
                s1r1 = fmaf(g10, w2s[col*3+1], fmaf(g11, w2s[(col+1)*3+1], s1r1));
                s2r1 = fmaf(g10, w2s[col*3+2], fmaf(g11, w2s[(col+1)*3+2], s2r1));
            }
            #pragma unroll
            for (int off = 1; off <= 2; off <<= 1) {
                pr0 += __shfl_xor_sync(0xffffffffu, pr0, off);
                pr1 += __shfl_xor_sync(0xffffffffu, pr1, off);
                s0r0 += __shfl_xor_sync(0xffffffffu, s0r0, off);
                s1r0 += __shfl_xor_sync(0xffffffffu, s1r0, off);
                s2r0 += __shfl_xor_sync(0xffffffffu, s2r0, off);
                s0r1 += __shfl_xor_sync(0xffffffffu, s0r1, off);
                s1r1 += __shfl_xor_sync(0xffffffffu, s1r1, off);
                s2r1 += __shfl_xor_sync(0xffffffffu, s2r1, off);
            }
            if ((lane & 3) == 0) {
                int r0 = m0 + (lane >> 2);
                float* p0 = pd + chalf*256 + r0*4;
                p0[0] = pr0; p0[1] = s0r0; p0[2] = s1r0; p0[3] = s2r0;
                float* p1 = pd + chalf*256 + (r0+8)*4;
                p1[0] = pr1; p1[1] = s0r1; p1[2] = s1r1; p1[3] = s2r1;
            }
        }
        __syncthreads();
        if (tid < 64) {
            int e = t*64 + tid;
            int r = g_er[e], c = g_ec[e];
            float psc = pd[tid*4+0] + pd[256 + tid*4+0] + bp2l[0];
            float s0  = pd[tid*4+1] + pd[256 + tid*4+1] + bs2l[0];
            float s1  = pd[tid*4+2] + pd[256 + tid*4+2] + bs2l[1];
            float s2  = pd[tid*4+3] + pd[256 + tid*4+3] + bs2l[2];
            float dp0 = g_pos[r*3+0] - g_pos[c*3+0];
            float dp1 = g_pos[r*3+1] - g_pos[c*3+1];
            float dp2 = g_pos[r*3+2] - g_pos[c*3+2];
            atomicAdd(&g_psum[r*3+0], dp0*psc);
            atomicAdd(&g_psum[r*3+1], dp1*psc);
            atomicAdd(&g_psum[r*3+2], dp2*psc);
            #pragma unroll
            for (int q = 0; q < 9; q++) {
                float diff = g_sh[r*9+q] - g_sh[c*9+q];
                atomicAdd(&g_ssum[r*9+q], diff * ((q == 0) ? s0 : (q < 4) ? s1 : s2));
            }
        }
    }
}

__global__ void posh_kernel() {
    int i = blockIdx.x*256 + threadIdx.x;
    if (i >= Nn) return;
    float inv = 1.0f / fmaxf(g_deg[i], 1.0f);
    #pragma unroll
    for (int q = 0; q < 3; q++) g_pos[i*3+q] += g_psum[i*3+q]*inv;
    #pragma unroll
    for (int q = 0; q < 9; q++) g_sh[i*9+q] += g_ssum[i*9+q]*inv;
}
__global__ void pool_kernel(const int* __restrict__ batch) {
    int idx = blockIdx.x*256 + threadIdx.x;
    if (idx >= Nn*140) return;
    int i = idx / 140, c = idx % 140;
    float v;
    if (c < 128)      v = g_feat[(size_t)i*128 + c];
    else if (c < 131) v = g_pos[i*3 + (c - 128)];
    else              v = g_sh[i*9 + (c - 131)];
    atomicAdd(&g_pool[batch[i]*140 + c], v);
}
__global__ void pred_kernel(const float* __restrict__ Wpred, const float* __restrict__ bpred,
                            float* __restrict__ out) {
    int g = blockIdx.x, lane = threadIdx.x;
    float s = 0.f;
    for (int c = lane; c < 140; c += 32)
        s = fmaf(g_pool[g*140 + c], Wpred[c], s);
    #pragma unroll
    for (int off = 16; off > 0; off >>= 1)
        s += __shfl_xor_sync(0xffffffffu, s, off);
    if (lane == 0) out[g] = s + bpred[0];
}

extern "C" void kernel_launch(void* const* d_in, const int* in_sizes, int n_in,
                              void* d_out, int out_size) {
    const int*   atoms = (const int*)d_in[0];
    const int*   ei    = (const int*)d_in[1];
    const int*   batch = (const int*)d_in[2];
    const float* pos   = (const float*)d_in[3];
    const float* emb   = (const float*)d_in[4];
    const float* Wsi1  = (const float*)d_in[5];  const float* bsi1  = (const float*)d_in[6];
    const float* Wsi2  = (const float*)d_in[7];  const float* bsi2  = (const float*)d_in[8];
    const float* WsiC1 = (const float*)d_in[9];  const float* bsiC1 = (const float*)d_in[10];
    const float* WsiC2 = (const float*)d_in[11]; const float* bsiC2 = (const float*)d_in[12];
    const float* Wm1   = (const float*)d_in[13]; const float* bm1   = (const float*)d_in[14];
    const float* Wm2   = (const float*)d_in[15]; const float* bm2   = (const float*)d_in[16];
    const float* Wp1   = (const float*)d_in[17]; const float* bp1   = (const float*)d_in[18];
    const float* Wp2   = (const float*)d_in[19]; const float* bp2   = (const float*)d_in[20];
    const float* Wn1   = (const float*)d_in[21]; const float* bn1   = (const float*)d_in[22];
    const float* Wn2   = (const float*)d_in[23]; const float* bn2   = (const float*)d_in[24];
    const float* Ws1   = (const float*)d_in[25]; const float* bs1   = (const float*)d_in[26];
    const float* Ws2   = (const float*)d_in[27]; const float* bs2   = (const float*)d_in[28];
    const float* Wpred = (const float*)d_in[29]; const float* bpred = (const float*)d_in[30];
    float* out = (float*)d_out;

    cudaFuncSetAttribute(featab_kernel, cudaFuncAttributeMaxDynamicSharedMemorySize, FAB_SMEM);
    cudaFuncSetAttribute(nodeup_kernel, cudaFuncAttributeMaxDynamicSharedMemorySize, NU_SMEM);
    cudaFuncSetAttribute(edge_hm_mma, cudaFuncAttributeMaxDynamicSharedMemorySize, E1_SMEM);
    cudaFuncSetAttribute(edge_ps_mma, cudaFuncAttributeMaxDynamicSharedMemorySize, E2_SMEM);

    void *p_msum, *p_psum, *p_ssum, *p_deg, *p_com, *p_cnt, *p_pool, *p_pos, *p_cur;
    cudaGetSymbolAddress(&p_msum, g_msum);
    cudaGetSymbolAddress(&p_psum, g_psum);
    cudaGetSymbolAddress(&p_ssum, g_ssum);
    cudaGetSymbolAddress(&p_deg,  g_deg);
    cudaGetSymbolAddress(&p_com,  g_com);
    cudaGetSymbolAddress(&p_cnt,  g_cnt);
    cudaGetSymbolAddress(&p_pool, g_pool);
    cudaGetSymbolAddress(&p_pos,  g_pos);
    cudaGetSymbolAddress(&p_cur,  g_cursor);

    cudaMemsetAsync(p_deg,  0, Nn*4, 0);
    cudaMemsetAsync(p_com,  0, Gg*3*4, 0);
    cudaMemsetAsync(p_cnt,  0, Gg*4, 0);
    cudaMemsetAsync(p_ssum, 0, Nn*9*4, 0);
    cudaMemsetAsync(p_pool, 0, Gg*140*4, 0);
    cudaMemsetAsync(p_cur,  0, Nn*4, 0);
    cudaMemcpyAsync(p_pos, pos, Nn*3*4, cudaMemcpyDeviceToDevice, 0);

    wprep_kernel<<<15, 256>>>(Wm2, Wp1, Ws1);
    node_init_kernel<<<(Nn*128)/256, 256>>>(atoms, emb);
    com_kernel<<<(Nn + 255)/256, 256>>>(batch);
    deg_kernel<<<(Ee + 255)/256, 256>>>(ei);
    scan_kernel<<<1, 256>>>();
    sortscatter_kernel<<<(Ee + 255)/256, 256>>>(ei);
    vocab_kernel<<<10, 128>>>(emb, Wsi1, WsiC1, bsiC1, WsiC2, bsiC2);
    edge_init_kernel<<<Ee/8, 256>>>(atoms, Wsi1, bsi1, Wsi2, bsi2);
    sh_init_kernel<<<(Nn + 255)/256, 256>>>(atoms, batch);

    int gridN = (Nn + 63)/64;

    for (int l = 0; l < Ll; l++) {
        cudaMemsetAsync(p_msum, 0, (size_t)Nn*128*4, 0);
        cudaMemsetAsync(p_psum, 0, Nn*3*4, 0);
        cudaMemsetAsync(p_ssum, 0, Nn*9*4, 0);

        featab_kernel<<<gridN, 256, FAB_SMEM>>>(
            Wm1 + (size_t)l*260*128, Wm1 + ((size_t)l*260 + 128)*128);

        edge_hm_mma<<<148, 256, E1_SMEM>>>(
            bm2 + l*128, Wm1 + ((size_t)l*260 + 256)*128, bm1 + l*128, l);

        edge_ps_mma<<<148, 256, E2_SMEM>>>(
            bp1 + l*128, Wp2 + l*128, bp2 + l,
            bs1 + l*128, Ws2 + l*384, bs2 + l*3, l);

        posh_kernel<<<(Nn + 255)/256, 256>>>();

        nodeup_kernel<<<gridN, 256, NU_SMEM>>>(
            Wn1 + (size_t)l*256*128, Wn1 + ((size_t)l*256 + 128)*128,
            Wn2 + (size_t)l*128*128, bn1 + l*128, bn2 + l*128);
    }

    pool_kernel<<<(Nn*140 + 255)/256, 256>>>(batch);
    pred_kernel<<<Gg, 32>>>(Wpred, bpred, out);
}

// round 10
// speedup vs baseline: 1.4329x; 1.2385x over previous
#include <cuda_runtime.h>
#include <cuda_bf16.h>
#include <cstdint>
#include <math.h>

#define Nn 10000
#define Ee 160000
#define Gg 100
#define Ll 5
#define NT 1250   // 128-edge tiles

typedef unsigned long long u64;
typedef unsigned short ush;

__device__ float g_feat [Nn*128];
__device__ float g_featA[Nn*128];
__device__ float g_featB[Nn*128];
__device__ float g_sh   [Nn*9];
__device__ float g_pos  [Nn*3];
__device__ float g_msum [Nn*128];
__device__ float g_psum [Nn*3];
__device__ float g_ssum [Nn*9];
__device__ float g_deg  [Nn];
__device__ float g_com  [Gg*3];
__device__ float g_cnt  [Gg];
__device__ float g_P1   [10*128];
__device__ float g_P2   [10*128];
__device__ float g_cmsg [10];
__device__ float g_pool [Gg*140];
__device__ int   g_off  [Nn];
__device__ int   g_cursor[Nn];
__device__ int   g_er   [Ee];
__device__ int   g_ec   [Ee];
__device__ ush   g_mh  [(size_t)NT*16384];  // m hi-bf16, [tile][128][128]
__device__ ush   g_ml  [(size_t)NT*16384];  // m lo-bf16
__device__ ush   g_Wbh [15*17408];          // [slot][n*136+k] hi
__device__ ush   g_Wbl [15*17408];          // lo

__device__ __forceinline__ float silu_f(float x) { return x / (1.0f + __expf(-x)); }

__device__ __forceinline__ void sph2(float vx, float vy, float vz, float* o) {
    const float S3 = 1.7320508075688772f, HS3 = 0.8660254037844386f;
    float r = sqrtf(vx*vx + vy*vy + vz*vz);
    float inv = 1.0f / fmaxf(r, 1e-12f);
    float x = vx*inv, y = vy*inv, z = vz*inv;
    o[0] = S3*x*z; o[1] = S3*x*y; o[2] = y*y - 0.5f*(x*x + z*z);
    o[3] = S3*y*z; o[4] = HS3*(z*z - x*x);
}

// ---- packed f32x2 (node GEMMs, proven) ----
__device__ __forceinline__ u64 fma2(u64 a, u64 b, u64 c) {
    u64 d; asm("fma.rn.f32x2 %0, %1, %2, %3;" : "=l"(d) : "l"(a), "l"(b), "l"(c)); return d;
}
__device__ __forceinline__ u64 pk2(float x) {
    u64 d; asm("mov.b64 %0, {%1, %1};" : "=l"(d) : "r"(__float_as_uint(x))); return d;
}
__device__ __forceinline__ float2 up2(u64 v) {
    float2 f; asm("mov.b64 {%0, %1}, %2;" : "=f"(f.x), "=f"(f.y) : "l"(v)); return f;
}
template<int RPW>
__device__ __forceinline__ void mmk(const float* __restrict__ As, const float* __restrict__ Ws,
                                    int r0, int c0, u64 acc[RPW][2]) {
    const float* ap = As + r0*128;
    const float* wp = Ws + c0;
    #pragma unroll 4
    for (int k0 = 0; k0 < 128; k0 += 2) {
        float2 a2[RPW];
        #pragma unroll
        for (int i = 0; i < RPW; i++) a2[i] = *(const float2*)(ap + i*128 + k0);
        ulonglong2 p0 = *(const ulonglong2*)(wp + k0*128);
        ulonglong2 q0 = *(const ulonglong2*)(wp + (k0+1)*128);
        #pragma unroll
        for (int i = 0; i < RPW; i++) {
            u64 ax = pk2(a2[i].x);
            acc[i][0] = fma2(ax, p0.x, acc[i][0]);
            acc[i][1] = fma2(ax, p0.y, acc[i][1]);
        }
        #pragma unroll
        for (int i = 0; i < RPW; i++) {
            u64 ay = pk2(a2[i].y);
            acc[i][0] = fma2(ay, q0.x, acc[i][0]);
            acc[i][1] = fma2(ay, q0.y, acc[i][1]);
        }
    }
}

// ---- HMMA helpers ----
__device__ __forceinline__ unsigned smem_u32(const void* p) {
    unsigned a; asm("{ .reg .u64 t; cvta.to.shared.u64 t, %1; cvt.u32.u64 %0, t; }" : "=r"(a) : "l"(p));
    return a;
}
__device__ __forceinline__ void ldsm4(unsigned addr, unsigned* r) {
    asm volatile("ldmatrix.sync.aligned.m8n8.x4.shared.b16 {%0,%1,%2,%3}, [%4];"
        : "=r"(r[0]), "=r"(r[1]), "=r"(r[2]), "=r"(r[3]) : "r"(addr));
}
__device__ __forceinline__ void mma_bf16(float* d, const unsigned* a, unsigned b0, unsigned b1) {
    asm volatile("mma.sync.aligned.m16n8k16.row.col.f32.bf16.bf16.f32 "
        "{%0,%1,%2,%3},{%4,%5,%6,%7},{%8,%9},{%0,%1,%2,%3};"
        : "+f"(d[0]), "+f"(d[1]), "+f"(d[2]), "+f"(d[3])
        : "r"(a[0]), "r"(a[1]), "r"(a[2]), "r"(a[3]), "r"(b0), "r"(b1));
}
__device__ __forceinline__ void split_bf16(float v, unsigned& h, unsigned& l) {
    __nv_bfloat16 hb = __float2bfloat16(v);
    h = (unsigned)__bfloat16_as_ushort(hb);
    l = (unsigned)__bfloat16_as_ushort(__float2bfloat16(v - __bfloat162float(hb)));
}

// split-bf16 GEMM core: rows m0..+15 x cols n0..+63, K=128; A/B ush stride 136 (272 B)
__device__ __forceinline__ void hmma_gemm(unsigned aH, unsigned aL, unsigned bH, unsigned bL,
                                          int m0, int n0, int lane, float acc[8][4]) {
    unsigned aoff = (unsigned)((m0 + (lane & 15))*272 + (lane >> 4)*16);
    unsigned boff = (unsigned)((n0 + (lane & 15))*272 + (lane >> 4)*16);
    #pragma unroll
    for (int kk = 0; kk < 8; kk++) {
        unsigned kb = kk*32;
        unsigned Ah[4], Al[4];
        ldsm4(aH + aoff + kb, Ah);
        ldsm4(aL + aoff + kb, Al);
        #pragma unroll
        for (int t = 0; t < 4; t++) {
            unsigned bo = boff + t*16*272 + kb;
            unsigned Bh[4], Bl[4];
            ldsm4(bH + bo, Bh);
            ldsm4(bL + bo, Bl);
            mma_bf16(acc[2*t],   Ah, Bh[0], Bh[2]);
            mma_bf16(acc[2*t],   Ah, Bl[0], Bl[2]);
            mma_bf16(acc[2*t],   Al, Bh[0], Bh[2]);
            mma_bf16(acc[2*t+1], Ah, Bh[1], Bh[3]);
            mma_bf16(acc[2*t+1], Ah, Bl[1], Bl[3]);
            mma_bf16(acc[2*t+1], Al, Bh[1], Bh[3]);
        }
    }
}

// weights -> split-bf16 [n][k] stride-136 tiles; slot: l*3 + {0:Wm2,1:Wp1,2:Ws1}
__global__ void wprep_kernel(const float* __restrict__ Wm2, const float* __restrict__ Wp1,
                             const float* __restrict__ Ws1) {
    int bid = blockIdx.x, l = bid / 3, slot = bid % 3;
    const float* src = (slot == 0 ? Wm2 : (slot == 1 ? Wp1 : Ws1)) + (size_t)l*16384;
    ush* dh = g_Wbh + (size_t)bid*17408;
    ush* dl = g_Wbl + (size_t)bid*17408;
    for (int o = threadIdx.x; o < 16384; o += 256) {
        int k = o >> 7, n = o & 127;
        unsigned h, lo;
        split_bf16(src[k*128 + n], h, lo);
        dh[n*136 + k] = (ush)h;
        dl[n*136 + k] = (ush)lo;
    }
}

// ---- init kernels (proven) ----
__global__ void node_init_kernel(const int* __restrict__ atoms, const float* __restrict__ emb) {
    int idx = blockIdx.x*256 + threadIdx.x;
    g_feat[idx] = emb[atoms[idx >> 7]*128 + (idx & 127)];
}
__global__ void com_kernel(const int* __restrict__ batch) {
    int i = blockIdx.x*256 + threadIdx.x;
    if (i >= Nn) return;
    int b = batch[i];
    atomicAdd(&g_com[b*3+0], g_pos[i*3+0]);
    atomicAdd(&g_com[b*3+1], g_pos[i*3+1]);
    atomicAdd(&g_com[b*3+2], g_pos[i*3+2]);
    atomicAdd(&g_cnt[b], 1.0f);
}
__global__ void deg_kernel(const int* __restrict__ ei) {
    int e = blockIdx.x*256 + threadIdx.x;
    if (e < Ee) atomicAdd(&g_deg[ei[e]], 1.0f);
}
__global__ void scan_kernel() {
    __shared__ int part[256];
    int tid = threadIdx.x;
    int lo = tid*40, hi = (lo + 40 < Nn) ? lo + 40 : Nn;
    int s = 0;
    for (int i = lo; i < hi; i++) s += (int)g_deg[i];
    part[tid] = s;
    __syncthreads();
    for (int off = 1; off < 256; off <<= 1) {
        int v = part[tid] + ((tid >= off) ? part[tid - off] : 0);
        __syncthreads(); part[tid] = v; __syncthreads();
    }
    int base = (tid > 0) ? part[tid - 1] : 0;
    for (int i = lo; i < hi; i++) { g_off[i] = base; base += (int)g_deg[i]; }
}
__global__ void sortscatter_kernel(const int* __restrict__ ei) {
    int e = blockIdx.x*256 + threadIdx.x;
    if (e >= Ee) return;
    int r = ei[e], c = ei[Ee + e];
    int p = g_off[r] + atomicAdd(&g_cursor[r], 1);
    g_er[p] = r; g_ec[p] = c;
}
__global__ void vocab_kernel(const float* __restrict__ emb, const float* __restrict__ Wsi1,
                             const float* __restrict__ WsiC1, const float* __restrict__ bsiC1,
                             const float* __restrict__ WsiC2, const float* __restrict__ bsiC2) {
    __shared__ float es[128], redv[128];
    int v = blockIdx.x, j = threadIdx.x;
    es[j] = emb[v*128 + j];
    __syncthreads();
    float p1 = 0.f, p2 = 0.f, hc = 0.f;
    for (int k = 0; k < 128; k++) {
        float e = es[k];
        p1 = fmaf(e, Wsi1[(1 + k)*128 + j], p1);
        p2 = fmaf(e, Wsi1[(129 + k)*128 + j], p2);
        hc = fmaf(e, WsiC1[k*128 + j], hc);
    }
    g_P1[v*128 + j] = p1; g_P2[v*128 + j] = p2;
    redv[j] = silu_f(hc + bsiC1[j]) * WsiC2[j*3 + 2];
    __syncthreads();
    for (int s = 64; s > 0; s >>= 1) {
        if (j < s) redv[j] += redv[j + s];
        __syncthreads();
    }
    if (j == 0) g_cmsg[v] = redv[0] + bsiC2[2];
}
__global__ void edge_init_kernel(const int* __restrict__ atoms,
                                 const float* __restrict__ Wsi1, const float* __restrict__ bsi1,
                                 const float* __restrict__ Wsi2, const float* __restrict__ bsi2) {
    int e = blockIdx.x*8 + (threadIdx.x >> 5);
    int lane = threadIdx.x & 31;
    int r = g_er[e], c = g_ec[e];
    float dp0 = g_pos[r*3+0] - g_pos[c*3+0];
    float dp1 = g_pos[r*3+1] - g_pos[c*3+1];
    float dp2 = g_pos[r*3+2] - g_pos[c*3+2];
    float dist = sqrtf(dp0*dp0 + dp1*dp1 + dp2*dp2);
    int ar = atoms[r], ac = atoms[c];
    float partial = 0.f;
    #pragma unroll
    for (int q = 0; q < 4; q++) {
        int d = lane + q*32;
        partial = fmaf(silu_f(dist*Wsi1[d] + g_P1[ar*128 + d] + g_P2[ac*128 + d] + bsi1[d]),
                       Wsi2[d*3 + 2], partial);
    }
    #pragma unroll
    for (int off = 16; off > 0; off >>= 1)
        partial += __shfl_xor_sync(0xffffffffu, partial, off);
    if (lane == 0) {
        float msg2 = partial + bsi2[2];
        float y2[5];
        sph2(dp0, dp1, dp2, y2);
        #pragma unroll
        for (int q = 0; q < 5; q++)
            atomicAdd(&g_ssum[r*9 + 4 + q], y2[q]*msg2);
    }
}
__global__ void sh_init_kernel(const int* __restrict__ atoms, const int* __restrict__ batch) {
    int i = blockIdx.x*256 + threadIdx.x;
    if (i >= Nn) return;
    float dg = fmaxf(g_deg[i], 1.0f);
    int b = batch[i];
    float cn = fmaxf(g_cnt[b], 1.0f);
    float y2[5];
    sph2(g_pos[i*3+0] - g_com[b*3+0]/cn, g_pos[i*3+1] - g_com[b*3+1]/cn,
         g_pos[i*3+2] - g_com[b*3+2]/cn, y2);
    float cm = g_cmsg[atoms[i]];
    #pragma unroll
    for (int q = 0; q < 4; q++) g_sh[i*9 + q] = 0.0f;
    #pragma unroll
    for (int q = 0; q < 5; q++)
        g_sh[i*9 + 4 + q] = g_ssum[i*9 + 4 + q]/dg + cm*y2[q];
}

// ---- featAB (scalar, proven) ----
#define FAB_SMEM ((64*128 + 2*128*128)*4)
__global__ void __launch_bounds__(256)
featab_kernel(const float* __restrict__ Wa, const float* __restrict__ Wb) {
    extern __shared__ float sm[];
    float* As = sm;
    float* Was = As + 64*128;
    float* Wbs = Was + 128*128;
    int tid = threadIdx.x, row0 = blockIdx.x * 64;
    for (int idx = tid; idx < 64*32; idx += 256) {
        int r = idx >> 5, c4 = (idx & 31)*4;
        float4 v = make_float4(0.f,0.f,0.f,0.f);
        if (row0 + r < Nn) v = *(const float4*)(g_feat + (size_t)(row0 + r)*128 + c4);
        *(float4*)(As + r*128 + c4) = v;
    }
    for (int idx = tid; idx < 128*32; idx += 256) {
        *(float4*)(Was + idx*4) = *(const float4*)(Wa + (size_t)idx*4);
        *(float4*)(Wbs + idx*4) = *(const float4*)(Wb + (size_t)idx*4);
    }
    __syncthreads();
    int ty = tid >> 5, tx = tid & 31, r0 = ty*8, c0 = tx*4;
    u64 acc[8][2];
    #pragma unroll
    for (int i = 0; i < 8; i++) { acc[i][0] = 0; acc[i][1] = 0; }
    mmk<8>(As, Was, r0, c0, acc);
    #pragma unroll
    for (int i = 0; i < 8; i++) {
        int r = row0 + r0 + i;
        if (r >= Nn) continue;
        float2 f0 = up2(acc[i][0]), f1 = up2(acc[i][1]);
        *(float4*)(g_featA + (size_t)r*128 + c0) = make_float4(f0.x, f0.y, f1.x, f1.y);
    }
    #pragma unroll
    for (int i = 0; i < 8; i++) { acc[i][0] = 0; acc[i][1] = 0; }
    mmk<8>(As, Wbs, r0, c0, acc);
    #pragma unroll
    for (int i = 0; i < 8; i++) {
        int r = row0 + r0 + i;
        if (r >= Nn) continue;
        float2 f0 = up2(acc[i][0]), f1 = up2(acc[i][1]);
        *(float4*)(g_featB + (size_t)r*128 + c0) = make_float4(f0.x, f0.y, f1.x, f1.y);
    }
}

// ---- node update (scalar, proven) ----
#define NU_SMEM ((2*64*128 + 2*128*128 + 256)*4)
__global__ void __launch_bounds__(256)
nodeup_kernel(const float* __restrict__ W5, const float* __restrict__ W6,
              const float* __restrict__ W7,
              const float* __restrict__ b1, const float* __restrict__ b2) {
    extern __shared__ float sm[];
    float* A1 = sm;
    float* A2 = A1 + 64*128;
    float* Wx = A2 + 64*128;
    float* Wy = Wx + 128*128;
    float* bb = Wy + 128*128;
    int tid = threadIdx.x, row0 = blockIdx.x * 64;
    for (int idx = tid; idx < 64*32; idx += 256) {
        int r = idx >> 5, c4 = (idx & 31)*4;
        float4 v1 = make_float4(0.f,0.f,0.f,0.f), v2 = v1;
        if (row0 + r < Nn) {
            v1 = *(const float4*)(g_feat + (size_t)(row0 + r)*128 + c4);
            v2 = *(const float4*)(g_msum + (size_t)(row0 + r)*128 + c4);
            float inv = 1.0f / fmaxf(g_deg[row0 + r], 1.0f);
            v2.x *= inv; v2.y *= inv; v2.z *= inv; v2.w *= inv;
        }
        *(float4*)(A1 + r*128 + c4) = v1;
        *(float4*)(A2 + r*128 + c4) = v2;
    }
    for (int idx = tid; idx < 128*32; idx += 256) {
        *(float4*)(Wx + idx*4) = *(const float4*)(W5 + (size_t)idx*4);
        *(float4*)(Wy + idx*4) = *(const float4*)(W6 + (size_t)idx*4);
    }
    if (tid < 128) { bb[tid] = b1[tid]; bb[128 + tid] = b2[tid]; }
    __syncthreads();
    int ty = tid >> 5, tx = tid & 31, r0 = ty*8, c0 = tx*4;
    u64 acc[8][2];
    #pragma unroll
    for (int i = 0; i < 8; i++) { acc[i][0] = 0; acc[i][1] = 0; }
    mmk<8>(A1, Wx, r0, c0, acc);
    mmk<8>(A2, Wy, r0, c0, acc);
    __syncthreads();
    #pragma unroll
    for (int i = 0; i < 8; i++) {
        float2 f0 = up2(acc[i][0]), f1 = up2(acc[i][1]);
        A1[(r0+i)*128 + c0 + 0] = silu_f(f0.x + bb[c0]);
        A1[(r0+i)*128 + c0 + 1] = silu_f(f0.y + bb[c0+1]);
        A1[(r0+i)*128 + c0 + 2] = silu_f(f1.x + bb[c0+2]);
        A1[(r0+i)*128 + c0 + 3] = silu_f(f1.y + bb[c0+3]);
    }
    for (int idx = tid; idx < 128*32; idx += 256)
        *(float4*)(Wx + idx*4) = *(const float4*)(W7 + (size_t)idx*4);
    __syncthreads();
    #pragma unroll
    for (int i = 0; i < 8; i++) { acc[i][0] = 0; acc[i][1] = 0; }
    mmk<8>(A1, Wx, r0, c0, acc);
    #pragma unroll
    for (int i = 0; i < 8; i++) {
        int r = row0 + r0 + i;
        if (r >= Nn) continue;
        float2 f0 = up2(acc[i][0]), f1 = up2(acc[i][1]);
        *(float4*)(g_feat + (size_t)r*128 + c0) =
            make_float4(f0.x + bb[128+c0], f0.y + bb[128+c0+1],
                        f1.x + bb[128+c0+2], f1.y + bb[128+c0+3]);
    }
}

// ============ E1: HMMA h-build + m-GEMM, 512 threads, 128-edge tiles ============
// bytes: Ah 0 | Al 34816 | Wh 69632 | Wl 104448 | m_s(f32,[128][137]) 139264 |
// scal 209408 | bh 211456 | wtl 211968 | ridx 214528 | cidx 215040 -> 215552
#define E1_SMEM 215552
__global__ void __launch_bounds__(512, 1)
edge_hm_mma(const float* __restrict__ bm2l, const float* __restrict__ Wm1tail,
            const float* __restrict__ bm1l, int layer) {
    extern __shared__ char smc[];
    unsigned sb = smem_u32(smc);
    float* m_s  = (float*)(smc + 139264);    // [128][137]
    float* scal = (float*)(smc + 209408);
    float* bh   = (float*)(smc + 211456);
    float* wtl  = (float*)(smc + 211968);
    int* ridx   = (int*)(smc + 214528);
    int* cidx   = (int*)(smc + 215040);
    int tid = threadIdx.x, w = tid >> 5, lane = tid & 31;

    {
        const uint4* sh = (const uint4*)(g_Wbh + (size_t)(layer*3)*17408);
        const uint4* sl = (const uint4*)(g_Wbl + (size_t)(layer*3)*17408);
        uint4* dh = (uint4*)(smc + 69632);
        uint4* dl = (uint4*)(smc + 104448);
        for (int i = tid; i < 2176; i += 512) { dh[i] = sh[i]; dl[i] = sl[i]; }
    }
    if (tid < 128) bh[tid] = bm2l[tid];
    for (int i = tid; i < 640; i += 512)
        wtl[i] = (i < 512) ? Wm1tail[i] : bm1l[i - 512];

    int m0 = (w & 7)*16, n0 = (w >> 3)*64;

    for (int t = blockIdx.x; t < NT; t += gridDim.x) {
        int e0 = t*128;
        __syncthreads();
        if (tid < 128) {
            int r = g_er[e0 + tid], c = g_ec[e0 + tid];
            ridx[tid] = r; cidx[tid] = c;
            float dp0 = g_pos[r*3+0] - g_pos[c*3+0];
            float dp1 = g_pos[r*3+1] - g_pos[c*3+1];
            float dp2 = g_pos[r*3+2] - g_pos[c*3+2];
            float ip2 = 0.f;
            #pragma unroll
            for (int q = 4; q < 9; q++) ip2 += g_sh[r*9+q]*g_sh[c*9+q];
            scal[tid*4+0] = dp0*dp0 + dp1*dp1 + dp2*dp2;
            scal[tid*4+1] = g_sh[r*9+0]*g_sh[c*9+0];
            scal[tid*4+2] = g_sh[r*9+1]*g_sh[c*9+1] + g_sh[r*9+2]*g_sh[c*9+2] + g_sh[r*9+3]*g_sh[c*9+3];
            scal[tid*4+3] = ip2;
        }
        __syncthreads();
        // h-build -> split-bf16 A tiles (128 edges x 128 cols)
        #pragma unroll
        for (int q = 0; q < 8; q++) {
            int idx = tid + q*512;
            int e = idx >> 5, c4 = (idx & 31)*4;
            int r = ridx[e], c = cidx[e];
            float4 fa = *(const float4*)(g_featA + (size_t)r*128 + c4);
            float4 fb = *(const float4*)(g_featB + (size_t)c*128 + c4);
            float d2 = scal[e*4+0], i0 = scal[e*4+1], i1 = scal[e*4+2], i2 = scal[e*4+3];
            float hv[4];
            hv[0] = silu_f(fa.x + fb.x + d2*wtl[c4+0] + i0*wtl[128+c4+0] + i1*wtl[256+c4+0] + i2*wtl[384+c4+0] + wtl[512+c4+0]);
            hv[1] = silu_f(fa.y + fb.y + d2*wtl[c4+1] + i0*wtl[128+c4+1] + i1*wtl[256+c4+1] + i2*wtl[384+c4+1] + wtl[512+c4+1]);
            hv[2] = silu_f(fa.z + fb.z + d2*wtl[c4+2] + i0*wtl[128+c4+2] + i1*wtl[256+c4+2] + i2*wtl[384+c4+2] + wtl[512+c4+2]);
            hv[3] = silu_f(fa.w + fb.w + d2*wtl[c4+3] + i0*wtl[128+c4+3] + i1*wtl[256+c4+3] + i2*wtl[384+c4+3] + wtl[512+c4+3]);
            unsigned h[4], l[4];
            #pragma unroll
            for (int j = 0; j < 4; j++) split_bf16(hv[j], h[j], l[j]);
            unsigned off = (unsigned)(e*136 + c4)*2u;
            *(uint2*)(smc + off)         = make_uint2(h[0]|(h[1]<<16), h[2]|(h[3]<<16));
            *(uint2*)(smc + 34816 + off) = make_uint2(l[0]|(l[1]<<16), l[2]|(l[3]<<16));
        }
        __syncthreads();
        float acc[8][4];
        #pragma unroll
        for (int i = 0; i < 8; i++)
            #pragma unroll
            for (int j = 0; j < 4; j++) acc[i][j] = 0.f;
        hmma_gemm(sb, sb + 34816, sb + 69632, sb + 104448, m0, n0, lane, acc);
        {
            int r0 = m0 + (lane >> 2), r1 = r0 + 8;
            #pragma unroll
            for (int s = 0; s < 8; s++) {
                int col = n0 + s*8 + (lane & 3)*2;
                m_s[r0*137 + col]     = silu_f(acc[s][0] + bh[col]);
                m_s[r0*137 + col + 1] = silu_f(acc[s][1] + bh[col+1]);
                m_s[r1*137 + col]     = silu_f(acc[s][2] + bh[col]);
                m_s[r1*137 + col + 1] = silu_f(acc[s][3] + bh[col+1]);
            }
        }
        __syncthreads();
        // msum sorted-run RED: 4 segs of 32 edges, col per thread (stride 137 -> conflict-free)
        {
            int c = tid & 127, seg = tid >> 7;
            int eb = seg*32;
            float agg = 0.f;
            int ar = ridx[eb];
            for (int e = eb; e < eb + 32; e++) {
                float v = m_s[e*137 + c];
                int r = ridx[e];
                if (r != ar) { atomicAdd(&g_msum[(size_t)ar*128 + c], agg); agg = v; ar = r; }
                else agg += v;
            }
            atomicAdd(&g_msum[(size_t)ar*128 + c], agg);
        }
        // m -> gmem split-bf16 (row-major [128][128])
        {
            unsigned* gh = (unsigned*)(g_mh + (size_t)t*16384);
            unsigned* gl = (unsigned*)(g_ml + (size_t)t*16384);
            #pragma unroll
            for (int q = 0; q < 16; q++) {
                int idx = tid + q*512;           // pair index 0..8191
                int e = idx >> 6, cp = idx & 63;
                float v0 = m_s[e*137 + cp*2], v1 = m_s[e*137 + cp*2 + 1];
                unsigned h0, l0, h1, l1;
                split_bf16(v0, h0, l0);
                split_bf16(v1, h1, l1);
                gh[idx] = h0 | (h1 << 16);
                gl[idx] = l0 | (l1 << 16);
            }
        }
    }
}

// ============ E2: HMMA p+s GEMMs, 512 threads, 128-edge tiles ============
// bytes: Ah 0 | Al 34816 | Wph 69632 | Wpl 104448 | Wsh 139264 | Wsl 174080 |
// bhp 208896 | bhs 209408 | w2p 209920 | w2s 210432 | pd 211968 ([2][128][4] f32) -> 216064
#define E2_SMEM 216064
__global__ void __launch_bounds__(512, 1)
edge_ps_mma(const float* __restrict__ bp1l, const float* __restrict__ Wp2l,
            const float* __restrict__ bp2l,
            const float* __restrict__ bs1l, const float* __restrict__ Ws2l,
            const float* __restrict__ bs2l, int layer) {
    extern __shared__ char smc[];
    unsigned sb = smem_u32(smc);
    float* bhp = (float*)(smc + 208896);
    float* bhs = (float*)(smc + 209408);
    float* w2p = (float*)(smc + 209920);
    float* w2s = (float*)(smc + 210432);
    float* pd  = (float*)(smc + 211968);     // [2][128][4]
    int tid = threadIdx.x, w = tid >> 5, lane = tid & 31;

    {
        const uint4* ph = (const uint4*)(g_Wbh + (size_t)(layer*3 + 1)*17408);
        const uint4* pl = (const uint4*)(g_Wbl + (size_t)(layer*3 + 1)*17408);
        const uint4* sh = (const uint4*)(g_Wbh + (size_t)(layer*3 + 2)*17408);
        const uint4* sl = (const uint4*)(g_Wbl + (size_t)(layer*3 + 2)*17408);
        uint4* dph = (uint4*)(smc + 69632);
        uint4* dpl = (uint4*)(smc + 104448);
        uint4* dsh = (uint4*)(smc + 139264);
        uint4* dsl = (uint4*)(smc + 174080);
        for (int i = tid; i < 2176; i += 512) {
            dph[i] = ph[i]; dpl[i] = pl[i]; dsh[i] = sh[i]; dsl[i] = sl[i];
        }
    }
    if (tid < 128) {
        bhp[tid] = bp1l[tid]; bhs[tid] = bs1l[tid]; w2p[tid] = Wp2l[tid];
        w2s[tid*3+0] = Ws2l[tid*3+0]; w2s[tid*3+1] = Ws2l[tid*3+1]; w2s[tid*3+2] = Ws2l[tid*3+2];
    }

    int m0 = (w & 7)*16, n0 = (w >> 3)*64;
    int chalf = w >> 3;

    for (int t = blockIdx.x; t < NT; t += gridDim.x) {
        __syncthreads();
        // load m tile (hi/lo) into A (stride 136 ush)
        {
            const char* srh = (const char*)(g_mh + (size_t)t*16384);
            const char* srl = (const char*)(g_ml + (size_t)t*16384);
            #pragma unroll
            for (int q = 0; q < 4; q++) {
                int ch = tid + q*512;             // 0..2047 chunks of 16B
                int e = ch >> 4, c16 = ch & 15;
                unsigned dof = (unsigned)(e*272 + c16*16);
                asm volatile("cp.async.cg.shared.global [%0], [%1], 16;"
                             :: "r"(sb + dof), "l"(srh + (size_t)ch*16) : "memory");
                asm volatile("cp.async.cg.shared.global [%0], [%1], 16;"
                             :: "r"(sb + 34816u + dof), "l"(srl + (size_t)ch*16) : "memory");
            }
            asm volatile("cp.async.commit_group;" ::: "memory");
            asm volatile("cp.async.wait_group 0;" ::: "memory");
        }
        __syncthreads();
        float accp[8][4], accs[8][4];
        #pragma unroll
        for (int i = 0; i < 8; i++)
            #pragma unroll
            for (int j = 0; j < 4; j++) { accp[i][j] = 0.f; accs[i][j] = 0.f; }
        {
            unsigned aoff = (unsigned)((m0 + (lane & 15))*272 + (lane >> 4)*16);
            unsigned boff = (unsigned)((n0 + (lane & 15))*272 + (lane >> 4)*16);
            #pragma unroll
            for (int kk = 0; kk < 8; kk++) {
                unsigned kb = kk*32;
                unsigned Ah[4], Al[4];
                ldsm4(sb + aoff + kb, Ah);
                ldsm4(sb + 34816u + aoff + kb, Al);
                #pragma unroll
                for (int tt = 0; tt < 4; tt++) {
                    unsigned bo = boff + tt*16*272 + kb;
                    unsigned Bh[4], Bl[4];
                    ldsm4(sb + 69632u + bo, Bh);
                    ldsm4(sb + 104448u + bo, Bl);
                    mma_bf16(accp[2*tt],   Ah, Bh[0], Bh[2]);
                    mma_bf16(accp[2*tt],   Ah, Bl[0], Bl[2]);
                    mma_bf16(accp[2*tt],   Al, Bh[0], Bh[2]);
                    mma_bf16(accp[2*tt+1], Ah, Bh[1], Bh[3]);
                    mma_bf16(accp[2*tt+1], Ah, Bl[1], Bl[3]);
                    mma_bf16(accp[2*tt+1], Al, Bh[1], Bh[3]);
                    ldsm4(sb + 139264u + bo, Bh);
                    ldsm4(sb + 174080u + bo, Bl);
                    mma_bf16(accs[2*tt],   Ah, Bh[0], Bh[2]);
                    mma_bf16(accs[2*tt],   Ah, Bl[0], Bl[2]);
                    mma_bf16(accs[2*tt],   Al, Bh[0], Bh[2]);
                    mma_bf16(accs[2*tt+1], Ah, Bh[1], Bh[3]);
                    mma_bf16(accs[2*tt+1], Ah, Bl[1], Bl[3]);
                    mma_bf16(accs[2*tt+1], Al, Bh[1], Bh[3]);
                }
            }
        }
        // epilogue: per-row dots + quad reduce
        {
            float pr0 = 0.f, pr1 = 0.f;
            float s0r0 = 0.f, s1r0 = 0.f, s2r0 = 0.f;
            float s0r1 = 0.f, s1r1 = 0.f, s2r1 = 0.f;
            #pragma unroll
            for (int s = 0; s < 8; s++) {
                int col = n0 + s*8 + (lane & 3)*2;
                float h00 = silu_f(accp[s][0] + bhp[col]);
                float h01 = silu_f(accp[s][1] + bhp[col+1]);
                float h10 = silu_f(accp[s][2] + bhp[col]);
                float h11 = silu_f(accp[s][3] + bhp[col+1]);
                pr0 = fmaf(h00, w2p[col], fmaf(h01, w2p[col+1], pr0));
                pr1 = fmaf(h10, w2p[col], fmaf(h11, w2p[col+1], pr1));
                float g00 = silu_f(accs[s][0] + bhs[col]);
                float g01 = silu_f(accs[s][1] + bhs[col+1]);
                float g10 = silu_f(accs[s][2] + bhs[col]);
                float g11 = silu_f(accs[s][3] + bhs[col+1]);
                s0r0 = fmaf(g00, w2s[col*3+0], fmaf(g01, w2s[(col+1)*3+0], s0r0));
                s1r0 = fmaf(g00, w2s[col*3+1], fmaf(g01, w2s[(col+1)*3+1], s1r0));
                s2r0 = fmaf(g00, w2s[col*3+2], fmaf(g01, w2s[(col+1)*3+2], s2r0));
                s0r1 = fmaf(g10, w2s[col*3+0], fmaf(g11, w2s[(col+1)*3+0], s0r1));
                s1r1 = fmaf(g10, w2s[col*3+1], fmaf(g11, w2s[(col+1)*3+1], s1r1));
                s2r1 = fmaf(g10, w2s[col*3+2], fmaf(g11, w2s[(col+1)*3+2], s2r1));
            }
            #pragma unroll
            for (int off = 1; off <= 2; off <<= 1) {
                pr0 += __shfl_xor_sync(0xffffffffu, pr0, off);
                pr1 += __shfl_xor_sync(0xffffffffu, pr1, off);
                s0r0 += __shfl_xor_sync(0xffffffffu, s0r0, off);
                s1r0 += __shfl_xor_sync(0xffffffffu, s1r0, off);
                s2r0 += __shfl_xor_sync(0xffffffffu, s2r0, off);
                s0r1 += __shfl_xor_sync(0xffffffffu, s0r1, off);
                s1r1 += __shfl_xor_sync(0xffffffffu, s1r1, off);
                s2r1 += __shfl_xor_sync(0xffffffffu, s2r1, off);
            }
            if ((lane & 3) == 0) {
                int r0 = m0 + (lane >> 2);
                float* p0 = pd + chalf*512 + r0*4;
                p0[0] = pr0; p0[1] = s0r0; p0[2] = s1r0; p0[3] = s2r0;
                float* p1 = pd + chalf*512 + (r0+8)*4;
                p1[0] = pr1; p1[1] = s0r1; p1[2] = s1r1; p1[3] = s2r1;
            }
        }
        __syncthreads();
        if (tid < 128) {
            int e = t*128 + tid;
            int r = g_er[e], c = g_ec[e];
            float psc = pd[tid*4+0] + pd[512 + tid*4+0] + bp2l[0];
            float s0  = pd[tid*4+1] + pd[512 + tid*4+1] + bs2l[0];
            float s1  = pd[tid*4+2] + pd[512 + tid*4+2] + bs2l[1];
            float s2  = pd[tid*4+3] + pd[512 + tid*4+3] + bs2l[2];
            float dp0 = g_pos[r*3+0] - g_pos[c*3+0];
            float dp1 = g_pos[r*3+1] - g_pos[c*3+1];
            float dp2 = g_pos[r*3+2] - g_pos[c*3+2];
            atomicAdd(&g_psum[r*3+0], dp0*psc);
            atomicAdd(&g_psum[r*3+1], dp1*psc);
            atomicAdd(&g_psum[r*3+2], dp2*psc);
            #pragma unroll
            for (int q = 0; q < 9; q++) {
                float diff = g_sh[r*9+q] - g_sh[c*9+q];
                atomicAdd(&g_ssum[r*9+q], diff * ((q == 0) ? s0 : (q < 4) ? s1 : s2));
            }
        }
    }
}

__global__ void posh_kernel() {
    int i = blockIdx.x*256 + threadIdx.x;
    if (i >= Nn) return;
    float inv = 1.0f / fmaxf(g_deg[i], 1.0f);
    #pragma unroll
    for (int q = 0; q < 3; q++) g_pos[i*3+q] += g_psum[i*3+q]*inv;
    #pragma unroll
    for (int q = 0; q < 9; q++) g_sh[i*9+q] += g_ssum[i*9+q]*inv;
}
__global__ void pool_kernel(const int* __restrict__ batch) {
    int idx = blockIdx.x*256 + threadIdx.x;
    if (idx >= Nn*140) return;
    int i = idx / 140, c = idx % 140;
    float v;
    if (c < 128)      v = g_feat[(size_t)i*128 + c];
    else if (c < 131) v = g_pos[i*3 + (c - 128)];
    else              v = g_sh[i*9 + (c - 131)];
    atomicAdd(&g_pool[batch[i]*140 + c], v);
}
__global__ void pred_kernel(const float* __restrict__ Wpred, const float* __restrict__ bpred,
                            float* __restrict__ out) {
    int g = blockIdx.x, lane = threadIdx.x;
    float s = 0.f;
    for (int c = lane; c < 140; c += 32)
        s = fmaf(g_pool[g*140 + c], Wpred[c], s);
    #pragma unroll
    for (int off = 16; off > 0; off >>= 1)
        s += __shfl_xor_sync(0xffffffffu, s, off);
    if (lane == 0) out[g] = s + bpred[0];
}

extern "C" void kernel_launch(void* const* d_in, const int* in_sizes, int n_in,
                              void* d_out, int out_size) {
    const int*   atoms = (const int*)d_in[0];
    const int*   ei    = (const int*)d_in[1];
    const int*   batch = (const int*)d_in[2];
    const float* pos   = (const float*)d_in[3];
    const float* emb   = (const float*)d_in[4];
    const float* Wsi1  = (const float*)d_in[5];  const float* bsi1  = (const float*)d_in[6];
    const float* Wsi2  = (const float*)d_in[7];  const float* bsi2  = (const float*)d_in[8];
    const float* WsiC1 = (const float*)d_in[9];  const float* bsiC1 = (const float*)d_in[10];
    const float* WsiC2 = (const float*)d_in[11]; const float* bsiC2 = (const float*)d_in[12];
    const float* Wm1   = (const float*)d_in[13]; const float* bm1   = (const float*)d_in[14];
    const float* Wm2   = (const float*)d_in[15]; const float* bm2   = (const float*)d_in[16];
    const float* Wp1   = (const float*)d_in[17]; const float* bp1   = (const float*)d_in[18];
    const float* Wp2   = (const float*)d_in[19]; const float* bp2   = (const float*)d_in[20];
    const float* Wn1   = (const float*)d_in[21]; const float* bn1   = (const float*)d_in[22];
    const float* Wn2   = (const float*)d_in[23]; const float* bn2   = (const float*)d_in[24];
    const float* Ws1   = (const float*)d_in[25]; const float* bs1   = (const float*)d_in[26];
    const float* Ws2   = (const float*)d_in[27]; const float* bs2   = (const float*)d_in[28];
    const float* Wpred = (const float*)d_in[29]; const float* bpred = (const float*)d_in[30];
    float* out = (float*)d_out;

    cudaFuncSetAttribute(featab_kernel, cudaFuncAttributeMaxDynamicSharedMemorySize, FAB_SMEM);
    cudaFuncSetAttribute(nodeup_kernel, cudaFuncAttributeMaxDynamicSharedMemorySize, NU_SMEM);
    cudaFuncSetAttribute(edge_hm_mma, cudaFuncAttributeMaxDynamicSharedMemorySize, E1_SMEM);
    cudaFuncSetAttribute(edge_ps_mma, cudaFuncAttributeMaxDynamicSharedMemorySize, E2_SMEM);

    void *p_msum, *p_psum, *p_ssum, *p_deg, *p_com, *p_cnt, *p_pool, *p_pos, *p_cur;
    cudaGetSymbolAddress(&p_msum, g_msum);
    cudaGetSymbolAddress(&p_psum, g_psum);
    cudaGetSymbolAddress(&p_ssum, g_ssum);
    cudaGetSymbolAddress(&p_deg,  g_deg);
    cudaGetSymbolAddress(&p_com,  g_com);
    cudaGetSymbolAddress(&p_cnt,  g_cnt);
    cudaGetSymbolAddress(&p_pool, g_pool);
    cudaGetSymbolAddress(&p_pos,  g_pos);
    cudaGetSymbolAddress(&p_cur,  g_cursor);

    cudaMemsetAsync(p_deg,  0, Nn*4, 0);
    cudaMemsetAsync(p_com,  0, Gg*3*4, 0);
    cudaMemsetAsync(p_cnt,  0, Gg*4, 0);
    cudaMemsetAsync(p_ssum, 0, Nn*9*4, 0);
    cudaMemsetAsync(p_pool, 0, Gg*140*4, 0);
    cudaMemsetAsync(p_cur,  0, Nn*4, 0);
    cudaMemcpyAsync(p_pos, pos, Nn*3*4, cudaMemcpyDeviceToDevice, 0);

    wprep_kernel<<<15, 256>>>(Wm2, Wp1, Ws1);
    node_init_kernel<<<(Nn*128)/256, 256>>>(atoms, emb);
    com_kernel<<<(Nn + 255)/256, 256>>>(batch);
    deg_kernel<<<(Ee + 255)/256, 256>>>(ei);
    scan_kernel<<<1, 256>>>();
    sortscatter_kernel<<<(Ee + 255)/256, 256>>>(ei);
    vocab_kernel<<<10, 128>>>(emb, Wsi1, WsiC1, bsiC1, WsiC2, bsiC2);
    edge_init_kernel<<<Ee/8, 256>>>(atoms, Wsi1, bsi1, Wsi2, bsi2);
    sh_init_kernel<<<(Nn + 255)/256, 256>>>(atoms, batch);

    int gridN = (Nn + 63)/64;

    for (int l = 0; l < Ll; l++) {
        cudaMemsetAsync(p_msum, 0, (size_t)Nn*128*4, 0);
        cudaMemsetAsync(p_psum, 0, Nn*3*4, 0);
        cudaMemsetAsync(p_ssum, 0, Nn*9*4, 0);

        featab_kernel<<<gridN, 256, FAB_SMEM>>>(
            Wm1 + (size_t)l*260*128, Wm1 + ((size_t)l*260 + 128)*128);

        edge_hm_mma<<<148, 512, E1_SMEM>>>(
            bm2 + l*128, Wm1 + ((size_t)l*260 + 256)*128, bm1 + l*128, l);

        edge_ps_mma<<<148, 512, E2_SMEM>>>(
            bp1 + l*128, Wp2 + l*128, bp2 + l,
            bs1 + l*128, Ws2 + l*384, bs2 + l*3, l);

        posh_kernel<<<(Nn + 255)/256, 256>>>();

        nodeup_kernel<<<gridN, 256, NU_SMEM>>>(
            Wn1 + (size_t)l*256*128, Wn1 + ((size_t)l*256 + 128)*128,
            Wn2 + (size_t)l*128*128, bn1 + l*128, bn2 + l*128);
    }

    pool_kernel<<<(Nn*140 + 255)/256, 256>>>(batch);
    pred_kernel<<<Gg, 32>>>(Wpred, bpred, out);
}

// round 11
// speedup vs baseline: 1.6828x; 1.1744x over previous
#include <cuda_runtime.h>
#include <cuda_bf16.h>
#include <cstdint>
#include <math.h>

#define Nn 10000
#define Ee 160000
#define Gg 100
#define Ll 5
#define NT 1250   // 128-edge tiles

typedef unsigned long long u64;
typedef unsigned short ush;

__device__ float g_feat [Nn*128];
__device__ float g_featA[Nn*128];
__device__ float g_featB[Nn*128];
__device__ float g_sh   [Nn*9];
__device__ float g_pos  [Nn*3];
__device__ float g_msum [Nn*128];
__device__ float g_psum [Nn*3];
__device__ float g_ssum [Nn*9];
__device__ float g_deg  [Nn];
__device__ float g_com  [Gg*3];
__device__ float g_cnt  [Gg];
__device__ float g_P1   [10*128];
__device__ float g_P2   [10*128];
__device__ float g_cmsg [10];
__device__ float g_pool [Gg*140];
__device__ int   g_off  [Nn];
__device__ int   g_cursor[Nn];
__device__ int   g_er   [Ee];
__device__ int   g_ec   [Ee];
__device__ ush   g_mh  [(size_t)NT*16384];  // m hi-bf16, [tile][128][128]
__device__ ush   g_ml  [(size_t)NT*16384];  // m lo-bf16
__device__ ush   g_Wbh [40*17408];          // [l*8+slot][n*136+k] hi
__device__ ush   g_Wbl [40*17408];          // lo

__device__ __forceinline__ float silu_f(float x) { return x / (1.0f + __expf(-x)); }

__device__ __forceinline__ void sph2(float vx, float vy, float vz, float* o) {
    const float S3 = 1.7320508075688772f, HS3 = 0.8660254037844386f;
    float r = sqrtf(vx*vx + vy*vy + vz*vz);
    float inv = 1.0f / fmaxf(r, 1e-12f);
    float x = vx*inv, y = vy*inv, z = vz*inv;
    o[0] = S3*x*z; o[1] = S3*x*y; o[2] = y*y - 0.5f*(x*x + z*z);
    o[3] = S3*y*z; o[4] = HS3*(z*z - x*x);
}

// ---- HMMA helpers ----
__device__ __forceinline__ unsigned smem_u32(const void* p) {
    unsigned a; asm("{ .reg .u64 t; cvta.to.shared.u64 t, %1; cvt.u32.u64 %0, t; }" : "=r"(a) : "l"(p));
    return a;
}
__device__ __forceinline__ void ldsm4(unsigned addr, unsigned* r) {
    asm volatile("ldmatrix.sync.aligned.m8n8.x4.shared.b16 {%0,%1,%2,%3}, [%4];"
        : "=r"(r[0]), "=r"(r[1]), "=r"(r[2]), "=r"(r[3]) : "r"(addr));
}
__device__ __forceinline__ void mma_bf16(float* d, const unsigned* a, unsigned b0, unsigned b1) {
    asm volatile("mma.sync.aligned.m16n8k16.row.col.f32.bf16.bf16.f32 "
        "{%0,%1,%2,%3},{%4,%5,%6,%7},{%8,%9},{%0,%1,%2,%3};"
        : "+f"(d[0]), "+f"(d[1]), "+f"(d[2]), "+f"(d[3])
        : "r"(a[0]), "r"(a[1]), "r"(a[2]), "r"(a[3]), "r"(b0), "r"(b1));
}
__device__ __forceinline__ void split_bf16(float v, unsigned& h, unsigned& l) {
    __nv_bfloat16 hb = __float2bfloat16(v);
    h = (unsigned)__bfloat16_as_ushort(hb);
    l = (unsigned)__bfloat16_as_ushort(__float2bfloat16(v - __bfloat162float(hb)));
}

// split-bf16 GEMM core: rows m0..+15 x cols n0..+63, K=128; A/B ush stride 136 (272 B)
// ACCUMULATES into acc (caller zeroes).
__device__ __forceinline__ void hmma_gemm(unsigned aH, unsigned aL, unsigned bH, unsigned bL,
                                          int m0, int n0, int lane, float acc[8][4]) {
    unsigned aoff = (unsigned)((m0 + (lane & 15))*272 + (lane >> 4)*16);
    unsigned boff = (unsigned)((n0 + (lane & 15))*272 + (lane >> 4)*16);
    #pragma unroll
    for (int kk = 0; kk < 8; kk++) {
        unsigned kb = kk*32;
        unsigned Ah[4], Al[4];
        ldsm4(aH + aoff + kb, Ah);
        ldsm4(aL + aoff + kb, Al);
        #pragma unroll
        for (int t = 0; t < 4; t++) {
            unsigned bo = boff + t*16*272 + kb;
            unsigned Bh[4], Bl[4];
            ldsm4(bH + bo, Bh);
            ldsm4(bL + bo, Bl);
            mma_bf16(acc[2*t],   Ah, Bh[0], Bh[2]);
            mma_bf16(acc[2*t],   Ah, Bl[0], Bl[2]);
            mma_bf16(acc[2*t],   Al, Bh[0], Bh[2]);
            mma_bf16(acc[2*t+1], Ah, Bh[1], Bh[3]);
            mma_bf16(acc[2*t+1], Ah, Bl[1], Bl[3]);
            mma_bf16(acc[2*t+1], Al, Bh[1], Bh[3]);
        }
    }
}

// weights -> split-bf16 [n][k] stride-136 tiles
// slot: 0 Wm2, 1 Wp1, 2 Ws1, 3 Wa(Wm1 lo), 4 Wb(Wm1 hi), 5 W5(Wn1 lo), 6 W6(Wn1 hi), 7 W7(Wn2)
__global__ void wprep_kernel(const float* __restrict__ Wm2, const float* __restrict__ Wp1,
                             const float* __restrict__ Ws1, const float* __restrict__ Wm1,
                             const float* __restrict__ Wn1, const float* __restrict__ Wn2) {
    int bid = blockIdx.x, l = bid >> 3, slot = bid & 7;
    const float* src;
    switch (slot) {
        case 0: src = Wm2 + (size_t)l*16384;              break;
        case 1: src = Wp1 + (size_t)l*16384;              break;
        case 2: src = Ws1 + (size_t)l*16384;              break;
        case 3: src = Wm1 + (size_t)l*260*128;            break;
        case 4: src = Wm1 + ((size_t)l*260 + 128)*128;    break;
        case 5: src = Wn1 + (size_t)l*256*128;            break;
        case 6: src = Wn1 + ((size_t)l*256 + 128)*128;    break;
        default:src = Wn2 + (size_t)l*16384;              break;
    }
    ush* dh = g_Wbh + (size_t)bid*17408;
    ush* dl = g_Wbl + (size_t)bid*17408;
    for (int o = threadIdx.x; o < 16384; o += 256) {
        int k = o >> 7, n = o & 127;
        unsigned h, lo;
        split_bf16(src[k*128 + n], h, lo);
        dh[n*136 + k] = (ush)h;
        dl[n*136 + k] = (ush)lo;
    }
}

// ---- init kernels (proven) ----
__global__ void node_init_kernel(const int* __restrict__ atoms, const float* __restrict__ emb) {
    int idx = blockIdx.x*256 + threadIdx.x;
    g_feat[idx] = emb[atoms[idx >> 7]*128 + (idx & 127)];
}
__global__ void com_kernel(const int* __restrict__ batch) {
    int i = blockIdx.x*256 + threadIdx.x;
    if (i >= Nn) return;
    int b = batch[i];
    atomicAdd(&g_com[b*3+0], g_pos[i*3+0]);
    atomicAdd(&g_com[b*3+1], g_pos[i*3+1]);
    atomicAdd(&g_com[b*3+2], g_pos[i*3+2]);
    atomicAdd(&g_cnt[b], 1.0f);
}
__global__ void deg_kernel(const int* __restrict__ ei) {
    int e = blockIdx.x*256 + threadIdx.x;
    if (e < Ee) atomicAdd(&g_deg[ei[e]], 1.0f);
}
__global__ void scan_kernel() {
    __shared__ int part[256];
    int tid = threadIdx.x;
    int lo = tid*40, hi = (lo + 40 < Nn) ? lo + 40 : Nn;
    int s = 0;
    for (int i = lo; i < hi; i++) s += (int)g_deg[i];
    part[tid] = s;
    __syncthreads();
    for (int off = 1; off < 256; off <<= 1) {
        int v = part[tid] + ((tid >= off) ? part[tid - off] : 0);
        __syncthreads(); part[tid] = v; __syncthreads();
    }
    int base = (tid > 0) ? part[tid - 1] : 0;
    for (int i = lo; i < hi; i++) { g_off[i] = base; base += (int)g_deg[i]; }
}
__global__ void sortscatter_kernel(const int* __restrict__ ei) {
    int e = blockIdx.x*256 + threadIdx.x;
    if (e >= Ee) return;
    int r = ei[e], c = ei[Ee + e];
    int p = g_off[r] + atomicAdd(&g_cursor[r], 1);
    g_er[p] = r; g_ec[p] = c;
}
__global__ void vocab_kernel(const float* __restrict__ emb, const float* __restrict__ Wsi1,
                             const float* __restrict__ WsiC1, const float* __restrict__ bsiC1,
                             const float* __restrict__ WsiC2, const float* __restrict__ bsiC2) {
    __shared__ float es[128], redv[128];
    int v = blockIdx.x, j = threadIdx.x;
    es[j] = emb[v*128 + j];
    __syncthreads();
    float p1 = 0.f, p2 = 0.f, hc = 0.f;
    for (int k = 0; k < 128; k++) {
        float e = es[k];
        p1 = fmaf(e, Wsi1[(1 + k)*128 + j], p1);
        p2 = fmaf(e, Wsi1[(129 + k)*128 + j], p2);
        hc = fmaf(e, WsiC1[k*128 + j], hc);
    }
    g_P1[v*128 + j] = p1; g_P2[v*128 + j] = p2;
    redv[j] = silu_f(hc + bsiC1[j]) * WsiC2[j*3 + 2];
    __syncthreads();
    for (int s = 64; s > 0; s >>= 1) {
        if (j < s) redv[j] += redv[j + s];
        __syncthreads();
    }
    if (j == 0) g_cmsg[v] = redv[0] + bsiC2[2];
}
__global__ void edge_init_kernel(const int* __restrict__ atoms,
                                 const float* __restrict__ Wsi1, const float* __restrict__ bsi1,
                                 const float* __restrict__ Wsi2, const float* __restrict__ bsi2) {
    int e = blockIdx.x*8 + (threadIdx.x >> 5);
    int lane = threadIdx.x & 31;
    int r = g_er[e], c = g_ec[e];
    float dp0 = g_pos[r*3+0] - g_pos[c*3+0];
    float dp1 = g_pos[r*3+1] - g_pos[c*3+1];
    float dp2 = g_pos[r*3+2] - g_pos[c*3+2];
    float dist = sqrtf(dp0*dp0 + dp1*dp1 + dp2*dp2);
    int ar = atoms[r], ac = atoms[c];
    float partial = 0.f;
    #pragma unroll
    for (int q = 0; q < 4; q++) {
        int d = lane + q*32;
        partial = fmaf(silu_f(dist*Wsi1[d] + g_P1[ar*128 + d] + g_P2[ac*128 + d] + bsi1[d]),
                       Wsi2[d*3 + 2], partial);
    }
    #pragma unroll
    for (int off = 16; off > 0; off >>= 1)
        partial += __shfl_xor_sync(0xffffffffu, partial, off);
    if (lane == 0) {
        float msg2 = partial + bsi2[2];
        float y2[5];
        sph2(dp0, dp1, dp2, y2);
        #pragma unroll
        for (int q = 0; q < 5; q++)
            atomicAdd(&g_ssum[r*9 + 4 + q], y2[q]*msg2);
    }
}
__global__ void sh_init_kernel(const int* __restrict__ atoms, const int* __restrict__ batch) {
    int i = blockIdx.x*256 + threadIdx.x;
    if (i >= Nn) return;
    float dg = fmaxf(g_deg[i], 1.0f);
    int b = batch[i];
    float cn = fmaxf(g_cnt[b], 1.0f);
    float y2[5];
    sph2(g_pos[i*3+0] - g_com[b*3+0]/cn, g_pos[i*3+1] - g_com[b*3+1]/cn,
         g_pos[i*3+2] - g_com[b*3+2]/cn, y2);
    float cm = g_cmsg[atoms[i]];
    #pragma unroll
    for (int q = 0; q < 4; q++) g_sh[i*9 + q] = 0.0f;
    #pragma unroll
    for (int q = 0; q < 5; q++)
        g_sh[i*9 + 4 + q] = g_ssum[i*9 + 4 + q]/dg + cm*y2[q];
}

// ============ featAB via HMMA: featA = feat@Wa, featB = feat@Wb ============
// bytes: Xh 0 | Xl 34816 | Wah 69632 | Wal 104448 | Wbh 139264 | Wbl 174080 -> 208896
#define FABM_SMEM 208896
__global__ void __launch_bounds__(512, 1)
featab_mma(int layer) {
    extern __shared__ char smc[];
    unsigned sb = smem_u32(smc);
    int tid = threadIdx.x, w = tid >> 5, lane = tid & 31;
    int row0 = blockIdx.x * 128;

    {
        const uint4* ah = (const uint4*)(g_Wbh + (size_t)(layer*8 + 3)*17408);
        const uint4* al = (const uint4*)(g_Wbl + (size_t)(layer*8 + 3)*17408);
        const uint4* bh = (const uint4*)(g_Wbh + (size_t)(layer*8 + 4)*17408);
        const uint4* bl = (const uint4*)(g_Wbl + (size_t)(layer*8 + 4)*17408);
        uint4* dah = (uint4*)(smc + 69632);
        uint4* dal = (uint4*)(smc + 104448);
        uint4* dbh = (uint4*)(smc + 139264);
        uint4* dbl = (uint4*)(smc + 174080);
        for (int i = tid; i < 2176; i += 512) {
            dah[i] = ah[i]; dal[i] = al[i]; dbh[i] = bh[i]; dbl[i] = bl[i];
        }
    }
    #pragma unroll
    for (int q = 0; q < 8; q++) {
        int idx = tid + q*512;
        int r = idx >> 5, c4 = (idx & 31)*4;
        float4 v = make_float4(0.f,0.f,0.f,0.f);
        if (row0 + r < Nn) v = *(const float4*)(g_feat + (size_t)(row0 + r)*128 + c4);
        unsigned h[4], l[4];
        split_bf16(v.x, h[0], l[0]); split_bf16(v.y, h[1], l[1]);
        split_bf16(v.z, h[2], l[2]); split_bf16(v.w, h[3], l[3]);
        unsigned off = (unsigned)(r*136 + c4)*2u;
        *(uint2*)(smc + off)         = make_uint2(h[0]|(h[1]<<16), h[2]|(h[3]<<16));
        *(uint2*)(smc + 34816 + off) = make_uint2(l[0]|(l[1]<<16), l[2]|(l[3]<<16));
    }
    __syncthreads();

    int m0 = (w & 7)*16, n0 = (w >> 3)*64;
    int rl = m0 + (lane >> 2);
    float acc[8][4];
    #pragma unroll
    for (int i = 0; i < 8; i++)
        #pragma unroll
        for (int j = 0; j < 4; j++) acc[i][j] = 0.f;
    hmma_gemm(sb, sb + 34816, sb + 69632, sb + 104448, m0, n0, lane, acc);
    #pragma unroll
    for (int s = 0; s < 8; s++) {
        int col = n0 + s*8 + (lane & 3)*2;
        int ra = row0 + rl, rb = ra + 8;
        if (ra < Nn) *(float2*)(g_featA + (size_t)ra*128 + col) = make_float2(acc[s][0], acc[s][1]);
        if (rb < Nn) *(float2*)(g_featA + (size_t)rb*128 + col) = make_float2(acc[s][2], acc[s][3]);
    }
    #pragma unroll
    for (int i = 0; i < 8; i++)
        #pragma unroll
        for (int j = 0; j < 4; j++) acc[i][j] = 0.f;
    hmma_gemm(sb, sb + 34816, sb + 139264, sb + 174080, m0, n0, lane, acc);
    #pragma unroll
    for (int s = 0; s < 8; s++) {
        int col = n0 + s*8 + (lane & 3)*2;
        int ra = row0 + rl, rb = ra + 8;
        if (ra < Nn) *(float2*)(g_featB + (size_t)ra*128 + col) = make_float2(acc[s][0], acc[s][1]);
        if (rb < Nn) *(float2*)(g_featB + (size_t)rb*128 + col) = make_float2(acc[s][2], acc[s][3]);
    }
}

// ============ node update via HMMA ============
// feat = silu(feat@W5 + (msum/deg)@W6 + b1) @ W7 + b2
// bytes: Xh 0 | Xl 34816 | W1h 69632 | W1l 104448 | W2h 139264 | W2l 174080 | bb 208896 -> 209920
#define NUM_SMEM 209920
__global__ void __launch_bounds__(512, 1)
nodeup_mma(const float* __restrict__ b1, const float* __restrict__ b2, int layer) {
    extern __shared__ char smc[];
    unsigned sb = smem_u32(smc);
    float* bb = (float*)(smc + 208896);
    int tid = threadIdx.x, w = tid >> 5, lane = tid & 31;
    int row0 = blockIdx.x * 128;

    {
        const uint4* ah = (const uint4*)(g_Wbh + (size_t)(layer*8 + 5)*17408);
        const uint4* al = (const uint4*)(g_Wbl + (size_t)(layer*8 + 5)*17408);
        const uint4* bh = (const uint4*)(g_Wbh + (size_t)(layer*8 + 6)*17408);
        const uint4* bl = (const uint4*)(g_Wbl + (size_t)(layer*8 + 6)*17408);
        uint4* d1h = (uint4*)(smc + 69632);
        uint4* d1l = (uint4*)(smc + 104448);
        uint4* d2h = (uint4*)(smc + 139264);
        uint4* d2l = (uint4*)(smc + 174080);
        for (int i = tid; i < 2176; i += 512) {
            d1h[i] = ah[i]; d1l[i] = al[i]; d2h[i] = bh[i]; d2l[i] = bl[i];
        }
    }
    if (tid < 128) { bb[tid] = b1[tid]; bb[128 + tid] = b2[tid]; }
    // X = split(feat)
    #pragma unroll
    for (int q = 0; q < 8; q++) {
        int idx = tid + q*512;
        int r = idx >> 5, c4 = (idx & 31)*4;
        float4 v = make_float4(0.f,0.f,0.f,0.f);
        if (row0 + r < Nn) v = *(const float4*)(g_feat + (size_t)(row0 + r)*128 + c4);
        unsigned h[4], l[4];
        split_bf16(v.x, h[0], l[0]); split_bf16(v.y, h[1], l[1]);
        split_bf16(v.z, h[2], l[2]); split_bf16(v.w, h[3], l[3]);
        unsigned off = (unsigned)(r*136 + c4)*2u;
        *(uint2*)(smc + off)         = make_uint2(h[0]|(h[1]<<16), h[2]|(h[3]<<16));
        *(uint2*)(smc + 34816 + off) = make_uint2(l[0]|(l[1]<<16), l[2]|(l[3]<<16));
    }
    __syncthreads();

    int m0 = (w & 7)*16, n0 = (w >> 3)*64;
    int rl = m0 + (lane >> 2);
    float acc[8][4];
    #pragma unroll
    for (int i = 0; i < 8; i++)
        #pragma unroll
        for (int j = 0; j < 4; j++) acc[i][j] = 0.f;
    hmma_gemm(sb, sb + 34816, sb + 69632, sb + 104448, m0, n0, lane, acc);
    __syncthreads();   // done reading X + W1

    // X = split(msum/deg); W1 <- W7
    {
        const uint4* ah = (const uint4*)(g_Wbh + (size_t)(layer*8 + 7)*17408);
        const uint4* al = (const uint4*)(g_Wbl + (size_t)(layer*8 + 7)*17408);
        uint4* d1h = (uint4*)(smc + 69632);
        uint4* d1l = (uint4*)(smc + 104448);
        for (int i = tid; i < 2176; i += 512) { d1h[i] = ah[i]; d1l[i] = al[i]; }
    }
    #pragma unroll
    for (int q = 0; q < 8; q++) {
        int idx = tid + q*512;
        int r = idx >> 5, c4 = (idx & 31)*4;
        float4 v = make_float4(0.f,0.f,0.f,0.f);
        if (row0 + r < Nn) {
            v = *(const float4*)(g_msum + (size_t)(row0 + r)*128 + c4);
            float inv = 1.0f / fmaxf(g_deg[row0 + r], 1.0f);
            v.x *= inv; v.y *= inv; v.z *= inv; v.w *= inv;
        }
        unsigned h[4], l[4];
        split_bf16(v.x, h[0], l[0]); split_bf16(v.y, h[1], l[1]);
        split_bf16(v.z, h[2], l[2]); split_bf16(v.w, h[3], l[3]);
        unsigned off = (unsigned)(r*136 + c4)*2u;
        *(uint2*)(smc + off)         = make_uint2(h[0]|(h[1]<<16), h[2]|(h[3]<<16));
        *(uint2*)(smc + 34816 + off) = make_uint2(l[0]|(l[1]<<16), l[2]|(l[3]<<16));
    }
    __syncthreads();
    hmma_gemm(sb, sb + 34816, sb + 139264, sb + 174080, m0, n0, lane, acc);
    __syncthreads();   // done reading X

    // X = split(H)
    #pragma unroll
    for (int s = 0; s < 8; s++) {
        int col = n0 + s*8 + (lane & 3)*2;
        float v00 = silu_f(acc[s][0] + bb[col]);
        float v01 = silu_f(acc[s][1] + bb[col+1]);
        float v10 = silu_f(acc[s][2] + bb[col]);
        float v11 = silu_f(acc[s][3] + bb[col+1]);
        unsigned h0, l0, h1, l1;
        split_bf16(v00, h0, l0); split_bf16(v01, h1, l1);
        *(unsigned*)(smc + (rl*136 + col)*2)         = h0 | (h1 << 16);
        *(unsigned*)(smc + 34816 + (rl*136 + col)*2) = l0 | (l1 << 16);
        split_bf16(v10, h0, l0); split_bf16(v11, h1, l1);
        *(unsigned*)(smc + ((rl+8)*136 + col)*2)         = h0 | (h1 << 16);
        *(unsigned*)(smc + 34816 + ((rl+8)*136 + col)*2) = l0 | (l1 << 16);
    }
    __syncthreads();
    #pragma unroll
    for (int i = 0; i < 8; i++)
        #pragma unroll
        for (int j = 0; j < 4; j++) acc[i][j] = 0.f;
    hmma_gemm(sb, sb + 34816, sb + 69632, sb + 104448, m0, n0, lane, acc);
    #pragma unroll
    for (int s = 0; s < 8; s++) {
        int col = n0 + s*8 + (lane & 3)*2;
        int ra = row0 + rl, rb = ra + 8;
        if (ra < Nn) *(float2*)(g_feat + (size_t)ra*128 + col) =
            make_float2(acc[s][0] + bb[128+col], acc[s][1] + bb[128+col+1]);
        if (rb < Nn) *(float2*)(g_feat + (size_t)rb*128 + col) =
            make_float2(acc[s][2] + bb[128+col], acc[s][3] + bb[128+col+1]);
    }
}

// ============ E1: HMMA h-build + m-GEMM, 512 threads, 128-edge tiles ============
#define E1_SMEM 215552
__global__ void __launch_bounds__(512, 1)
edge_hm_mma(const float* __restrict__ bm2l, const float* __restrict__ Wm1tail,
            const float* __restrict__ bm1l, int layer) {
    extern __shared__ char smc[];
    unsigned sb = smem_u32(smc);
    float* m_s  = (float*)(smc + 139264);    // [128][137]
    float* scal = (float*)(smc + 209408);
    float* bh   = (float*)(smc + 211456);
    float* wtl  = (float*)(smc + 211968);
    int* ridx   = (int*)(smc + 214528);
    int* cidx   = (int*)(smc + 215040);
    int tid = threadIdx.x, w = tid >> 5, lane = tid & 31;

    {
        const uint4* sh = (const uint4*)(g_Wbh + (size_t)(layer*8)*17408);
        const uint4* sl = (const uint4*)(g_Wbl + (size_t)(layer*8)*17408);
        uint4* dh = (uint4*)(smc + 69632);
        uint4* dl = (uint4*)(smc + 104448);
        for (int i = tid; i < 2176; i += 512) { dh[i] = sh[i]; dl[i] = sl[i]; }
    }
    if (tid < 128) bh[tid] = bm2l[tid];
    for (int i = tid; i < 640; i += 512)
        wtl[i] = (i < 512) ? Wm1tail[i] : bm1l[i - 512];

    int m0 = (w & 7)*16, n0 = (w >> 3)*64;

    for (int t = blockIdx.x; t < NT; t += gridDim.x) {
        int e0 = t*128;
        __syncthreads();
        if (tid < 128) {
            int r = g_er[e0 + tid], c = g_ec[e0 + tid];
            ridx[tid] = r; cidx[tid] = c;
            float dp0 = g_pos[r*3+0] - g_pos[c*3+0];
            float dp1 = g_pos[r*3+1] - g_pos[c*3+1];
            float dp2 = g_pos[r*3+2] - g_pos[c*3+2];
            float ip2 = 0.f;
            #pragma unroll
            for (int q = 4; q < 9; q++) ip2 += g_sh[r*9+q]*g_sh[c*9+q];
            scal[tid*4+0] = dp0*dp0 + dp1*dp1 + dp2*dp2;
            scal[tid*4+1] = g_sh[r*9+0]*g_sh[c*9+0];
            scal[tid*4+2] = g_sh[r*9+1]*g_sh[c*9+1] + g_sh[r*9+2]*g_sh[c*9+2] + g_sh[r*9+3]*g_sh[c*9+3];
            scal[tid*4+3] = ip2;
        }
        __syncthreads();
        #pragma unroll
        for (int q = 0; q < 8; q++) {
            int idx = tid + q*512;
            int e = idx >> 5, c4 = (idx & 31)*4;
            int r = ridx[e], c = cidx[e];
            float4 fa = *(const float4*)(g_featA + (size_t)r*128 + c4);
            float4 fb = *(const float4*)(g_featB + (size_t)c*128 + c4);
            float d2 = scal[e*4+0], i0 = scal[e*4+1], i1 = scal[e*4+2], i2 = scal[e*4+3];
            float hv[4];
            hv[0] = silu_f(fa.x + fb.x + d2*wtl[c4+0] + i0*wtl[128+c4+0] + i1*wtl[256+c4+0] + i2*wtl[384+c4+0] + wtl[512+c4+0]);
            hv[1] = silu_f(fa.y + fb.y + d2*wtl[c4+1] + i0*wtl[128+c4+1] + i1*wtl[256+c4+1] + i2*wtl[384+c4+1] + wtl[512+c4+1]);
            hv[2] = silu_f(fa.z + fb.z + d2*wtl[c4+2] + i0*wtl[128+c4+2] + i1*wtl[256+c4+2] + i2*wtl[384+c4+2] + wtl[512+c4+2]);
            hv[3] = silu_f(fa.w + fb.w + d2*wtl[c4+3] + i0*wtl[128+c4+3] + i1*wtl[256+c4+3] + i2*wtl[384+c4+3] + wtl[512+c4+3]);
            unsigned h[4], l[4];
            #pragma unroll
            for (int j = 0; j < 4; j++) split_bf16(hv[j], h[j], l[j]);
            unsigned off = (unsigned)(e*136 + c4)*2u;
            *(uint2*)(smc + off)         = make_uint2(h[0]|(h[1]<<16), h[2]|(h[3]<<16));
            *(uint2*)(smc + 34816 + off) = make_uint2(l[0]|(l[1]<<16), l[2]|(l[3]<<16));
        }
        __syncthreads();
        float acc[8][4];
        #pragma unroll
        for (int i = 0; i < 8; i++)
            #pragma unroll
            for (int j = 0; j < 4; j++) acc[i][j] = 0.f;
        hmma_gemm(sb, sb + 34816, sb + 69632, sb + 104448, m0, n0, lane, acc);
        // epilogue: m -> m_s fp32 AND direct split-bf16 gmem writes from regs
        {
            int r0 = m0 + (lane >> 2), r1 = r0 + 8;
            unsigned* gh = (unsigned*)(g_mh + (size_t)t*16384);
            unsigned* gl = (unsigned*)(g_ml + (size_t)t*16384);
            #pragma unroll
            for (int s = 0; s < 8; s++) {
                int col = n0 + s*8 + (lane & 3)*2;
                float v00 = silu_f(acc[s][0] + bh[col]);
                float v01 = silu_f(acc[s][1] + bh[col+1]);
                float v10 = silu_f(acc[s][2] + bh[col]);
                float v11 = silu_f(acc[s][3] + bh[col+1]);
                m_s[r0*137 + col]     = v00;
                m_s[r0*137 + col + 1] = v01;
                m_s[r1*137 + col]     = v10;
                m_s[r1*137 + col + 1] = v11;
                unsigned h0, l0, h1, l1;
                split_bf16(v00, h0, l0); split_bf16(v01, h1, l1);
                gh[r0*64 + (col >> 1)] = h0 | (h1 << 16);
                gl[r0*64 + (col >> 1)] = l0 | (l1 << 16);
                split_bf16(v10, h0, l0); split_bf16(v11, h1, l1);
                gh[r1*64 + (col >> 1)] = h0 | (h1 << 16);
                gl[r1*64 + (col >> 1)] = l0 | (l1 << 16);
            }
        }
        __syncthreads();
        // msum sorted-run RED
        {
            int c = tid & 127, seg = tid >> 7;
            int eb = seg*32;
            float agg = 0.f;
            int ar = ridx[eb];
            for (int e = eb; e < eb + 32; e++) {
                float v = m_s[e*137 + c];
                int r = ridx[e];
                if (r != ar) { atomicAdd(&g_msum[(size_t)ar*128 + c], agg); agg = v; ar = r; }
                else agg += v;
            }
            atomicAdd(&g_msum[(size_t)ar*128 + c], agg);
        }
    }
}

// ============ E2: HMMA p+s GEMMs, 512 threads, 128-edge tiles ============
#define E2_SMEM 216064
__global__ void __launch_bounds__(512, 1)
edge_ps_mma(const float* __restrict__ bp1l, const float* __restrict__ Wp2l,
            const float* __restrict__ bp2l,
            const float* __restrict__ bs1l, const float* __restrict__ Ws2l,
            const float* __restrict__ bs2l, int layer) {
    extern __shared__ char smc[];
    unsigned sb = smem_u32(smc);
    float* bhp = (float*)(smc + 208896);
    float* bhs = (float*)(smc + 209408);
    float* w2p = (float*)(smc + 209920);
    float* w2s = (float*)(smc + 210432);
    float* pd  = (float*)(smc + 211968);     // [2][128][4]
    int tid = threadIdx.x, w = tid >> 5, lane = tid & 31;

    {
        const uint4* ph = (const uint4*)(g_Wbh + (size_t)(layer*8 + 1)*17408);
        const uint4* pl = (const uint4*)(g_Wbl + (size_t)(layer*8 + 1)*17408);
        const uint4* sh = (const uint4*)(g_Wbh + (size_t)(layer*8 + 2)*17408);
        const uint4* sl = (const uint4*)(g_Wbl + (size_t)(layer*8 + 2)*17408);
        uint4* dph = (uint4*)(smc + 69632);
        uint4* dpl = (uint4*)(smc + 104448);
        uint4* dsh = (uint4*)(smc + 139264);
        uint4* dsl = (uint4*)(smc + 174080);
        for (int i = tid; i < 2176; i += 512) {
            dph[i] = ph[i]; dpl[i] = pl[i]; dsh[i] = sh[i]; dsl[i] = sl[i];
        }
    }
    if (tid < 128) {
        bhp[tid] = bp1l[tid]; bhs[tid] = bs1l[tid]; w2p[tid] = Wp2l[tid];
        w2s[tid*3+0] = Ws2l[tid*3+0]; w2s[tid*3+1] = Ws2l[tid*3+1]; w2s[tid*3+2] = Ws2l[tid*3+2];
    }

    int m0 = (w & 7)*16, n0 = (w >> 3)*64;
    int chalf = w >> 3;

    for (int t = blockIdx.x; t < NT; t += gridDim.x) {
        __syncthreads();
        {
            const char* srh = (const char*)(g_mh + (size_t)t*16384);
            const char* srl = (const char*)(g_ml + (size_t)t*16384);
            #pragma unroll
            for (int q = 0; q < 4; q++) {
                int ch = tid + q*512;
                int e = ch >> 4, c16 = ch & 15;
                unsigned dof = (unsigned)(e*272 + c16*16);
                asm volatile("cp.async.cg.shared.global [%0], [%1], 16;"
                             :: "r"(sb + dof), "l"(srh + (size_t)ch*16) : "memory");
                asm volatile("cp.async.cg.shared.global [%0], [%1], 16;"
                             :: "r"(sb + 34816u + dof), "l"(srl + (size_t)ch*16) : "memory");
            }
            asm volatile("cp.async.commit_group;" ::: "memory");
            asm volatile("cp.async.wait_group 0;" ::: "memory");
        }
        __syncthreads();
        float accp[8][4], accs[8][4];
        #pragma unroll
        for (int i = 0; i < 8; i++)
            #pragma unroll
            for (int j = 0; j < 4; j++) { accp[i][j] = 0.f; accs[i][j] = 0.f; }
        {
            unsigned aoff = (unsigned)((m0 + (lane & 15))*272 + (lane >> 4)*16);
            unsigned boff = (unsigned)((n0 + (lane & 15))*272 + (lane >> 4)*16);
            #pragma unroll
            for (int kk = 0; kk < 8; kk++) {
                unsigned kb = kk*32;
                unsigned Ah[4], Al[4];
                ldsm4(sb + aoff + kb, Ah);
                ldsm4(sb + 34816u + aoff + kb, Al);
                #pragma unroll
                for (int tt = 0; tt < 4; tt++) {
                    unsigned bo = boff + tt*16*272 + kb;
                    unsigned Bh[4], Bl[4];
                    ldsm4(sb + 69632u + bo, Bh);
                    ldsm4(sb + 104448u + bo, Bl);
                    mma_bf16(accp[2*tt],   Ah, Bh[0], Bh[2]);
                    mma_bf16(accp[2*tt],   Ah, Bl[0], Bl[2]);
                    mma_bf16(accp[2*tt],   Al, Bh[0], Bh[2]);
                    mma_bf16(accp[2*tt+1], Ah, Bh[1], Bh[3]);
                    mma_bf16(accp[2*tt+1], Ah, Bl[1], Bl[3]);
                    mma_bf16(accp[2*tt+1], Al, Bh[1], Bh[3]);
                    ldsm4(sb + 139264u + bo, Bh);
                    ldsm4(sb + 174080u + bo, Bl);
                    mma_bf16(accs[2*tt],   Ah, Bh[0], Bh[2]);
                    mma_bf16(accs[2*tt],   Ah, Bl[0], Bl[2]);
                    mma_bf16(accs[2*tt],   Al, Bh[0], Bh[2]);
                    mma_bf16(accs[2*tt+1], Ah, Bh[1], Bh[3]);
                    mma_bf16(accs[2*tt+1], Ah, Bl[1], Bl[3]);
                    mma_bf16(accs[2*tt+1], Al, Bh[1], Bh[3]);
                }
            }
        }
        {
            float pr0 = 0.f, pr1 = 0.f;
            float s0r0 = 0.f, s1r0 = 0.f, s2r0 = 0.f;
            float s0r1 = 0.f, s1r1 = 0.f, s2r1 = 0.f;
            #pragma unroll
            for (int s = 0; s < 8; s++) {
                int col = n0 + s*8 + (lane & 3)*2;
                float h00 = silu_f(accp[s][0] + bhp[col]);
                float h01 = silu_f(accp[s][1] + bhp[col+1]);
                float h10 = silu_f(accp[s][2] + bhp[col]);
                float h11 = silu_f(accp[s][3] + bhp[col+1]);
                pr0 = fmaf(h00, w2p[col], fmaf(h01, w2p[col+1], pr0));
                pr1 = fmaf(h10, w2p[col], fmaf(h11, w2p[col+1], pr1));
                float g00 = silu_f(accs[s][0] + bhs[col]);
                float g01 = silu_f(accs[s][1] + bhs[col+1]);
                float g10 = silu_f(accs[s][2] + bhs[col]);
                float g11 = silu_f(accs[s][3] + bhs[col+1]);
                s0r0 = fmaf(g00, w2s[col*3+0], fmaf(g01, w2s[(col+1)*3+0], s0r0));
                s1r0 = fmaf(g00, w2s[col*3+1], fmaf(g01, w2s[(col+1)*3+1], s1r0));
                s2r0 = fmaf(g00, w2s[col*3+2], fmaf(g01, w2s[(col+1)*3+2], s2r0));
                s0r1 = fmaf(g10, w2s[col*3+0], fmaf(g11, w2s[(col+1)*3+0], s0r1));
                s1r1 = fmaf(g10, w2s[col*3+1], fmaf(g11, w2s[(col+1)*3+1], s1r1));
                s2r1 = fmaf(g10, w2s[col*3+2], fmaf(g11, w2s[(col+1)*3+2], s2r1));
            }
            #pragma unroll
            for (int off = 1; off <= 2; off <<= 1) {
                pr0 += __shfl_xor_sync(0xffffffffu, pr0, off);
                pr1 += __shfl_xor_sync(0xffffffffu, pr1, off);
                s0r0 += __shfl_xor_sync(0xffffffffu, s0r0, off);
                s1r0 += __shfl_xor_sync(0xffffffffu, s1r0, off);
                s2r0 += __shfl_xor_sync(0xffffffffu, s2r0, off);
                s0r1 += __shfl_xor_sync(0xffffffffu, s0r1, off);
                s1r1 += __shfl_xor_sync(0xffffffffu, s1r1, off);
                s2r1 += __shfl_xor_sync(0xffffffffu, s2r1, off);
            }
            if ((lane & 3) == 0) {
                int r0 = m0 + (lane >> 2);
                float* p0 = pd + chalf*512 + r0*4;
                p0[0] = pr0; p0[1] = s0r0; p0[2] = s1r0; p0[3] = s2r0;
                float* p1 = pd + chalf*512 + (r0+8)*4;
                p1[0] = pr1; p1[1] = s0r1; p1[2] = s1r1; p1[3] = s2r1;
            }
        }
        __syncthreads();
        if (tid < 128) {
            int e = t*128 + tid;
            int r = g_er[e], c = g_ec[e];
            float psc = pd[tid*4+0] + pd[512 + tid*4+0] + bp2l[0];
            float s0  = pd[tid*4+1] + pd[512 + tid*4+1] + bs2l[0];
            float s1  = pd[tid*4+2] + pd[512 + tid*4+2] + bs2l[1];
            float s2  = pd[tid*4+3] + pd[512 + tid*4+3] + bs2l[2];
            float dp0 = g_pos[r*3+0] - g_pos[c*3+0];
            float dp1 = g_pos[r*3+1] - g_pos[c*3+1];
            float dp2 = g_pos[r*3+2] - g_pos[c*3+2];
            atomicAdd(&g_psum[r*3+0], dp0*psc);
            atomicAdd(&g_psum[r*3+1], dp1*psc);
            atomicAdd(&g_psum[r*3+2], dp2*psc);
            #pragma unroll
            for (int q = 0; q < 9; q++) {
                float diff = g_sh[r*9+q] - g_sh[c*9+q];
                atomicAdd(&g_ssum[r*9+q], diff * ((q == 0) ? s0 : (q < 4) ? s1 : s2));
            }
        }
    }
}

__global__ void posh_kernel() {
    int i = blockIdx.x*256 + threadIdx.x;
    if (i >= Nn) return;
    float inv = 1.0f / fmaxf(g_deg[i], 1.0f);
    #pragma unroll
    for (int q = 0; q < 3; q++) g_pos[i*3+q] += g_psum[i*3+q]*inv;
    #pragma unroll
    for (int q = 0; q < 9; q++) g_sh[i*9+q] += g_ssum[i*9+q]*inv;
}
__global__ void pool_kernel(const int* __restrict__ batch) {
    int idx = blockIdx.x*256 + threadIdx.x;
    if (idx >= Nn*140) return;
    int i = idx / 140, c = idx % 140;
    float v;
    if (c < 128)      v = g_feat[(size_t)i*128 + c];
    else if (c < 131) v = g_pos[i*3 + (c - 128)];
    else              v = g_sh[i*9 + (c - 131)];
    atomicAdd(&g_pool[batch[i]*140 + c], v);
}
__global__ void pred_kernel(const float* __restrict__ Wpred, const float* __restrict__ bpred,
                            float* __restrict__ out) {
    int g = blockIdx.x, lane = threadIdx.x;
    float s = 0.f;
    for (int c = lane; c < 140; c += 32)
        s = fmaf(g_pool[g*140 + c], Wpred[c], s);
    #pragma unroll
    for (int off = 16; off > 0; off >>= 1)
        s += __shfl_xor_sync(0xffffffffu, s, off);
    if (lane == 0) out[g] = s + bpred[0];
}

extern "C" void kernel_launch(void* const* d_in, const int* in_sizes, int n_in,
                              void* d_out, int out_size) {
    const int*   atoms = (const int*)d_in[0];
    const int*   ei    = (const int*)d_in[1];
    const int*   batch = (const int*)d_in[2];
    const float* pos   = (const float*)d_in[3];
    const float* emb   = (const float*)d_in[4];
    const float* Wsi1  = (const float*)d_in[5];  const float* bsi1  = (const float*)d_in[6];
    const float* Wsi2  = (const float*)d_in[7];  const float* bsi2  = (const float*)d_in[8];
    const float* WsiC1 = (const float*)d_in[9];  const float* bsiC1 = (const float*)d_in[10];
    const float* WsiC2 = (const float*)d_in[11]; const float* bsiC2 = (const float*)d_in[12];
    const float* Wm1   = (const float*)d_in[13]; const float* bm1   = (const float*)d_in[14];
    const float* Wm2   = (const float*)d_in[15]; const float* bm2   = (const float*)d_in[16];
    const float* Wp1   = (const float*)d_in[17]; const float* bp1   = (const float*)d_in[18];
    const float* Wp2   = (const float*)d_in[19]; const float* bp2   = (const float*)d_in[20];
    const float* Wn1   = (const float*)d_in[21]; const float* bn1   = (const float*)d_in[22];
    const float* Wn2   = (const float*)d_in[23]; const float* bn2   = (const float*)d_in[24];
    const float* Ws1   = (const float*)d_in[25]; const float* bs1   = (const float*)d_in[26];
    const float* Ws2   = (const float*)d_in[27]; const float* bs2   = (const float*)d_in[28];
    const float* Wpred = (const float*)d_in[29]; const float* bpred = (const float*)d_in[30];
    float* out = (float*)d_out;

    cudaFuncSetAttribute(featab_mma, cudaFuncAttributeMaxDynamicSharedMemorySize, FABM_SMEM);
    cudaFuncSetAttribute(nodeup_mma, cudaFuncAttributeMaxDynamicSharedMemorySize, NUM_SMEM);
    cudaFuncSetAttribute(edge_hm_mma, cudaFuncAttributeMaxDynamicSharedMemorySize, E1_SMEM);
    cudaFuncSetAttribute(edge_ps_mma, cudaFuncAttributeMaxDynamicSharedMemorySize, E2_SMEM);

    void *p_msum, *p_psum, *p_ssum, *p_deg, *p_com, *p_cnt, *p_pool, *p_pos, *p_cur;
    cudaGetSymbolAddress(&p_msum, g_msum);
    cudaGetSymbolAddress(&p_psum, g_psum);
    cudaGetSymbolAddress(&p_ssum, g_ssum);
    cudaGetSymbolAddress(&p_deg,  g_deg);
    cudaGetSymbolAddress(&p_com,  g_com);
    cudaGetSymbolAddress(&p_cnt,  g_cnt);
    cudaGetSymbolAddress(&p_pool, g_pool);
    cudaGetSymbolAddress(&p_pos,  g_pos);
    cudaGetSymbolAddress(&p_cur,  g_cursor);

    cudaMemsetAsync(p_deg,  0, Nn*4, 0);
    cudaMemsetAsync(p_com,  0, Gg*3*4, 0);
    cudaMemsetAsync(p_cnt,  0, Gg*4, 0);
    cudaMemsetAsync(p_ssum, 0, Nn*9*4, 0);
    cudaMemsetAsync(p_pool, 0, Gg*140*4, 0);
    cudaMemsetAsync(p_cur,  0, Nn*4, 0);
    cudaMemcpyAsync(p_pos, pos, Nn*3*4, cudaMemcpyDeviceToDevice, 0);

    wprep_kernel<<<40, 256>>>(Wm2, Wp1, Ws1, Wm1, Wn1, Wn2);
    node_init_kernel<<<(Nn*128)/256, 256>>>(atoms, emb);
    com_kernel<<<(Nn + 255)/256, 256>>>(batch);
    deg_kernel<<<(Ee + 255)/256, 256>>>(ei);
    scan_kernel<<<1, 256>>>();
    sortscatter_kernel<<<(Ee + 255)/256, 256>>>(ei);
    vocab_kernel<<<10, 128>>>(emb, Wsi1, WsiC1, bsiC1, WsiC2, bsiC2);
    edge_init_kernel<<<Ee/8, 256>>>(atoms, Wsi1, bsi1, Wsi2, bsi2);
    sh_init_kernel<<<(Nn + 255)/256, 256>>>(atoms, batch);

    int gridNM = (Nn + 127)/128;   // 79

    for (int l = 0; l < Ll; l++) {
        cudaMemsetAsync(p_msum, 0, (size_t)Nn*128*4, 0);
        cudaMemsetAsync(p_psum, 0, Nn*3*4, 0);
        cudaMemsetAsync(p_ssum, 0, Nn*9*4, 0);

        featab_mma<<<gridNM, 512, FABM_SMEM>>>(l);

        edge_hm_mma<<<148, 512, E1_SMEM>>>(
            bm2 + l*128, Wm1 + ((size_t)l*260 + 256)*128, bm1 + l*128, l);

        edge_ps_mma<<<148, 512, E2_SMEM>>>(
            bp1 + l*128, Wp2 + l*128, bp2 + l,
            bs1 + l*128, Ws2 + l*384, bs2 + l*3, l);

        posh_kernel<<<(Nn + 255)/256, 256>>>();

        nodeup_mma<<<gridNM, 512, NUM_SMEM>>>(bn1 + l*128, bn2 + l*128, l);
    }

    pool_kernel<<<(Nn*140 + 255)/256, 256>>>(batch);
    pred_kernel<<<Gg, 32>>>(Wpred, bpred, out);
}

// round 12
// speedup vs baseline: 1.8441x; 1.0958x over previous
#include <cuda_runtime.h>
#include <cuda_bf16.h>
#include <cstdint>
#include <math.h>

#define Nn 10000
#define Ee 160000
#define Gg 100
#define Ll 5
#define NT 1250   // 128-edge tiles

typedef unsigned long long u64;
typedef unsigned short ush;

__device__ float g_feat [Nn*128];
__device__ float g_featA[Nn*128];
__device__ float g_featB[Nn*128];
__device__ float g_sh   [Nn*9];
__device__ float g_pos  [Nn*3];
__device__ float g_msum [Nn*128];
__device__ float g_psum [Nn*3];
__device__ float g_ssum [Nn*9];
__device__ float g_deg  [Nn];
__device__ float g_com  [Gg*3];
__device__ float g_cnt  [Gg];
__device__ float g_P1   [10*128];
__device__ float g_P2   [10*128];
__device__ float g_cmsg [10];
__device__ float g_pool [Gg*140];
__device__ int   g_off  [Nn];
__device__ int   g_cursor[Nn];
__device__ int   g_er   [Ee];
__device__ int   g_ec   [Ee];
__device__ ush   g_Wbh [40*17408];          // [l*8+slot][n*136+k] hi
__device__ ush   g_Wbl [40*17408];          // lo

__device__ __forceinline__ float silu_f(float x) { return x / (1.0f + __expf(-x)); }

__device__ __forceinline__ void sph2(float vx, float vy, float vz, float* o) {
    const float S3 = 1.7320508075688772f, HS3 = 0.8660254037844386f;
    float r = sqrtf(vx*vx + vy*vy + vz*vz);
    float inv = 1.0f / fmaxf(r, 1e-12f);
    float x = vx*inv, y = vy*inv, z = vz*inv;
    o[0] = S3*x*z; o[1] = S3*x*y; o[2] = y*y - 0.5f*(x*x + z*z);
    o[3] = S3*y*z; o[4] = HS3*(z*z - x*x);
}

// ---- HMMA helpers ----
__device__ __forceinline__ unsigned smem_u32(const void* p) {
    unsigned a; asm("{ .reg .u64 t; cvta.to.shared.u64 t, %1; cvt.u32.u64 %0, t; }" : "=r"(a) : "l"(p));
    return a;
}
__device__ __forceinline__ void ldsm4(unsigned addr, unsigned* r) {
    asm volatile("ldmatrix.sync.aligned.m8n8.x4.shared.b16 {%0,%1,%2,%3}, [%4];"
        : "=r"(r[0]), "=r"(r[1]), "=r"(r[2]), "=r"(r[3]) : "r"(addr));
}
__device__ __forceinline__ void mma_bf16(float* d, const unsigned* a, unsigned b0, unsigned b1) {
    asm volatile("mma.sync.aligned.m16n8k16.row.col.f32.bf16.bf16.f32 "
        "{%0,%1,%2,%3},{%4,%5,%6,%7},{%8,%9},{%0,%1,%2,%3};"
        : "+f"(d[0]), "+f"(d[1]), "+f"(d[2]), "+f"(d[3])
        : "r"(a[0]), "r"(a[1]), "r"(a[2]), "r"(a[3]), "r"(b0), "r"(b1));
}
__device__ __forceinline__ void split_bf16(float v, unsigned& h, unsigned& l) {
    __nv_bfloat16 hb = __float2bfloat16(v);
    h = (unsigned)__bfloat16_as_ushort(hb);
    l = (unsigned)__bfloat16_as_ushort(__float2bfloat16(v - __bfloat162float(hb)));
}

// split-bf16 GEMM core: rows m0..+15 x cols n0..+63, K=128; A/B ush stride 136 (272 B)
__device__ __forceinline__ void hmma_gemm(unsigned aH, unsigned aL, unsigned bH, unsigned bL,
                                          int m0, int n0, int lane, float acc[8][4]) {
    unsigned aoff = (unsigned)((m0 + (lane & 15))*272 + (lane >> 4)*16);
    unsigned boff = (unsigned)((n0 + (lane & 15))*272 + (lane >> 4)*16);
    #pragma unroll
    for (int kk = 0; kk < 8; kk++) {
        unsigned kb = kk*32;
        unsigned Ah[4], Al[4];
        ldsm4(aH + aoff + kb, Ah);
        ldsm4(aL + aoff + kb, Al);
        #pragma unroll
        for (int t = 0; t < 4; t++) {
            unsigned bo = boff + t*16*272 + kb;
            unsigned Bh[4], Bl[4];
            ldsm4(bH + bo, Bh);
            ldsm4(bL + bo, Bl);
            mma_bf16(acc[2*t],   Ah, Bh[0], Bh[2]);
            mma_bf16(acc[2*t],   Ah, Bl[0], Bl[2]);
            mma_bf16(acc[2*t],   Al, Bh[0], Bh[2]);
            mma_bf16(acc[2*t+1], Ah, Bh[1], Bh[3]);
            mma_bf16(acc[2*t+1], Ah, Bl[1], Bl[3]);
            mma_bf16(acc[2*t+1], Al, Bh[1], Bh[3]);
        }
    }
}

// weights -> split-bf16 [n][k] stride-136 tiles
// slot: 0 Wm2, 1 Wp1, 2 Ws1, 3 Wa, 4 Wb, 5 W5, 6 W6, 7 W7
__global__ void wprep_kernel(const float* __restrict__ Wm2, const float* __restrict__ Wp1,
                             const float* __restrict__ Ws1, const float* __restrict__ Wm1,
                             const float* __restrict__ Wn1, const float* __restrict__ Wn2) {
    int bid = blockIdx.x, l = bid >> 3, slot = bid & 7;
    const float* src;
    switch (slot) {
        case 0: src = Wm2 + (size_t)l*16384;              break;
        case 1: src = Wp1 + (size_t)l*16384;              break;
        case 2: src = Ws1 + (size_t)l*16384;              break;
        case 3: src = Wm1 + (size_t)l*260*128;            break;
        case 4: src = Wm1 + ((size_t)l*260 + 128)*128;    break;
        case 5: src = Wn1 + (size_t)l*256*128;            break;
        case 6: src = Wn1 + ((size_t)l*256 + 128)*128;    break;
        default:src = Wn2 + (size_t)l*16384;              break;
    }
    ush* dh = g_Wbh + (size_t)bid*17408;
    ush* dl = g_Wbl + (size_t)bid*17408;
    for (int o = threadIdx.x; o < 16384; o += 256) {
        int k = o >> 7, n = o & 127;
        unsigned h, lo;
        split_bf16(src[k*128 + n], h, lo);
        dh[n*136 + k] = (ush)h;
        dl[n*136 + k] = (ush)lo;
    }
}

// ---- init kernels (proven) ----
__global__ void node_init_kernel(const int* __restrict__ atoms, const float* __restrict__ emb) {
    int idx = blockIdx.x*256 + threadIdx.x;
    g_feat[idx] = emb[atoms[idx >> 7]*128 + (idx & 127)];
}
__global__ void com_kernel(const int* __restrict__ batch) {
    int i = blockIdx.x*256 + threadIdx.x;
    if (i >= Nn) return;
    int b = batch[i];
    atomicAdd(&g_com[b*3+0], g_pos[i*3+0]);
    atomicAdd(&g_com[b*3+1], g_pos[i*3+1]);
    atomicAdd(&g_com[b*3+2], g_pos[i*3+2]);
    atomicAdd(&g_cnt[b], 1.0f);
}
__global__ void deg_kernel(const int* __restrict__ ei) {
    int e = blockIdx.x*256 + threadIdx.x;
    if (e < Ee) atomicAdd(&g_deg[ei[e]], 1.0f);
}
__global__ void scan_kernel() {
    __shared__ int part[256];
    int tid = threadIdx.x;
    int lo = tid*40, hi = (lo + 40 < Nn) ? lo + 40 : Nn;
    int s = 0;
    for (int i = lo; i < hi; i++) s += (int)g_deg[i];
    part[tid] = s;
    __syncthreads();
    for (int off = 1; off < 256; off <<= 1) {
        int v = part[tid] + ((tid >= off) ? part[tid - off] : 0);
        __syncthreads(); part[tid] = v; __syncthreads();
    }
    int base = (tid > 0) ? part[tid - 1] : 0;
    for (int i = lo; i < hi; i++) { g_off[i] = base; base += (int)g_deg[i]; }
}
__global__ void sortscatter_kernel(const int* __restrict__ ei) {
    int e = blockIdx.x*256 + threadIdx.x;
    if (e >= Ee) return;
    int r = ei[e], c = ei[Ee + e];
    int p = g_off[r] + atomicAdd(&g_cursor[r], 1);
    g_er[p] = r; g_ec[p] = c;
}
__global__ void vocab_kernel(const float* __restrict__ emb, const float* __restrict__ Wsi1,
                             const float* __restrict__ WsiC1, const float* __restrict__ bsiC1,
                             const float* __restrict__ WsiC2, const float* __restrict__ bsiC2) {
    __shared__ float es[128], redv[128];
    int v = blockIdx.x, j = threadIdx.x;
    es[j] = emb[v*128 + j];
    __syncthreads();
    float p1 = 0.f, p2 = 0.f, hc = 0.f;
    for (int k = 0; k < 128; k++) {
        float e = es[k];
        p1 = fmaf(e, Wsi1[(1 + k)*128 + j], p1);
        p2 = fmaf(e, Wsi1[(129 + k)*128 + j], p2);
        hc = fmaf(e, WsiC1[k*128 + j], hc);
    }
    g_P1[v*128 + j] = p1; g_P2[v*128 + j] = p2;
    redv[j] = silu_f(hc + bsiC1[j]) * WsiC2[j*3 + 2];
    __syncthreads();
    for (int s = 64; s > 0; s >>= 1) {
        if (j < s) redv[j] += redv[j + s];
        __syncthreads();
    }
    if (j == 0) g_cmsg[v] = redv[0] + bsiC2[2];
}
__global__ void edge_init_kernel(const int* __restrict__ atoms,
                                 const float* __restrict__ Wsi1, const float* __restrict__ bsi1,
                                 const float* __restrict__ Wsi2, const float* __restrict__ bsi2) {
    int e = blockIdx.x*8 + (threadIdx.x >> 5);
    int lane = threadIdx.x & 31;
    int r = g_er[e], c = g_ec[e];
    float dp0 = g_pos[r*3+0] - g_pos[c*3+0];
    float dp1 = g_pos[r*3+1] - g_pos[c*3+1];
    float dp2 = g_pos[r*3+2] - g_pos[c*3+2];
    float dist = sqrtf(dp0*dp0 + dp1*dp1 + dp2*dp2);
    int ar = atoms[r], ac = atoms[c];
    float partial = 0.f;
    #pragma unroll
    for (int q = 0; q < 4; q++) {
        int d = lane + q*32;
        partial = fmaf(silu_f(dist*Wsi1[d] + g_P1[ar*128 + d] + g_P2[ac*128 + d] + bsi1[d]),
                       Wsi2[d*3 + 2], partial);
    }
    #pragma unroll
    for (int off = 16; off > 0; off >>= 1)
        partial += __shfl_xor_sync(0xffffffffu, partial, off);
    if (lane == 0) {
        float msg2 = partial + bsi2[2];
        float y2[5];
        sph2(dp0, dp1, dp2, y2);
        #pragma unroll
        for (int q = 0; q < 5; q++)
            atomicAdd(&g_ssum[r*9 + 4 + q], y2[q]*msg2);
    }
}
__global__ void sh_init_kernel(const int* __restrict__ atoms, const int* __restrict__ batch) {
    int i = blockIdx.x*256 + threadIdx.x;
    if (i >= Nn) return;
    float dg = fmaxf(g_deg[i], 1.0f);
    int b = batch[i];
    float cn = fmaxf(g_cnt[b], 1.0f);
    float y2[5];
    sph2(g_pos[i*3+0] - g_com[b*3+0]/cn, g_pos[i*3+1] - g_com[b*3+1]/cn,
         g_pos[i*3+2] - g_com[b*3+2]/cn, y2);
    float cm = g_cmsg[atoms[i]];
    #pragma unroll
    for (int q = 0; q < 4; q++) g_sh[i*9 + q] = 0.0f;
    #pragma unroll
    for (int q = 0; q < 5; q++)
        g_sh[i*9 + 4 + q] = g_ssum[i*9 + 4 + q]/dg + cm*y2[q];
}

// ============ featAB via HMMA (proven R11) ============
#define FABM_SMEM 208896
__global__ void __launch_bounds__(512, 1)
featab_mma(int layer) {
    extern __shared__ char smc[];
    unsigned sb = smem_u32(smc);
    int tid = threadIdx.x, w = tid >> 5, lane = tid & 31;
    int row0 = blockIdx.x * 128;

    {
        const uint4* ah = (const uint4*)(g_Wbh + (size_t)(layer*8 + 3)*17408);
        const uint4* al = (const uint4*)(g_Wbl + (size_t)(layer*8 + 3)*17408);
        const uint4* bh = (const uint4*)(g_Wbh + (size_t)(layer*8 + 4)*17408);
        const uint4* bl = (const uint4*)(g_Wbl + (size_t)(layer*8 + 4)*17408);
        uint4* dah = (uint4*)(smc + 69632);
        uint4* dal = (uint4*)(smc + 104448);
        uint4* dbh = (uint4*)(smc + 139264);
        uint4* dbl = (uint4*)(smc + 174080);
        for (int i = tid; i < 2176; i += 512) {
            dah[i] = ah[i]; dal[i] = al[i]; dbh[i] = bh[i]; dbl[i] = bl[i];
        }
    }
    #pragma unroll
    for (int q = 0; q < 8; q++) {
        int idx = tid + q*512;
        int r = idx >> 5, c4 = (idx & 31)*4;
        float4 v = make_float4(0.f,0.f,0.f,0.f);
        if (row0 + r < Nn) v = *(const float4*)(g_feat + (size_t)(row0 + r)*128 + c4);
        unsigned h[4], l[4];
        split_bf16(v.x, h[0], l[0]); split_bf16(v.y, h[1], l[1]);
        split_bf16(v.z, h[2], l[2]); split_bf16(v.w, h[3], l[3]);
        unsigned off = (unsigned)(r*136 + c4)*2u;
        *(uint2*)(smc + off)         = make_uint2(h[0]|(h[1]<<16), h[2]|(h[3]<<16));
        *(uint2*)(smc + 34816 + off) = make_uint2(l[0]|(l[1]<<16), l[2]|(l[3]<<16));
    }
    __syncthreads();

    int m0 = (w & 7)*16, n0 = (w >> 3)*64;
    int rl = m0 + (lane >> 2);
    float acc[8][4];
    #pragma unroll
    for (int i = 0; i < 8; i++)
        #pragma unroll
        for (int j = 0; j < 4; j++) acc[i][j] = 0.f;
    hmma_gemm(sb, sb + 34816, sb + 69632, sb + 104448, m0, n0, lane, acc);
    #pragma unroll
    for (int s = 0; s < 8; s++) {
        int col = n0 + s*8 + (lane & 3)*2;
        int ra = row0 + rl, rb = ra + 8;
        if (ra < Nn) *(float2*)(g_featA + (size_t)ra*128 + col) = make_float2(acc[s][0], acc[s][1]);
        if (rb < Nn) *(float2*)(g_featA + (size_t)rb*128 + col) = make_float2(acc[s][2], acc[s][3]);
    }
    #pragma unroll
    for (int i = 0; i < 8; i++)
        #pragma unroll
        for (int j = 0; j < 4; j++) acc[i][j] = 0.f;
    hmma_gemm(sb, sb + 34816, sb + 139264, sb + 174080, m0, n0, lane, acc);
    #pragma unroll
    for (int s = 0; s < 8; s++) {
        int col = n0 + s*8 + (lane & 3)*2;
        int ra = row0 + rl, rb = ra + 8;
        if (ra < Nn) *(float2*)(g_featB + (size_t)ra*128 + col) = make_float2(acc[s][0], acc[s][1]);
        if (rb < Nn) *(float2*)(g_featB + (size_t)rb*128 + col) = make_float2(acc[s][2], acc[s][3]);
    }
}

// ============ node update via HMMA (proven R11) ============
#define NUM_SMEM 209920
__global__ void __launch_bounds__(512, 1)
nodeup_mma(const float* __restrict__ b1, const float* __restrict__ b2, int layer) {
    extern __shared__ char smc[];
    unsigned sb = smem_u32(smc);
    float* bb = (float*)(smc + 208896);
    int tid = threadIdx.x, w = tid >> 5, lane = tid & 31;
    int row0 = blockIdx.x * 128;

    {
        const uint4* ah = (const uint4*)(g_Wbh + (size_t)(layer*8 + 5)*17408);
        const uint4* al = (const uint4*)(g_Wbl + (size_t)(layer*8 + 5)*17408);
        const uint4* bh = (const uint4*)(g_Wbh + (size_t)(layer*8 + 6)*17408);
        const uint4* bl = (const uint4*)(g_Wbl + (size_t)(layer*8 + 6)*17408);
        uint4* d1h = (uint4*)(smc + 69632);
        uint4* d1l = (uint4*)(smc + 104448);
        uint4* d2h = (uint4*)(smc + 139264);
        uint4* d2l = (uint4*)(smc + 174080);
        for (int i = tid; i < 2176; i += 512) {
            d1h[i] = ah[i]; d1l[i] = al[i]; d2h[i] = bh[i]; d2l[i] = bl[i];
        }
    }
    if (tid < 128) { bb[tid] = b1[tid]; bb[128 + tid] = b2[tid]; }
    #pragma unroll
    for (int q = 0; q < 8; q++) {
        int idx = tid + q*512;
        int r = idx >> 5, c4 = (idx & 31)*4;
        float4 v = make_float4(0.f,0.f,0.f,0.f);
        if (row0 + r < Nn) v = *(const float4*)(g_feat + (size_t)(row0 + r)*128 + c4);
        unsigned h[4], l[4];
        split_bf16(v.x, h[0], l[0]); split_bf16(v.y, h[1], l[1]);
        split_bf16(v.z, h[2], l[2]); split_bf16(v.w, h[3], l[3]);
        unsigned off = (unsigned)(r*136 + c4)*2u;
        *(uint2*)(smc + off)         = make_uint2(h[0]|(h[1]<<16), h[2]|(h[3]<<16));
        *(uint2*)(smc + 34816 + off) = make_uint2(l[0]|(l[1]<<16), l[2]|(l[3]<<16));
    }
    __syncthreads();

    int m0 = (w & 7)*16, n0 = (w >> 3)*64;
    int rl = m0 + (lane >> 2);
    float acc[8][4];
    #pragma unroll
    for (int i = 0; i < 8; i++)
        #pragma unroll
        for (int j = 0; j < 4; j++) acc[i][j] = 0.f;
    hmma_gemm(sb, sb + 34816, sb + 69632, sb + 104448, m0, n0, lane, acc);
    __syncthreads();

    {
        const uint4* ah = (const uint4*)(g_Wbh + (size_t)(layer*8 + 7)*17408);
        const uint4* al = (const uint4*)(g_Wbl + (size_t)(layer*8 + 7)*17408);
        uint4* d1h = (uint4*)(smc + 69632);
        uint4* d1l = (uint4*)(smc + 104448);
        for (int i = tid; i < 2176; i += 512) { d1h[i] = ah[i]; d1l[i] = al[i]; }
    }
    #pragma unroll
    for (int q = 0; q < 8; q++) {
        int idx = tid + q*512;
        int r = idx >> 5, c4 = (idx & 31)*4;
        float4 v = make_float4(0.f,0.f,0.f,0.f);
        if (row0 + r < Nn) {
            v = *(const float4*)(g_msum + (size_t)(row0 + r)*128 + c4);
            float inv = 1.0f / fmaxf(g_deg[row0 + r], 1.0f);
            v.x *= inv; v.y *= inv; v.z *= inv; v.w *= inv;
        }
        unsigned h[4], l[4];
        split_bf16(v.x, h[0], l[0]); split_bf16(v.y, h[1], l[1]);
        split_bf16(v.z, h[2], l[2]); split_bf16(v.w, h[3], l[3]);
        unsigned off = (unsigned)(r*136 + c4)*2u;
        *(uint2*)(smc + off)         = make_uint2(h[0]|(h[1]<<16), h[2]|(h[3]<<16));
        *(uint2*)(smc + 34816 + off) = make_uint2(l[0]|(l[1]<<16), l[2]|(l[3]<<16));
    }
    __syncthreads();
    hmma_gemm(sb, sb + 34816, sb + 139264, sb + 174080, m0, n0, lane, acc);
    __syncthreads();

    #pragma unroll
    for (int s = 0; s < 8; s++) {
        int col = n0 + s*8 + (lane & 3)*2;
        float v00 = silu_f(acc[s][0] + bb[col]);
        float v01 = silu_f(acc[s][1] + bb[col+1]);
        float v10 = silu_f(acc[s][2] + bb[col]);
        float v11 = silu_f(acc[s][3] + bb[col+1]);
        unsigned h0, l0, h1, l1;
        split_bf16(v00, h0, l0); split_bf16(v01, h1, l1);
        *(unsigned*)(smc + (rl*136 + col)*2)         = h0 | (h1 << 16);
        *(unsigned*)(smc + 34816 + (rl*136 + col)*2) = l0 | (l1 << 16);
        split_bf16(v10, h0, l0); split_bf16(v11, h1, l1);
        *(unsigned*)(smc + ((rl+8)*136 + col)*2)         = h0 | (h1 << 16);
        *(unsigned*)(smc + 34816 + ((rl+8)*136 + col)*2) = l0 | (l1 << 16);
    }
    __syncthreads();
    #pragma unroll
    for (int i = 0; i < 8; i++)
        #pragma unroll
        for (int j = 0; j < 4; j++) acc[i][j] = 0.f;
    hmma_gemm(sb, sb + 34816, sb + 69632, sb + 104448, m0, n0, lane, acc);
    #pragma unroll
    for (int s = 0; s < 8; s++) {
        int col = n0 + s*8 + (lane & 3)*2;
        int ra = row0 + rl, rb = ra + 8;
        if (ra < Nn) *(float2*)(g_feat + (size_t)ra*128 + col) =
            make_float2(acc[s][0] + bb[128+col], acc[s][1] + bb[128+col+1]);
        if (rb < Nn) *(float2*)(g_feat + (size_t)rb*128 + col) =
            make_float2(acc[s][2] + bb[128+col], acc[s][3] + bb[128+col+1]);
    }
}

// ============ FUSED edge kernel: h-build + m/p/s GEMMs + scatters ============
// bytes: Ah 0 | Al 34816 | Wh 69632 | Wl 104448 | m_s[128][137] 139264 (70144) |
// scal 209408 | bh 211456 | bhp 211968 | bhs 212480 | w2p 212992 | w2s 213504 |
// pd 215040 (4096) | ridx 219136 | cidx 219648 | wtl 220160 (2560) -> 222720
#define FU_SMEM 222720
__global__ void __launch_bounds__(512, 1)
edge_fused_mma(const float* __restrict__ bm2l,
               const float* __restrict__ Wm1tail, const float* __restrict__ bm1l,
               const float* __restrict__ bp1l, const float* __restrict__ Wp2l,
               const float* __restrict__ bp2l,
               const float* __restrict__ bs1l, const float* __restrict__ Ws2l,
               const float* __restrict__ bs2l, int layer) {
    extern __shared__ char smc[];
    unsigned sb = smem_u32(smc);
    float* m_s  = (float*)(smc + 139264);
    float* scal = (float*)(smc + 209408);
    float* bh   = (float*)(smc + 211456);
    float* bhp  = (float*)(smc + 211968);
    float* bhs  = (float*)(smc + 212480);
    float* w2p  = (float*)(smc + 212992);
    float* w2s  = (float*)(smc + 213504);
    float* pd   = (float*)(smc + 215040);
    int* ridx   = (int*)(smc + 219136);
    int* cidx   = (int*)(smc + 219648);
    float* wtl  = (float*)(smc + 220160);
    int tid = threadIdx.x, w = tid >> 5, lane = tid & 31;

    const char* Wm2h = (const char*)(g_Wbh + (size_t)(layer*8 + 0)*17408);
    const char* Wm2l = (const char*)(g_Wbl + (size_t)(layer*8 + 0)*17408);
    const char* Wp1h = (const char*)(g_Wbh + (size_t)(layer*8 + 1)*17408);
    const char* Wp1l = (const char*)(g_Wbl + (size_t)(layer*8 + 1)*17408);
    const char* Ws1h = (const char*)(g_Wbh + (size_t)(layer*8 + 2)*17408);
    const char* Ws1l = (const char*)(g_Wbl + (size_t)(layer*8 + 2)*17408);

    if (tid < 128) {
        bh[tid] = bm2l[tid]; bhp[tid] = bp1l[tid]; bhs[tid] = bs1l[tid];
        w2p[tid] = Wp2l[tid];
        w2s[tid*3+0] = Ws2l[tid*3+0]; w2s[tid*3+1] = Ws2l[tid*3+1]; w2s[tid*3+2] = Ws2l[tid*3+2];
    }
    for (int i = tid; i < 640; i += 512)
        wtl[i] = (i < 512) ? Wm1tail[i] : bm1l[i - 512];

    int m0 = (w & 7)*16, n0 = (w >> 3)*64;
    int chalf = w >> 3;
    int r0l = m0 + (lane >> 2), r1l = r0l + 8;

    for (int t = blockIdx.x; t < NT; t += gridDim.x) {
        int e0 = t*128;
        __syncthreads();   // prev tile fully done (m_s/A/W/pd free)
        // async-load Wm2 while doing scal + h-build
        for (int i = tid; i < 2176; i += 512) {
            asm volatile("cp.async.cg.shared.global [%0], [%1], 16;"
                :: "r"(sb + 69632u + (unsigned)i*16u), "l"(Wm2h + (size_t)i*16) : "memory");
            asm volatile("cp.async.cg.shared.global [%0], [%1], 16;"
                :: "r"(sb + 104448u + (unsigned)i*16u), "l"(Wm2l + (size_t)i*16) : "memory");
        }
        asm volatile("cp.async.commit_group;" ::: "memory");
        if (tid < 128) {
            int r = g_er[e0 + tid], c = g_ec[e0 + tid];
            ridx[tid] = r; cidx[tid] = c;
            float dp0 = g_pos[r*3+0] - g_pos[c*3+0];
            float dp1 = g_pos[r*3+1] - g_pos[c*3+1];
            float dp2 = g_pos[r*3+2] - g_pos[c*3+2];
            float ip2 = 0.f;
            #pragma unroll
            for (int q = 4; q < 9; q++) ip2 += g_sh[r*9+q]*g_sh[c*9+q];
            scal[tid*4+0] = dp0*dp0 + dp1*dp1 + dp2*dp2;
            scal[tid*4+1] = g_sh[r*9+0]*g_sh[c*9+0];
            scal[tid*4+2] = g_sh[r*9+1]*g_sh[c*9+1] + g_sh[r*9+2]*g_sh[c*9+2] + g_sh[r*9+3]*g_sh[c*9+3];
            scal[tid*4+3] = ip2;
        }
        __syncthreads();   // scal/idx ready
        #pragma unroll
        for (int q = 0; q < 8; q++) {
            int idx = tid + q*512;
            int e = idx >> 5, c4 = (idx & 31)*4;
            int r = ridx[e], c = cidx[e];
            float4 fa = *(const float4*)(g_featA + (size_t)r*128 + c4);
            float4 fb = *(const float4*)(g_featB + (size_t)c*128 + c4);
            float d2 = scal[e*4+0], i0 = scal[e*4+1], i1 = scal[e*4+2], i2 = scal[e*4+3];
            float hv[4];
            hv[0] = silu_f(fa.x + fb.x + d2*wtl[c4+0] + i0*wtl[128+c4+0] + i1*wtl[256+c4+0] + i2*wtl[384+c4+0] + wtl[512+c4+0]);
            hv[1] = silu_f(fa.y + fb.y + d2*wtl[c4+1] + i0*wtl[128+c4+1] + i1*wtl[256+c4+1] + i2*wtl[384+c4+1] + wtl[512+c4+1]);
            hv[2] = silu_f(fa.z + fb.z + d2*wtl[c4+2] + i0*wtl[128+c4+2] + i1*wtl[256+c4+2] + i2*wtl[384+c4+2] + wtl[512+c4+2]);
            hv[3] = silu_f(fa.w + fb.w + d2*wtl[c4+3] + i0*wtl[128+c4+3] + i1*wtl[256+c4+3] + i2*wtl[384+c4+3] + wtl[512+c4+3]);
            unsigned h[4], l[4];
            #pragma unroll
            for (int j = 0; j < 4; j++) split_bf16(hv[j], h[j], l[j]);
            unsigned off = (unsigned)(e*136 + c4)*2u;
            *(uint2*)(smc + off)         = make_uint2(h[0]|(h[1]<<16), h[2]|(h[3]<<16));
            *(uint2*)(smc + 34816 + off) = make_uint2(l[0]|(l[1]<<16), l[2]|(l[3]<<16));
        }
        asm volatile("cp.async.wait_group 0;" ::: "memory");
        __syncthreads();   // A(h) + Wm2 ready

        // GEMM1: m
        float acc[8][4];
        #pragma unroll
        for (int i = 0; i < 8; i++)
            #pragma unroll
            for (int j = 0; j < 4; j++) acc[i][j] = 0.f;
        hmma_gemm(sb, sb + 34816, sb + 69632, sb + 104448, m0, n0, lane, acc);
        __syncthreads();   // all reads of A + W done

        // async-load Wp1 while writing m epilogue (m_s fp32 + split into A)
        for (int i = tid; i < 2176; i += 512) {
            asm volatile("cp.async.cg.shared.global [%0], [%1], 16;"
                :: "r"(sb + 69632u + (unsigned)i*16u), "l"(Wp1h + (size_t)i*16) : "memory");
            asm volatile("cp.async.cg.shared.global [%0], [%1], 16;"
                :: "r"(sb + 104448u + (unsigned)i*16u), "l"(Wp1l + (size_t)i*16) : "memory");
        }
        asm volatile("cp.async.commit_group;" ::: "memory");
        #pragma unroll
        for (int s = 0; s < 8; s++) {
            int col = n0 + s*8 + (lane & 3)*2;
            float v00 = silu_f(acc[s][0] + bh[col]);
            float v01 = silu_f(acc[s][1] + bh[col+1]);
            float v10 = silu_f(acc[s][2] + bh[col]);
            float v11 = silu_f(acc[s][3] + bh[col+1]);
            m_s[r0l*137 + col]     = v00;
            m_s[r0l*137 + col + 1] = v01;
            m_s[r1l*137 + col]     = v10;
            m_s[r1l*137 + col + 1] = v11;
            unsigned h0, l0, h1, l1;
            split_bf16(v00, h0, l0); split_bf16(v01, h1, l1);
            *(unsigned*)(smc + (r0l*136 + col)*2)         = h0 | (h1 << 16);
            *(unsigned*)(smc + 34816 + (r0l*136 + col)*2) = l0 | (l1 << 16);
            split_bf16(v10, h0, l0); split_bf16(v11, h1, l1);
            *(unsigned*)(smc + (r1l*136 + col)*2)         = h0 | (h1 << 16);
            *(unsigned*)(smc + 34816 + (r1l*136 + col)*2) = l0 | (l1 << 16);
        }
        asm volatile("cp.async.wait_group 0;" ::: "memory");
        __syncthreads();   // A(m-split) + Wp1 ready

        // GEMM2: p
        float accp[8][4];
        #pragma unroll
        for (int i = 0; i < 8; i++)
            #pragma unroll
            for (int j = 0; j < 4; j++) accp[i][j] = 0.f;
        hmma_gemm(sb, sb + 34816, sb + 69632, sb + 104448, m0, n0, lane, accp);
        __syncthreads();   // W reads done

        // async-load Ws1 while doing p epilogue
        for (int i = tid; i < 2176; i += 512) {
            asm volatile("cp.async.cg.shared.global [%0], [%1], 16;"
                :: "r"(sb + 69632u + (unsigned)i*16u), "l"(Ws1h + (size_t)i*16) : "memory");
            asm volatile("cp.async.cg.shared.global [%0], [%1], 16;"
                :: "r"(sb + 104448u + (unsigned)i*16u), "l"(Ws1l + (size_t)i*16) : "memory");
        }
        asm volatile("cp.async.commit_group;" ::: "memory");
        {
            float pr0 = 0.f, pr1 = 0.f;
            #pragma unroll
            for (int s = 0; s < 8; s++) {
                int col = n0 + s*8 + (lane & 3)*2;
                pr0 = fmaf(silu_f(accp[s][0] + bhp[col]),   w2p[col],
                      fmaf(silu_f(accp[s][1] + bhp[col+1]), w2p[col+1], pr0));
                pr1 = fmaf(silu_f(accp[s][2] + bhp[col]),   w2p[col],
                      fmaf(silu_f(accp[s][3] + bhp[col+1]), w2p[col+1], pr1));
            }
            #pragma unroll
            for (int off = 1; off <= 2; off <<= 1) {
                pr0 += __shfl_xor_sync(0xffffffffu, pr0, off);
                pr1 += __shfl_xor_sync(0xffffffffu, pr1, off);
            }
            if ((lane & 3) == 0) {
                pd[chalf*512 + r0l*4 + 0] = pr0;
                pd[chalf*512 + r1l*4 + 0] = pr1;
            }
        }
        asm volatile("cp.async.wait_group 0;" ::: "memory");
        __syncthreads();   // Ws1 ready (A untouched)

        // GEMM3: s
        float accs[8][4];
        #pragma unroll
        for (int i = 0; i < 8; i++)
            #pragma unroll
            for (int j = 0; j < 4; j++) accs[i][j] = 0.f;
        hmma_gemm(sb, sb + 34816, sb + 69632, sb + 104448, m0, n0, lane, accs);
        {
            float s0r0 = 0.f, s1r0 = 0.f, s2r0 = 0.f;
            float s0r1 = 0.f, s1r1 = 0.f, s2r1 = 0.f;
            #pragma unroll
            for (int s = 0; s < 8; s++) {
                int col = n0 + s*8 + (lane & 3)*2;
                float g00 = silu_f(accs[s][0] + bhs[col]);
                float g01 = silu_f(accs[s][1] + bhs[col+1]);
                float g10 = silu_f(accs[s][2] + bhs[col]);
                float g11 = silu_f(accs[s][3] + bhs[col+1]);
                s0r0 = fmaf(g00, w2s[col*3+0], fmaf(g01, w2s[(col+1)*3+0], s0r0));
                s1r0 = fmaf(g00, w2s[col*3+1], fmaf(g01, w2s[(col+1)*3+1], s1r0));
                s2r0 = fmaf(g00, w2s[col*3+2], fmaf(g01, w2s[(col+1)*3+2], s2r0));
                s0r1 = fmaf(g10, w2s[col*3+0], fmaf(g11, w2s[(col+1)*3+0], s0r1));
                s1r1 = fmaf(g10, w2s[col*3+1], fmaf(g11, w2s[(col+1)*3+1], s1r1));
                s2r1 = fmaf(g10, w2s[col*3+2], fmaf(g11, w2s[(col+1)*3+2], s2r1));
            }
            #pragma unroll
            for (int off = 1; off <= 2; off <<= 1) {
                s0r0 += __shfl_xor_sync(0xffffffffu, s0r0, off);
                s1r0 += __shfl_xor_sync(0xffffffffu, s1r0, off);
                s2r0 += __shfl_xor_sync(0xffffffffu, s2r0, off);
                s0r1 += __shfl_xor_sync(0xffffffffu, s0r1, off);
                s1r1 += __shfl_xor_sync(0xffffffffu, s1r1, off);
                s2r1 += __shfl_xor_sync(0xffffffffu, s2r1, off);
            }
            if ((lane & 3) == 0) {
                float* p0 = pd + chalf*512 + r0l*4;
                p0[1] = s0r0; p0[2] = s1r0; p0[3] = s2r0;
                float* p1 = pd + chalf*512 + r1l*4;
                p1[1] = s0r1; p1[2] = s1r1; p1[3] = s2r1;
            }
        }
        __syncthreads();
        // scatters
        if (tid < 128) {
            int e = e0 + tid;
            int r = ridx[tid], c = cidx[tid];
            (void)e;
            float psc = pd[tid*4+0] + pd[512 + tid*4+0] + bp2l[0];
            float s0  = pd[tid*4+1] + pd[512 + tid*4+1] + bs2l[0];
            float s1  = pd[tid*4+2] + pd[512 + tid*4+2] + bs2l[1];
            float s2  = pd[tid*4+3] + pd[512 + tid*4+3] + bs2l[2];
            float dp0 = g_pos[r*3+0] - g_pos[c*3+0];
            float dp1 = g_pos[r*3+1] - g_pos[c*3+1];
            float dp2 = g_pos[r*3+2] - g_pos[c*3+2];
            atomicAdd(&g_psum[r*3+0], dp0*psc);
            atomicAdd(&g_psum[r*3+1], dp1*psc);
            atomicAdd(&g_psum[r*3+2], dp2*psc);
            #pragma unroll
            for (int q = 0; q < 9; q++) {
                float diff = g_sh[r*9+q] - g_sh[c*9+q];
                atomicAdd(&g_ssum[r*9+q], diff * ((q == 0) ? s0 : (q < 4) ? s1 : s2));
            }
        }
        // msum sorted-run RED
        {
            int c = tid & 127, seg = tid >> 7;
            int eb = seg*32;
            float agg = 0.f;
            int ar = ridx[eb];
            for (int e = eb; e < eb + 32; e++) {
                float v = m_s[e*137 + c];
                int r = ridx[e];
                if (r != ar) { atomicAdd(&g_msum[(size_t)ar*128 + c], agg); agg = v; ar = r; }
                else agg += v;
            }
            atomicAdd(&g_msum[(size_t)ar*128 + c], agg);
        }
    }
}

__global__ void posh_kernel() {
    int i = blockIdx.x*256 + threadIdx.x;
    if (i >= Nn) return;
    float inv = 1.0f / fmaxf(g_deg[i], 1.0f);
    #pragma unroll
    for (int q = 0; q < 3; q++) g_pos[i*3+q] += g_psum[i*3+q]*inv;
    #pragma unroll
    for (int q = 0; q < 9; q++) g_sh[i*9+q] += g_ssum[i*9+q]*inv;
}
__global__ void pool_kernel(const int* __restrict__ batch) {
    int idx = blockIdx.x*256 + threadIdx.x;
    if (idx >= Nn*140) return;
    int i = idx / 140, c = idx % 140;
    float v;
    if (c < 128)      v = g_feat[(size_t)i*128 + c];
    else if (c < 131) v = g_pos[i*3 + (c - 128)];
    else              v = g_sh[i*9 + (c - 131)];
    atomicAdd(&g_pool[batch[i]*140 + c], v);
}
__global__ void pred_kernel(const float* __restrict__ Wpred, const float* __restrict__ bpred,
                            float* __restrict__ out) {
    int g = blockIdx.x, lane = threadIdx.x;
    float s = 0.f;
    for (int c = lane; c < 140; c += 32)
        s = fmaf(g_pool[g*140 + c], Wpred[c], s);
    #pragma unroll
    for (int off = 16; off > 0; off >>= 1)
        s += __shfl_xor_sync(0xffffffffu, s, off);
    if (lane == 0) out[g] = s + bpred[0];
}

extern "C" void kernel_launch(void* const* d_in, const int* in_sizes, int n_in,
                              void* d_out, int out_size) {
    const int*   atoms = (const int*)d_in[0];
    const int*   ei    = (const int*)d_in[1];
    const int*   batch = (const int*)d_in[2];
    const float* pos   = (const float*)d_in[3];
    const float* emb   = (const float*)d_in[4];
    const float* Wsi1  = (const float*)d_in[5];  const float* bsi1  = (const float*)d_in[6];
    const float* Wsi2  = (const float*)d_in[7];  const float* bsi2  = (const float*)d_in[8];
    const float* WsiC1 = (const float*)d_in[9];  const float* bsiC1 = (const float*)d_in[10];
    const float* WsiC2 = (const float*)d_in[11]; const float* bsiC2 = (const float*)d_in[12];
    const float* Wm1   = (const float*)d_in[13]; const float* bm1   = (const float*)d_in[14];
    const float* Wm2   = (const float*)d_in[15]; const float* bm2   = (const float*)d_in[16];
    const float* Wp1   = (const float*)d_in[17]; const float* bp1   = (const float*)d_in[18];
    const float* Wp2   = (const float*)d_in[19]; const float* bp2   = (const float*)d_in[20];
    const float* Wn1   = (const float*)d_in[21]; const float* bn1   = (const float*)d_in[22];
    const float* Wn2   = (const float*)d_in[23]; const float* bn2   = (const float*)d_in[24];
    const float* Ws1   = (const float*)d_in[25]; const float* bs1   = (const float*)d_in[26];
    const float* Ws2   = (const float*)d_in[27]; const float* bs2   = (const float*)d_in[28];
    const float* Wpred = (const float*)d_in[29]; const float* bpred = (const float*)d_in[30];
    float* out = (float*)d_out;

    cudaFuncSetAttribute(featab_mma, cudaFuncAttributeMaxDynamicSharedMemorySize, FABM_SMEM);
    cudaFuncSetAttribute(nodeup_mma, cudaFuncAttributeMaxDynamicSharedMemorySize, NUM_SMEM);
    cudaFuncSetAttribute(edge_fused_mma, cudaFuncAttributeMaxDynamicSharedMemorySize, FU_SMEM);

    void *p_msum, *p_psum, *p_ssum, *p_deg, *p_com, *p_cnt, *p_pool, *p_pos, *p_cur;
    cudaGetSymbolAddress(&p_msum, g_msum);
    cudaGetSymbolAddress(&p_psum, g_psum);
    cudaGetSymbolAddress(&p_ssum, g_ssum);
    cudaGetSymbolAddress(&p_deg,  g_deg);
    cudaGetSymbolAddress(&p_com,  g_com);
    cudaGetSymbolAddress(&p_cnt,  g_cnt);
    cudaGetSymbolAddress(&p_pool, g_pool);
    cudaGetSymbolAddress(&p_pos,  g_pos);
    cudaGetSymbolAddress(&p_cur,  g_cursor);

    cudaMemsetAsync(p_deg,  0, Nn*4, 0);
    cudaMemsetAsync(p_com,  0, Gg*3*4, 0);
    cudaMemsetAsync(p_cnt,  0, Gg*4, 0);
    cudaMemsetAsync(p_ssum, 0, Nn*9*4, 0);
    cudaMemsetAsync(p_pool, 0, Gg*140*4, 0);
    cudaMemsetAsync(p_cur,  0, Nn*4, 0);
    cudaMemcpyAsync(p_pos, pos, Nn*3*4, cudaMemcpyDeviceToDevice, 0);

    wprep_kernel<<<40, 256>>>(Wm2, Wp1, Ws1, Wm1, Wn1, Wn2);
    node_init_kernel<<<(Nn*128)/256, 256>>>(atoms, emb);
    com_kernel<<<(Nn + 255)/256, 256>>>(batch);
    deg_kernel<<<(Ee + 255)/256, 256>>>(ei);
    scan_kernel<<<1, 256>>>();
    sortscatter_kernel<<<(Ee + 255)/256, 256>>>(ei);
    vocab_kernel<<<10, 128>>>(emb, Wsi1, WsiC1, bsiC1, WsiC2, bsiC2);
    edge_init_kernel<<<Ee/8, 256>>>(atoms, Wsi1, bsi1, Wsi2, bsi2);
    sh_init_kernel<<<(Nn + 255)/256, 256>>>(atoms, batch);

    int gridNM = (Nn + 127)/128;   // 79

    for (int l = 0; l < Ll; l++) {
        cudaMemsetAsync(p_msum, 0, (size_t)Nn*128*4, 0);
        cudaMemsetAsync(p_psum, 0, Nn*3*4, 0);
        cudaMemsetAsync(p_ssum, 0, Nn*9*4, 0);

        featab_mma<<<gridNM, 512, FABM_SMEM>>>(l);

        edge_fused_mma<<<148, 512, FU_SMEM>>>(
            bm2 + l*128,
            Wm1 + ((size_t)l*260 + 256)*128, bm1 + l*128,
            bp1 + l*128, Wp2 + l*128, bp2 + l,
            bs1 + l*128, Ws2 + l*384, bs2 + l*3, l);

        posh_kernel<<<(Nn + 255)/256, 256>>>();

        nodeup_mma<<<gridNM, 512, NUM_SMEM>>>(bn1 + l*128, bn2 + l*128, l);
    }

    pool_kernel<<<(Nn*140 + 255)/256, 256>>>(batch);
    pred_kernel<<<Gg, 32>>>(Wpred, bpred, out);
}

// round 13
// speedup vs baseline: 1.8468x; 1.0015x over previous
#include <cuda_runtime.h>
#include <cuda_bf16.h>
#include <cstdint>
#include <math.h>

#define Nn 10000
#define Ee 160000
#define Gg 100
#define Ll 5
#define NT 1250   // 128-edge tiles

typedef unsigned long long u64;
typedef unsigned short ush;

__device__ float g_feat [Nn*128];
__device__ float g_featA[Nn*128];
__device__ float g_featB[Nn*128];
__device__ float g_sh   [Nn*9];
__device__ float g_pos  [Nn*3];
__device__ float g_msum [Nn*128];
__device__ float g_psum [Nn*3];
__device__ float g_ssum [Nn*9];
__device__ float g_deg  [Nn];
__device__ float g_com  [Gg*3];
__device__ float g_cnt  [Gg];
__device__ float g_P1   [10*128];
__device__ float g_P2   [10*128];
__device__ float g_cmsg [10];
__device__ float g_pool [Gg*140];
__device__ int   g_off  [Nn];
__device__ int   g_cursor[Nn];
__device__ int   g_er   [Ee];
__device__ int   g_ec   [Ee];
__device__ ush   g_Wbh [40*17408];          // [l*8+slot][n*136+k] hi
__device__ ush   g_Wbl [40*17408];          // lo

__device__ __forceinline__ float silu_f(float x) { return x / (1.0f + __expf(-x)); }

__device__ __forceinline__ void sph2(float vx, float vy, float vz, float* o) {
    const float S3 = 1.7320508075688772f, HS3 = 0.8660254037844386f;
    float r = sqrtf(vx*vx + vy*vy + vz*vz);
    float inv = 1.0f / fmaxf(r, 1e-12f);
    float x = vx*inv, y = vy*inv, z = vz*inv;
    o[0] = S3*x*z; o[1] = S3*x*y; o[2] = y*y - 0.5f*(x*x + z*z);
    o[3] = S3*y*z; o[4] = HS3*(z*z - x*x);
}

// ---- HMMA helpers ----
__device__ __forceinline__ unsigned smem_u32(const void* p) {
    unsigned a; asm("{ .reg .u64 t; cvta.to.shared.u64 t, %1; cvt.u32.u64 %0, t; }" : "=r"(a) : "l"(p));
    return a;
}
__device__ __forceinline__ void ldsm4(unsigned addr, unsigned* r) {
    asm volatile("ldmatrix.sync.aligned.m8n8.x4.shared.b16 {%0,%1,%2,%3}, [%4];"
        : "=r"(r[0]), "=r"(r[1]), "=r"(r[2]), "=r"(r[3]) : "r"(addr));
}
__device__ __forceinline__ void mma_bf16(float* d, const unsigned* a, unsigned b0, unsigned b1) {
    asm volatile("mma.sync.aligned.m16n8k16.row.col.f32.bf16.bf16.f32 "
        "{%0,%1,%2,%3},{%4,%5,%6,%7},{%8,%9},{%0,%1,%2,%3};"
        : "+f"(d[0]), "+f"(d[1]), "+f"(d[2]), "+f"(d[3])
        : "r"(a[0]), "r"(a[1]), "r"(a[2]), "r"(a[3]), "r"(b0), "r"(b1));
}
__device__ __forceinline__ void split_bf16(float v, unsigned& h, unsigned& l) {
    __nv_bfloat16 hb = __float2bfloat16(v);
    h = (unsigned)__bfloat16_as_ushort(hb);
    l = (unsigned)__bfloat16_as_ushort(__float2bfloat16(v - __bfloat162float(hb)));
}

// split-bf16 GEMM core: rows m0..+15 x cols n0..+63, K=128; A/B ush stride 136 (272 B)
__device__ __forceinline__ void hmma_gemm(unsigned aH, unsigned aL, unsigned bH, unsigned bL,
                                          int m0, int n0, int lane, float acc[8][4]) {
    unsigned aoff = (unsigned)((m0 + (lane & 15))*272 + (lane >> 4)*16);
    unsigned boff = (unsigned)((n0 + (lane & 15))*272 + (lane >> 4)*16);
    #pragma unroll
    for (int kk = 0; kk < 8; kk++) {
        unsigned kb = kk*32;
        unsigned Ah[4], Al[4];
        ldsm4(aH + aoff + kb, Ah);
        ldsm4(aL + aoff + kb, Al);
        #pragma unroll
        for (int t = 0; t < 4; t++) {
            unsigned bo = boff + t*16*272 + kb;
            unsigned Bh[4], Bl[4];
            ldsm4(bH + bo, Bh);
            ldsm4(bL + bo, Bl);
            mma_bf16(acc[2*t],   Ah, Bh[0], Bh[2]);
            mma_bf16(acc[2*t],   Ah, Bl[0], Bl[2]);
            mma_bf16(acc[2*t],   Al, Bh[0], Bh[2]);
            mma_bf16(acc[2*t+1], Ah, Bh[1], Bh[3]);
            mma_bf16(acc[2*t+1], Ah, Bl[1], Bl[3]);
            mma_bf16(acc[2*t+1], Al, Bh[1], Bh[3]);
        }
    }
}

// weights -> split-bf16 [n][k] stride-136 tiles
// slot: 0 Wm2, 1 Wp1, 2 Ws1, 3 Wa, 4 Wb, 5 W5, 6 W6, 7 W7
__global__ void wprep_kernel(const float* __restrict__ Wm2, const float* __restrict__ Wp1,
                             const float* __restrict__ Ws1, const float* __restrict__ Wm1,
                             const float* __restrict__ Wn1, const float* __restrict__ Wn2) {
    int bid = blockIdx.x, l = bid >> 3, slot = bid & 7;
    const float* src;
    switch (slot) {
        case 0: src = Wm2 + (size_t)l*16384;              break;
        case 1: src = Wp1 + (size_t)l*16384;              break;
        case 2: src = Ws1 + (size_t)l*16384;              break;
        case 3: src = Wm1 + (size_t)l*260*128;            break;
        case 4: src = Wm1 + ((size_t)l*260 + 128)*128;    break;
        case 5: src = Wn1 + (size_t)l*256*128;            break;
        case 6: src = Wn1 + ((size_t)l*256 + 128)*128;    break;
        default:src = Wn2 + (size_t)l*16384;              break;
    }
    ush* dh = g_Wbh + (size_t)bid*17408;
    ush* dl = g_Wbl + (size_t)bid*17408;
    for (int o = threadIdx.x; o < 16384; o += 256) {
        int k = o >> 7, n = o & 127;
        unsigned h, lo;
        split_bf16(src[k*128 + n], h, lo);
        dh[n*136 + k] = (ush)h;
        dl[n*136 + k] = (ush)lo;
    }
}

// ---- init kernels ----
__global__ void node_init_kernel(const int* __restrict__ atoms, const float* __restrict__ emb) {
    int idx = blockIdx.x*256 + threadIdx.x;
    g_feat[idx] = emb[atoms[idx >> 7]*128 + (idx & 127)];
}
__global__ void com_kernel(const int* __restrict__ batch) {
    int i = blockIdx.x*256 + threadIdx.x;
    if (i >= Nn) return;
    int b = batch[i];
    atomicAdd(&g_com[b*3+0], g_pos[i*3+0]);
    atomicAdd(&g_com[b*3+1], g_pos[i*3+1]);
    atomicAdd(&g_com[b*3+2], g_pos[i*3+2]);
    atomicAdd(&g_cnt[b], 1.0f);
}
__global__ void deg_kernel(const int* __restrict__ ei) {
    int e = blockIdx.x*256 + threadIdx.x;
    if (e < Ee) atomicAdd(&g_deg[ei[e]], 1.0f);
}
__global__ void scan_kernel() {
    __shared__ int part[256];
    int tid = threadIdx.x;
    int lo = tid*40, hi = (lo + 40 < Nn) ? lo + 40 : Nn;
    int s = 0;
    for (int i = lo; i < hi; i++) s += (int)g_deg[i];
    part[tid] = s;
    __syncthreads();
    for (int off = 1; off < 256; off <<= 1) {
        int v = part[tid] + ((tid >= off) ? part[tid - off] : 0);
        __syncthreads(); part[tid] = v; __syncthreads();
    }
    int base = (tid > 0) ? part[tid - 1] : 0;
    for (int i = lo; i < hi; i++) { g_off[i] = base; base += (int)g_deg[i]; }
}
__global__ void sortscatter_kernel(const int* __restrict__ ei) {
    int e = blockIdx.x*256 + threadIdx.x;
    if (e >= Ee) return;
    int r = ei[e], c = ei[Ee + e];
    int p = g_off[r] + atomicAdd(&g_cursor[r], 1);
    g_er[p] = r; g_ec[p] = c;
}
__global__ void vocab_kernel(const float* __restrict__ emb, const float* __restrict__ Wsi1,
                             const float* __restrict__ WsiC1, const float* __restrict__ bsiC1,
                             const float* __restrict__ WsiC2, const float* __restrict__ bsiC2) {
    __shared__ float es[128], redv[128];
    int v = blockIdx.x, j = threadIdx.x;
    es[j] = emb[v*128 + j];
    __syncthreads();
    float p1 = 0.f, p2 = 0.f, hc = 0.f;
    for (int k = 0; k < 128; k++) {
        float e = es[k];
        p1 = fmaf(e, Wsi1[(1 + k)*128 + j], p1);
        p2 = fmaf(e, Wsi1[(129 + k)*128 + j], p2);
        hc = fmaf(e, WsiC1[k*128 + j], hc);
    }
    g_P1[v*128 + j] = p1; g_P2[v*128 + j] = p2;
    redv[j] = silu_f(hc + bsiC1[j]) * WsiC2[j*3 + 2];
    __syncthreads();
    for (int s = 64; s > 0; s >>= 1) {
        if (j < s) redv[j] += redv[j + s];
        __syncthreads();
    }
    if (j == 0) g_cmsg[v] = redv[0] + bsiC2[2];
}
__global__ void edge_init_kernel(const int* __restrict__ atoms,
                                 const float* __restrict__ Wsi1, const float* __restrict__ bsi1,
                                 const float* __restrict__ Wsi2, const float* __restrict__ bsi2) {
    int e = blockIdx.x*8 + (threadIdx.x >> 5);
    int lane = threadIdx.x & 31;
    int r = g_er[e], c = g_ec[e];
    float dp0 = g_pos[r*3+0] - g_pos[c*3+0];
    float dp1 = g_pos[r*3+1] - g_pos[c*3+1];
    float dp2 = g_pos[r*3+2] - g_pos[c*3+2];
    float dist = sqrtf(dp0*dp0 + dp1*dp1 + dp2*dp2);
    int ar = atoms[r], ac = atoms[c];
    float partial = 0.f;
    #pragma unroll
    for (int q = 0; q < 4; q++) {
        int d = lane + q*32;
        partial = fmaf(silu_f(dist*Wsi1[d] + g_P1[ar*128 + d] + g_P2[ac*128 + d] + bsi1[d]),
                       Wsi2[d*3 + 2], partial);
    }
    #pragma unroll
    for (int off = 16; off > 0; off >>= 1)
        partial += __shfl_xor_sync(0xffffffffu, partial, off);
    if (lane == 0) {
        float msg2 = partial + bsi2[2];
        float y2[5];
        sph2(dp0, dp1, dp2, y2);
        #pragma unroll
        for (int q = 0; q < 5; q++)
            atomicAdd(&g_ssum[r*9 + 4 + q], y2[q]*msg2);
    }
}
// sh_init also clears ssum for the first layer's edge pass
__global__ void sh_init_kernel(const int* __restrict__ atoms, const int* __restrict__ batch) {
    int i = blockIdx.x*256 + threadIdx.x;
    if (i >= Nn) return;
    float dg = fmaxf(g_deg[i], 1.0f);
    int b = batch[i];
    float cn = fmaxf(g_cnt[b], 1.0f);
    float y2[5];
    sph2(g_pos[i*3+0] - g_com[b*3+0]/cn, g_pos[i*3+1] - g_com[b*3+1]/cn,
         g_pos[i*3+2] - g_com[b*3+2]/cn, y2);
    float cm = g_cmsg[atoms[i]];
    #pragma unroll
    for (int q = 0; q < 4; q++) g_sh[i*9 + q] = 0.0f;
    #pragma unroll
    for (int q = 0; q < 5; q++)
        g_sh[i*9 + 4 + q] = g_ssum[i*9 + 4 + q]/dg + cm*y2[q];
    #pragma unroll
    for (int q = 0; q < 9; q++) g_ssum[i*9 + q] = 0.0f;
}

// ============ featAB via HMMA (layer 0 only) ============
#define FABM_SMEM 208896
__global__ void __launch_bounds__(512, 1)
featab_mma(int layer) {
    extern __shared__ char smc[];
    unsigned sb = smem_u32(smc);
    int tid = threadIdx.x, w = tid >> 5, lane = tid & 31;
    int row0 = blockIdx.x * 128;

    {
        const uint4* ah = (const uint4*)(g_Wbh + (size_t)(layer*8 + 3)*17408);
        const uint4* al = (const uint4*)(g_Wbl + (size_t)(layer*8 + 3)*17408);
        const uint4* bh = (const uint4*)(g_Wbh + (size_t)(layer*8 + 4)*17408);
        const uint4* bl = (const uint4*)(g_Wbl + (size_t)(layer*8 + 4)*17408);
        uint4* dah = (uint4*)(smc + 69632);
        uint4* dal = (uint4*)(smc + 104448);
        uint4* dbh = (uint4*)(smc + 139264);
        uint4* dbl = (uint4*)(smc + 174080);
        for (int i = tid; i < 2176; i += 512) {
            dah[i] = ah[i]; dal[i] = al[i]; dbh[i] = bh[i]; dbl[i] = bl[i];
        }
    }
    #pragma unroll
    for (int q = 0; q < 8; q++) {
        int idx = tid + q*512;
        int r = idx >> 5, c4 = (idx & 31)*4;
        float4 v = make_float4(0.f,0.f,0.f,0.f);
        if (row0 + r < Nn) v = *(const float4*)(g_feat + (size_t)(row0 + r)*128 + c4);
        unsigned h[4], l[4];
        split_bf16(v.x, h[0], l[0]); split_bf16(v.y, h[1], l[1]);
        split_bf16(v.z, h[2], l[2]); split_bf16(v.w, h[3], l[3]);
        unsigned off = (unsigned)(r*136 + c4)*2u;
        *(uint2*)(smc + off)         = make_uint2(h[0]|(h[1]<<16), h[2]|(h[3]<<16));
        *(uint2*)(smc + 34816 + off) = make_uint2(l[0]|(l[1]<<16), l[2]|(l[3]<<16));
    }
    __syncthreads();

    int m0 = (w & 7)*16, n0 = (w >> 3)*64;
    int rl = m0 + (lane >> 2);
    float acc[8][4];
    #pragma unroll
    for (int i = 0; i < 8; i++)
        #pragma unroll
        for (int j = 0; j < 4; j++) acc[i][j] = 0.f;
    hmma_gemm(sb, sb + 34816, sb + 69632, sb + 104448, m0, n0, lane, acc);
    #pragma unroll
    for (int s = 0; s < 8; s++) {
        int col = n0 + s*8 + (lane & 3)*2;
        int ra = row0 + rl, rb = ra + 8;
        if (ra < Nn) *(float2*)(g_featA + (size_t)ra*128 + col) = make_float2(acc[s][0], acc[s][1]);
        if (rb < Nn) *(float2*)(g_featA + (size_t)rb*128 + col) = make_float2(acc[s][2], acc[s][3]);
    }
    #pragma unroll
    for (int i = 0; i < 8; i++)
        #pragma unroll
        for (int j = 0; j < 4; j++) acc[i][j] = 0.f;
    hmma_gemm(sb, sb + 34816, sb + 139264, sb + 174080, m0, n0, lane, acc);
    #pragma unroll
    for (int s = 0; s < 8; s++) {
        int col = n0 + s*8 + (lane & 3)*2;
        int ra = row0 + rl, rb = ra + 8;
        if (ra < Nn) *(float2*)(g_featB + (size_t)ra*128 + col) = make_float2(acc[s][0], acc[s][1]);
        if (rb < Nn) *(float2*)(g_featB + (size_t)rb*128 + col) = make_float2(acc[s][2], acc[s][3]);
    }
}

// ============ node update via HMMA + fused featAB for next layer ============
// feat = silu(feat@W5 + (msum/deg)@W6 + b1) @ W7 + b2 ; if next>=0: featA/B = feat@Wa/Wb(next)
// Also zeroes msum after reading it.
#define NUM_SMEM 209920
__global__ void __launch_bounds__(512, 1)
nodeup_mma(const float* __restrict__ b1, const float* __restrict__ b2, int layer, int next) {
    extern __shared__ char smc[];
    unsigned sb = smem_u32(smc);
    float* bb = (float*)(smc + 208896);
    int tid = threadIdx.x, w = tid >> 5, lane = tid & 31;
    int row0 = blockIdx.x * 128;

    {
        const uint4* ah = (const uint4*)(g_Wbh + (size_t)(layer*8 + 5)*17408);
        const uint4* al = (const uint4*)(g_Wbl + (size_t)(layer*8 + 5)*17408);
        const uint4* bh = (const uint4*)(g_Wbh + (size_t)(layer*8 + 6)*17408);
        const uint4* bl = (const uint4*)(g_Wbl + (size_t)(layer*8 + 6)*17408);
        uint4* d1h = (uint4*)(smc + 69632);
        uint4* d1l = (uint4*)(smc + 104448);
        uint4* d2h = (uint4*)(smc + 139264);
        uint4* d2l = (uint4*)(smc + 174080);
        for (int i = tid; i < 2176; i += 512) {
            d1h[i] = ah[i]; d1l[i] = al[i]; d2h[i] = bh[i]; d2l[i] = bl[i];
        }
    }
    if (tid < 128) { bb[tid] = b1[tid]; bb[128 + tid] = b2[tid]; }
    #pragma unroll
    for (int q = 0; q < 8; q++) {
        int idx = tid + q*512;
        int r = idx >> 5, c4 = (idx & 31)*4;
        float4 v = make_float4(0.f,0.f,0.f,0.f);
        if (row0 + r < Nn) v = *(const float4*)(g_feat + (size_t)(row0 + r)*128 + c4);
        unsigned h[4], l[4];
        split_bf16(v.x, h[0], l[0]); split_bf16(v.y, h[1], l[1]);
        split_bf16(v.z, h[2], l[2]); split_bf16(v.w, h[3], l[3]);
        unsigned off = (unsigned)(r*136 + c4)*2u;
        *(uint2*)(smc + off)         = make_uint2(h[0]|(h[1]<<16), h[2]|(h[3]<<16));
        *(uint2*)(smc + 34816 + off) = make_uint2(l[0]|(l[1]<<16), l[2]|(l[3]<<16));
    }
    __syncthreads();

    int m0 = (w & 7)*16, n0 = (w >> 3)*64;
    int rl = m0 + (lane >> 2);
    float acc[8][4];
    #pragma unroll
    for (int i = 0; i < 8; i++)
        #pragma unroll
        for (int j = 0; j < 4; j++) acc[i][j] = 0.f;
    hmma_gemm(sb, sb + 34816, sb + 69632, sb + 104448, m0, n0, lane, acc);
    __syncthreads();

    {
        const uint4* ah = (const uint4*)(g_Wbh + (size_t)(layer*8 + 7)*17408);
        const uint4* al = (const uint4*)(g_Wbl + (size_t)(layer*8 + 7)*17408);
        uint4* d1h = (uint4*)(smc + 69632);
        uint4* d1l = (uint4*)(smc + 104448);
        for (int i = tid; i < 2176; i += 512) { d1h[i] = ah[i]; d1l[i] = al[i]; }
    }
    #pragma unroll
    for (int q = 0; q < 8; q++) {
        int idx = tid + q*512;
        int r = idx >> 5, c4 = (idx & 31)*4;
        float4 v = make_float4(0.f,0.f,0.f,0.f);
        if (row0 + r < Nn) {
            float* mp = g_msum + (size_t)(row0 + r)*128 + c4;
            v = *(const float4*)mp;
            *(float4*)mp = make_float4(0.f,0.f,0.f,0.f);   // zero for next layer
            float inv = 1.0f / fmaxf(g_deg[row0 + r], 1.0f);
            v.x *= inv; v.y *= inv; v.z *= inv; v.w *= inv;
        }
        unsigned h[4], l[4];
        split_bf16(v.x, h[0], l[0]); split_bf16(v.y, h[1], l[1]);
        split_bf16(v.z, h[2], l[2]); split_bf16(v.w, h[3], l[3]);
        unsigned off = (unsigned)(r*136 + c4)*2u;
        *(uint2*)(smc + off)         = make_uint2(h[0]|(h[1]<<16), h[2]|(h[3]<<16));
        *(uint2*)(smc + 34816 + off) = make_uint2(l[0]|(l[1]<<16), l[2]|(l[3]<<16));
    }
    __syncthreads();
    hmma_gemm(sb, sb + 34816, sb + 139264, sb + 174080, m0, n0, lane, acc);
    __syncthreads();

    // X = split(H)
    #pragma unroll
    for (int s = 0; s < 8; s++) {
        int col = n0 + s*8 + (lane & 3)*2;
        float v00 = silu_f(acc[s][0] + bb[col]);
        float v01 = silu_f(acc[s][1] + bb[col+1]);
        float v10 = silu_f(acc[s][2] + bb[col]);
        float v11 = silu_f(acc[s][3] + bb[col+1]);
        unsigned h0, l0, h1, l1;
        split_bf16(v00, h0, l0); split_bf16(v01, h1, l1);
        *(unsigned*)(smc + (rl*136 + col)*2)         = h0 | (h1 << 16);
        *(unsigned*)(smc + 34816 + (rl*136 + col)*2) = l0 | (l1 << 16);
        split_bf16(v10, h0, l0); split_bf16(v11, h1, l1);
        *(unsigned*)(smc + ((rl+8)*136 + col)*2)         = h0 | (h1 << 16);
        *(unsigned*)(smc + 34816 + ((rl+8)*136 + col)*2) = l0 | (l1 << 16);
    }
    __syncthreads();
    // GEMM3: newfeat = H @ W7 + b2
    #pragma unroll
    for (int i = 0; i < 8; i++)
        #pragma unroll
        for (int j = 0; j < 4; j++) acc[i][j] = 0.f;
    hmma_gemm(sb, sb + 34816, sb + 69632, sb + 104448, m0, n0, lane, acc);
    #pragma unroll
    for (int s = 0; s < 8; s++) {
        int col = n0 + s*8 + (lane & 3)*2;
        acc[s][0] += bb[128+col]; acc[s][1] += bb[128+col+1];
        acc[s][2] += bb[128+col]; acc[s][3] += bb[128+col+1];
        int ra = row0 + rl, rb = ra + 8;
        if (ra < Nn) *(float2*)(g_feat + (size_t)ra*128 + col) = make_float2(acc[s][0], acc[s][1]);
        if (rb < Nn) *(float2*)(g_feat + (size_t)rb*128 + col) = make_float2(acc[s][2], acc[s][3]);
    }
    if (next < 0) return;

    __syncthreads();   // GEMM3 reads of A/W1 done block-wide
    // load Wa(next)->W1, Wb(next)->W2 async while splitting newfeat into A
    {
        const char* ah = (const char*)(g_Wbh + (size_t)(next*8 + 3)*17408);
        const char* al = (const char*)(g_Wbl + (size_t)(next*8 + 3)*17408);
        const char* bh = (const char*)(g_Wbh + (size_t)(next*8 + 4)*17408);
        const char* bl = (const char*)(g_Wbl + (size_t)(next*8 + 4)*17408);
        for (int i = tid; i < 2176; i += 512) {
            asm volatile("cp.async.cg.shared.global [%0], [%1], 16;"
                :: "r"(sb + 69632u + (unsigned)i*16u), "l"(ah + (size_t)i*16) : "memory");
            asm volatile("cp.async.cg.shared.global [%0], [%1], 16;"
                :: "r"(sb + 104448u + (unsigned)i*16u), "l"(al + (size_t)i*16) : "memory");
            asm volatile("cp.async.cg.shared.global [%0], [%1], 16;"
                :: "r"(sb + 139264u + (unsigned)i*16u), "l"(bh + (size_t)i*16) : "memory");
            asm volatile("cp.async.cg.shared.global [%0], [%1], 16;"
                :: "r"(sb + 174080u + (unsigned)i*16u), "l"(bl + (size_t)i*16) : "memory");
        }
        asm volatile("cp.async.commit_group;" ::: "memory");
    }
    #pragma unroll
    for (int s = 0; s < 8; s++) {
        int col = n0 + s*8 + (lane & 3)*2;
        unsigned h0, l0, h1, l1;
        split_bf16(acc[s][0], h0, l0); split_bf16(acc[s][1], h1, l1);
        *(unsigned*)(smc + (rl*136 + col)*2)         = h0 | (h1 << 16);
        *(unsigned*)(smc + 34816 + (rl*136 + col)*2) = l0 | (l1 << 16);
        split_bf16(acc[s][2], h0, l0); split_bf16(acc[s][3], h1, l1);
        *(unsigned*)(smc + ((rl+8)*136 + col)*2)         = h0 | (h1 << 16);
        *(unsigned*)(smc + 34816 + ((rl+8)*136 + col)*2) = l0 | (l1 << 16);
    }
    asm volatile("cp.async.wait_group 0;" ::: "memory");
    __syncthreads();

    // GEMM4: featA
    #pragma unroll
    for (int i = 0; i < 8; i++)
        #pragma unroll
        for (int j = 0; j < 4; j++) acc[i][j] = 0.f;
    hmma_gemm(sb, sb + 34816, sb + 69632, sb + 104448, m0, n0, lane, acc);
    #pragma unroll
    for (int s = 0; s < 8; s++) {
        int col = n0 + s*8 + (lane & 3)*2;
        int ra = row0 + rl, rb = ra + 8;
        if (ra < Nn) *(float2*)(g_featA + (size_t)ra*128 + col) = make_float2(acc[s][0], acc[s][1]);
        if (rb < Nn) *(float2*)(g_featA + (size_t)rb*128 + col) = make_float2(acc[s][2], acc[s][3]);
    }
    // GEMM5: featB (A and W2 untouched since GEMM4)
    #pragma unroll
    for (int i = 0; i < 8; i++)
        #pragma unroll
        for (int j = 0; j < 4; j++) acc[i][j] = 0.f;
    hmma_gemm(sb, sb + 34816, sb + 139264, sb + 174080, m0, n0, lane, acc);
    #pragma unroll
    for (int s = 0; s < 8; s++) {
        int col = n0 + s*8 + (lane & 3)*2;
        int ra = row0 + rl, rb = ra + 8;
        if (ra < Nn) *(float2*)(g_featB + (size_t)ra*128 + col) = make_float2(acc[s][0], acc[s][1]);
        if (rb < Nn) *(float2*)(g_featB + (size_t)rb*128 + col) = make_float2(acc[s][2], acc[s][3]);
    }
}

// ============ FUSED edge kernel: h-build + m/p/s GEMMs + scatters ============
#define FU_SMEM 222720
__global__ void __launch_bounds__(512, 1)
edge_fused_mma(const float* __restrict__ bm2l,
               const float* __restrict__ Wm1tail, const float* __restrict__ bm1l,
               const float* __restrict__ bp1l, const float* __restrict__ Wp2l,
               const float* __restrict__ bp2l,
               const float* __restrict__ bs1l, const float* __restrict__ Ws2l,
               const float* __restrict__ bs2l, int layer) {
    extern __shared__ char smc[];
    unsigned sb = smem_u32(smc);
    float* m_s  = (float*)(smc + 139264);
    float* scal = (float*)(smc + 209408);
    float* bh   = (float*)(smc + 211456);
    float* bhp  = (float*)(smc + 211968);
    float* bhs  = (float*)(smc + 212480);
    float* w2p  = (float*)(smc + 212992);
    float* w2s  = (float*)(smc + 213504);
    float* pd   = (float*)(smc + 215040);
    int* ridx   = (int*)(smc + 219136);
    int* cidx   = (int*)(smc + 219648);
    float* wtl  = (float*)(smc + 220160);
    int tid = threadIdx.x, w = tid >> 5, lane = tid & 31;

    const char* Wm2h = (const char*)(g_Wbh + (size_t)(layer*8 + 0)*17408);
    const char* Wm2l = (const char*)(g_Wbl + (size_t)(layer*8 + 0)*17408);
    const char* Wp1h = (const char*)(g_Wbh + (size_t)(layer*8 + 1)*17408);
    const char* Wp1l = (const char*)(g_Wbl + (size_t)(layer*8 + 1)*17408);
    const char* Ws1h = (const char*)(g_Wbh + (size_t)(layer*8 + 2)*17408);
    const char* Ws1l = (const char*)(g_Wbl + (size_t)(layer*8 + 2)*17408);

    if (tid < 128) {
        bh[tid] = bm2l[tid]; bhp[tid] = bp1l[tid]; bhs[tid] = bs1l[tid];
        w2p[tid] = Wp2l[tid];
        w2s[tid*3+0] = Ws2l[tid*3+0]; w2s[tid*3+1] = Ws2l[tid*3+1]; w2s[tid*3+2] = Ws2l[tid*3+2];
    }
    for (int i = tid; i < 640; i += 512)
        wtl[i] = (i < 512) ? Wm1tail[i] : bm1l[i - 512];

    int m0 = (w & 7)*16, n0 = (w >> 3)*64;
    int chalf = w >> 3;
    int r0l = m0 + (lane >> 2), r1l = r0l + 8;

    for (int t = blockIdx.x; t < NT; t += gridDim.x) {
        int e0 = t*128;
        __syncthreads();
        for (int i = tid; i < 2176; i += 512) {
            asm volatile("cp.async.cg.shared.global [%0], [%1], 16;"
                :: "r"(sb + 69632u + (unsigned)i*16u), "l"(Wm2h + (size_t)i*16) : "memory");
            asm volatile("cp.async.cg.shared.global [%0], [%1], 16;"
                :: "r"(sb + 104448u + (unsigned)i*16u), "l"(Wm2l + (size_t)i*16) : "memory");
        }
        asm volatile("cp.async.commit_group;" ::: "memory");
        if (tid < 128) {
            int r = g_er[e0 + tid], c = g_ec[e0 + tid];
            ridx[tid] = r; cidx[tid] = c;
            float dp0 = g_pos[r*3+0] - g_pos[c*3+0];
            float dp1 = g_pos[r*3+1] - g_pos[c*3+1];
            float dp2 = g_pos[r*3+2] - g_pos[c*3+2];
            float ip2 = 0.f;
            #pragma unroll
            for (int q = 4; q < 9; q++) ip2 += g_sh[r*9+q]*g_sh[c*9+q];
            scal[tid*4+0] = dp0*dp0 + dp1*dp1 + dp2*dp2;
            scal[tid*4+1] = g_sh[r*9+0]*g_sh[c*9+0];
            scal[tid*4+2] = g_sh[r*9+1]*g_sh[c*9+1] + g_sh[r*9+2]*g_sh[c*9+2] + g_sh[r*9+3]*g_sh[c*9+3];
            scal[tid*4+3] = ip2;
        }
        __syncthreads();
        #pragma unroll
        for (int q = 0; q < 8; q++) {
            int idx = tid + q*512;
            int e = idx >> 5, c4 = (idx & 31)*4;
            int r = ridx[e], c = cidx[e];
            float4 fa = *(const float4*)(g_featA + (size_t)r*128 + c4);
            float4 fb = *(const float4*)(g_featB + (size_t)c*128 + c4);
            float d2 = scal[e*4+0], i0 = scal[e*4+1], i1 = scal[e*4+2], i2 = scal[e*4+3];
            float hv[4];
            hv[0] = silu_f(fa.x + fb.x + d2*wtl[c4+0] + i0*wtl[128+c4+0] + i1*wtl[256+c4+0] + i2*wtl[384+c4+0] + wtl[512+c4+0]);
            hv[1] = silu_f(fa.y + fb.y + d2*wtl[c4+1] + i0*wtl[128+c4+1] + i1*wtl[256+c4+1] + i2*wtl[384+c4+1] + wtl[512+c4+1]);
            hv[2] = silu_f(fa.z + fb.z + d2*wtl[c4+2] + i0*wtl[128+c4+2] + i1*wtl[256+c4+2] + i2*wtl[384+c4+2] + wtl[512+c4+2]);
            hv[3] = silu_f(fa.w + fb.w + d2*wtl[c4+3] + i0*wtl[128+c4+3] + i1*wtl[256+c4+3] + i2*wtl[384+c4+3] + wtl[512+c4+3]);
            unsigned h[4], l[4];
            #pragma unroll
            for (int j = 0; j < 4; j++) split_bf16(hv[j], h[j], l[j]);
            unsigned off = (unsigned)(e*136 + c4)*2u;
            *(uint2*)(smc + off)         = make_uint2(h[0]|(h[1]<<16), h[2]|(h[3]<<16));
            *(uint2*)(smc + 34816 + off) = make_uint2(l[0]|(l[1]<<16), l[2]|(l[3]<<16));
        }
        asm volatile("cp.async.wait_group 0;" ::: "memory");
        __syncthreads();

        float acc[8][4];
        #pragma unroll
        for (int i = 0; i < 8; i++)
            #pragma unroll
            for (int j = 0; j < 4; j++) acc[i][j] = 0.f;
        hmma_gemm(sb, sb + 34816, sb + 69632, sb + 104448, m0, n0, lane, acc);
        __syncthreads();

        for (int i = tid; i < 2176; i += 512) {
            asm volatile("cp.async.cg.shared.global [%0], [%1], 16;"
                :: "r"(sb + 69632u + (unsigned)i*16u), "l"(Wp1h + (size_t)i*16) : "memory");
            asm volatile("cp.async.cg.shared.global [%0], [%1], 16;"
                :: "r"(sb + 104448u + (unsigned)i*16u), "l"(Wp1l + (size_t)i*16) : "memory");
        }
        asm volatile("cp.async.commit_group;" ::: "memory");
        #pragma unroll
        for (int s = 0; s < 8; s++) {
            int col = n0 + s*8 + (lane & 3)*2;
            float v00 = silu_f(acc[s][0] + bh[col]);
            float v01 = silu_f(acc[s][1] + bh[col+1]);
            float v10 = silu_f(acc[s][2] + bh[col]);
            float v11 = silu_f(acc[s][3] + bh[col+1]);
            m_s[r0l*137 + col]     = v00;
            m_s[r0l*137 + col + 1] = v01;
            m_s[r1l*137 + col]     = v10;
            m_s[r1l*137 + col + 1] = v11;
            unsigned h0, l0, h1, l1;
            split_bf16(v00, h0, l0); split_bf16(v01, h1, l1);
            *(unsigned*)(smc + (r0l*136 + col)*2)         = h0 | (h1 << 16);
            *(unsigned*)(smc + 34816 + (r0l*136 + col)*2) = l0 | (l1 << 16);
            split_bf16(v10, h0, l0); split_bf16(v11, h1, l1);
            *(unsigned*)(smc + (r1l*136 + col)*2)         = h0 | (h1 << 16);
            *(unsigned*)(smc + 34816 + (r1l*136 + col)*2) = l0 | (l1 << 16);
        }
        asm volatile("cp.async.wait_group 0;" ::: "memory");
        __syncthreads();

        float accp[8][4];
        #pragma unroll
        for (int i = 0; i < 8; i++)
            #pragma unroll
            for (int j = 0; j < 4; j++) accp[i][j] = 0.f;
        hmma_gemm(sb, sb + 34816, sb + 69632, sb + 104448, m0, n0, lane, accp);
        __syncthreads();

        for (int i = tid; i < 2176; i += 512) {
            asm volatile("cp.async.cg.shared.global [%0], [%1], 16;"
                :: "r"(sb + 69632u + (unsigned)i*16u), "l"(Ws1h + (size_t)i*16) : "memory");
            asm volatile("cp.async.cg.shared.global [%0], [%1], 16;"
                :: "r"(sb + 104448u + (unsigned)i*16u), "l"(Ws1l + (size_t)i*16) : "memory");
        }
        asm volatile("cp.async.commit_group;" ::: "memory");
        {
            float pr0 = 0.f, pr1 = 0.f;
            #pragma unroll
            for (int s = 0; s < 8; s++) {
                int col = n0 + s*8 + (lane & 3)*2;
                pr0 = fmaf(silu_f(accp[s][0] + bhp[col]),   w2p[col],
                      fmaf(silu_f(accp[s][1] + bhp[col+1]), w2p[col+1], pr0));
                pr1 = fmaf(silu_f(accp[s][2] + bhp[col]),   w2p[col],
                      fmaf(silu_f(accp[s][3] + bhp[col+1]), w2p[col+1], pr1));
            }
            #pragma unroll
            for (int off = 1; off <= 2; off <<= 1) {
                pr0 += __shfl_xor_sync(0xffffffffu, pr0, off);
                pr1 += __shfl_xor_sync(0xffffffffu, pr1, off);
            }
            if ((lane & 3) == 0) {
                pd[chalf*512 + r0l*4 + 0] = pr0;
                pd[chalf*512 + r1l*4 + 0] = pr1;
            }
        }
        asm volatile("cp.async.wait_group 0;" ::: "memory");
        __syncthreads();

        float accs[8][4];
        #pragma unroll
        for (int i = 0; i < 8; i++)
            #pragma unroll
            for (int j = 0; j < 4; j++) accs[i][j] = 0.f;
        hmma_gemm(sb, sb + 34816, sb + 69632, sb + 104448, m0, n0, lane, accs);
        {
            float s0r0 = 0.f, s1r0 = 0.f, s2r0 = 0.f;
            float s0r1 = 0.f, s1r1 = 0.f, s2r1 = 0.f;
            #pragma unroll
            for (int s = 0; s < 8; s++) {
                int col = n0 + s*8 + (lane & 3)*2;
                float g00 = silu_f(accs[s][0] + bhs[col]);
                float g01 = silu_f(accs[s][1] + bhs[col+1]);
                float g10 = silu_f(accs[s][2] + bhs[col]);
                float g11 = silu_f(accs[s][3] + bhs[col+1]);
                s0r0 = fmaf(g00, w2s[col*3+0], fmaf(g01, w2s[(col+1)*3+0], s0r0));
                s1r0 = fmaf(g00, w2s[col*3+1], fmaf(g01, w2s[(col+1)*3+1], s1r0));
                s2r0 = fmaf(g00, w2s[col*3+2], fmaf(g01, w2s[(col+1)*3+2], s2r0));
                s0r1 = fmaf(g10, w2s[col*3+0], fmaf(g11, w2s[(col+1)*3+0], s0r1));
                s1r1 = fmaf(g10, w2s[col*3+1], fmaf(g11, w2s[(col+1)*3+1], s1r1));
                s2r1 = fmaf(g10, w2s[col*3+2], fmaf(g11, w2s[(col+1)*3+2], s2r1));
            }
            #pragma unroll
            for (int off = 1; off <= 2; off <<= 1) {
                s0r0 += __shfl_xor_sync(0xffffffffu, s0r0, off);
                s1r0 += __shfl_xor_sync(0xffffffffu, s1r0, off);
                s2r0 += __shfl_xor_sync(0xffffffffu, s2r0, off);
                s0r1 += __shfl_xor_sync(0xffffffffu, s0r1, off);
                s1r1 += __shfl_xor_sync(0xffffffffu, s1r1, off);
                s2r1 += __shfl_xor_sync(0xffffffffu, s2r1, off);
            }
            if ((lane & 3) == 0) {
                float* p0 = pd + chalf*512 + r0l*4;
                p0[1] = s0r0; p0[2] = s1r0; p0[3] = s2r0;
                float* p1 = pd + chalf*512 + r1l*4;
                p1[1] = s0r1; p1[2] = s1r1; p1[3] = s2r1;
            }
        }
        __syncthreads();
        if (tid < 128) {
            int r = ridx[tid], c = cidx[tid];
            float psc = pd[tid*4+0] + pd[512 + tid*4+0] + bp2l[0];
            float s0  = pd[tid*4+1] + pd[512 + tid*4+1] + bs2l[0];
            float s1  = pd[tid*4+2] + pd[512 + tid*4+2] + bs2l[1];
            float s2  = pd[tid*4+3] + pd[512 + tid*4+3] + bs2l[2];
            float dp0 = g_pos[r*3+0] - g_pos[c*3+0];
            float dp1 = g_pos[r*3+1] - g_pos[c*3+1];
            float dp2 = g_pos[r*3+2] - g_pos[c*3+2];
            atomicAdd(&g_psum[r*3+0], dp0*psc);
            atomicAdd(&g_psum[r*3+1], dp1*psc);
            atomicAdd(&g_psum[r*3+2], dp2*psc);
            #pragma unroll
            for (int q = 0; q < 9; q++) {
                float diff = g_sh[r*9+q] - g_sh[c*9+q];
                atomicAdd(&g_ssum[r*9+q], diff * ((q == 0) ? s0 : (q < 4) ? s1 : s2));
            }
        }
        {
            int c = tid & 127, seg = tid >> 7;
            int eb = seg*32;
            float agg = 0.f;
            int ar = ridx[eb];
            for (int e = eb; e < eb + 32; e++) {
                float v = m_s[e*137 + c];
                int r = ridx[e];
                if (r != ar) { atomicAdd(&g_msum[(size_t)ar*128 + c], agg); agg = v; ar = r; }
                else agg += v;
            }
            atomicAdd(&g_msum[(size_t)ar*128 + c], agg);
        }
    }
}

// posh also zeroes psum/ssum for the next layer
__global__ void posh_kernel() {
    int i = blockIdx.x*256 + threadIdx.x;
    if (i >= Nn) return;
    float inv = 1.0f / fmaxf(g_deg[i], 1.0f);
    #pragma unroll
    for (int q = 0; q < 3; q++) {
        g_pos[i*3+q] += g_psum[i*3+q]*inv;
        g_psum[i*3+q] = 0.0f;
    }
    #pragma unroll
    for (int q = 0; q < 9; q++) {
        g_sh[i*9+q] += g_ssum[i*9+q]*inv;
        g_ssum[i*9+q] = 0.0f;
    }
}
__global__ void pool_kernel(const int* __restrict__ batch) {
    int idx = blockIdx.x*256 + threadIdx.x;
    if (idx >= Nn*140) return;
    int i = idx / 140, c = idx % 140;
    float v;
    if (c < 128)      v = g_feat[(size_t)i*128 + c];
    else if (c < 131) v = g_pos[i*3 + (c - 128)];
    else              v = g_sh[i*9 + (c - 131)];
    atomicAdd(&g_pool[batch[i]*140 + c], v);
}
__global__ void pred_kernel(const float* __restrict__ Wpred, const float* __restrict__ bpred,
                            float* __restrict__ out) {
    int g = blockIdx.x, lane = threadIdx.x;
    float s = 0.f;
    for (int c = lane; c < 140; c += 32)
        s = fmaf(g_pool[g*140 + c], Wpred[c], s);
    #pragma unroll
    for (int off = 16; off > 0; off >>= 1)
        s += __shfl_xor_sync(0xffffffffu, s, off);
    if (lane == 0) out[g] = s + bpred[0];
}

extern "C" void kernel_launch(void* const* d_in, const int* in_sizes, int n_in,
                              void* d_out, int out_size) {
    const int*   atoms = (const int*)d_in[0];
    const int*   ei    = (const int*)d_in[1];
    const int*   batch = (const int*)d_in[2];
    const float* pos   = (const float*)d_in[3];
    const float* emb   = (const float*)d_in[4];
    const float* Wsi1  = (const float*)d_in[5];  const float* bsi1  = (const float*)d_in[6];
    const float* Wsi2  = (const float*)d_in[7];  const float* bsi2  = (const float*)d_in[8];
    const float* WsiC1 = (const float*)d_in[9];  const float* bsiC1 = (const float*)d_in[10];
    const float* WsiC2 = (const float*)d_in[11]; const float* bsiC2 = (const float*)d_in[12];
    const float* Wm1   = (const float*)d_in[13]; const float* bm1   = (const float*)d_in[14];
    const float* Wm2   = (const float*)d_in[15]; const float* bm2   = (const float*)d_in[16];
    const float* Wp1   = (const float*)d_in[17]; const float* bp1   = (const float*)d_in[18];
    const float* Wp2   = (const float*)d_in[19]; const float* bp2   = (const float*)d_in[20];
    const float* Wn1   = (const float*)d_in[21]; const float* bn1   = (const float*)d_in[22];
    const float* Wn2   = (const float*)d_in[23]; const float* bn2   = (const float*)d_in[24];
    const float* Ws1   = (const float*)d_in[25]; const float* bs1   = (const float*)d_in[26];
    const float* Ws2   = (const float*)d_in[27]; const float* bs2   = (const float*)d_in[28];
    const float* Wpred = (const float*)d_in[29]; const float* bpred = (const float*)d_in[30];
    float* out = (float*)d_out;

    cudaFuncSetAttribute(featab_mma, cudaFuncAttributeMaxDynamicSharedMemorySize, FABM_SMEM);
    cudaFuncSetAttribute(nodeup_mma, cudaFuncAttributeMaxDynamicSharedMemorySize, NUM_SMEM);
    cudaFuncSetAttribute(edge_fused_mma, cudaFuncAttributeMaxDynamicSharedMemorySize, FU_SMEM);

    void *p_msum, *p_psum, *p_ssum, *p_deg, *p_com, *p_cnt, *p_pool, *p_pos, *p_cur;
    cudaGetSymbolAddress(&p_msum, g_msum);
    cudaGetSymbolAddress(&p_psum, g_psum);
    cudaGetSymbolAddress(&p_ssum, g_ssum);
    cudaGetSymbolAddress(&p_deg,  g_deg);
    cudaGetSymbolAddress(&p_com,  g_com);
    cudaGetSymbolAddress(&p_cnt,  g_cnt);
    cudaGetSymbolAddress(&p_pool, g_pool);
    cudaGetSymbolAddress(&p_pos,  g_pos);
    cudaGetSymbolAddress(&p_cur,  g_cursor);

    cudaMemsetAsync(p_deg,  0, Nn*4, 0);
    cudaMemsetAsync(p_com,  0, Gg*3*4, 0);
    cudaMemsetAsync(p_cnt,  0, Gg*4, 0);
    cudaMemsetAsync(p_ssum, 0, Nn*9*4, 0);
    cudaMemsetAsync(p_psum, 0, Nn*3*4, 0);
    cudaMemsetAsync(p_msum, 0, (size_t)Nn*128*4, 0);
    cudaMemsetAsync(p_pool, 0, Gg*140*4, 0);
    cudaMemsetAsync(p_cur,  0, Nn*4, 0);
    cudaMemcpyAsync(p_pos, pos, Nn*3*4, cudaMemcpyDeviceToDevice, 0);

    wprep_kernel<<<40, 256>>>(Wm2, Wp1, Ws1, Wm1, Wn1, Wn2);
    node_init_kernel<<<(Nn*128)/256, 256>>>(atoms, emb);
    com_kernel<<<(Nn + 255)/256, 256>>>(batch);
    deg_kernel<<<(Ee + 255)/256, 256>>>(ei);
    scan_kernel<<<1, 256>>>();
    sortscatter_kernel<<<(Ee + 255)/256, 256>>>(ei);
    vocab_kernel<<<10, 128>>>(emb, Wsi1, WsiC1, bsiC1, WsiC2, bsiC2);
    edge_init_kernel<<<Ee/8, 256>>>(atoms, Wsi1, bsi1, Wsi2, bsi2);
    sh_init_kernel<<<(Nn + 255)/256, 256>>>(atoms, batch);

    int gridNM = (Nn + 127)/128;   // 79

    featab_mma<<<gridNM, 512, FABM_SMEM>>>(0);

    for (int l = 0; l < Ll; l++) {
        edge_fused_mma<<<148, 512, FU_SMEM>>>(
            bm2 + l*128,
            Wm1 + ((size_t)l*260 + 256)*128, bm1 + l*128,
            bp1 + l*128, Wp2 + l*128, bp2 + l,
            bs1 + l*128, Ws2 + l*384, bs2 + l*3, l);

        posh_kernel<<<(Nn + 255)/256, 256>>>();

        nodeup_mma<<<gridNM, 512, NUM_SMEM>>>(bn1 + l*128, bn2 + l*128, l,
                                              (l + 1 < Ll) ? (l + 1) : -1);
    }

    pool_kernel<<<(Nn*140 + 255)/256, 256>>>(batch);
    pred_kernel<<<Gg, 32>>>(Wpred, bpred, out);
}

// round 14
// speedup vs baseline: 1.8536x; 1.0037x over previous
#include <cuda_runtime.h>
#include <cuda_bf16.h>
#include <cstdint>
#include <math.h>

#define Nn 10000
#define Ee 160000
#define Gg 100
#define Ll 5
#define NT 1250   // 128-edge tiles

typedef unsigned long long u64;
typedef unsigned short ush;

__device__ float g_feat [Nn*128];
__device__ float g_featA[Nn*128];
__device__ float g_featB[Nn*128];
__device__ float g_sh   [Nn*9];
__device__ float g_pos  [Nn*3];
__device__ float g_msum [Nn*128];
__device__ float g_psum [Nn*3];
__device__ float g_ssum [Nn*9];
__device__ float g_deg  [Nn];
__device__ float g_com  [Gg*3];
__device__ float g_cnt  [Gg];
__device__ float g_P1   [10*128];
__device__ float g_P2   [10*128];
__device__ float g_cmsg [10];
__device__ float g_pool [Gg*140];
__device__ int   g_off  [Nn];
__device__ int   g_cursor[Nn];
__device__ int   g_er   [Ee];
__device__ int   g_ec   [Ee];
__device__ ush   g_Wbh [40*17408];          // [l*8+slot][n*136+k] hi
__device__ ush   g_Wbl [40*17408];          // lo

__device__ __forceinline__ float silu_f(float x) { return x / (1.0f + __expf(-x)); }

__device__ __forceinline__ void sph2(float vx, float vy, float vz, float* o) {
    const float S3 = 1.7320508075688772f, HS3 = 0.8660254037844386f;
    float r = sqrtf(vx*vx + vy*vy + vz*vz);
    float inv = 1.0f / fmaxf(r, 1e-12f);
    float x = vx*inv, y = vy*inv, z = vz*inv;
    o[0] = S3*x*z; o[1] = S3*x*y; o[2] = y*y - 0.5f*(x*x + z*z);
    o[3] = S3*y*z; o[4] = HS3*(z*z - x*x);
}

// ---- HMMA helpers ----
__device__ __forceinline__ unsigned smem_u32(const void* p) {
    unsigned a; asm("{ .reg .u64 t; cvta.to.shared.u64 t, %1; cvt.u32.u64 %0, t; }" : "=r"(a) : "l"(p));
    return a;
}
__device__ __forceinline__ void ldsm4(unsigned addr, unsigned* r) {
    asm volatile("ldmatrix.sync.aligned.m8n8.x4.shared.b16 {%0,%1,%2,%3}, [%4];"
        : "=r"(r[0]), "=r"(r[1]), "=r"(r[2]), "=r"(r[3]) : "r"(addr));
}
__device__ __forceinline__ void mma_bf16(float* d, const unsigned* a, unsigned b0, unsigned b1) {
    asm volatile("mma.sync.aligned.m16n8k16.row.col.f32.bf16.bf16.f32 "
        "{%0,%1,%2,%3},{%4,%5,%6,%7},{%8,%9},{%0,%1,%2,%3};"
        : "+f"(d[0]), "+f"(d[1]), "+f"(d[2]), "+f"(d[3])
        : "r"(a[0]), "r"(a[1]), "r"(a[2]), "r"(a[3]), "r"(b0), "r"(b1));
}
__device__ __forceinline__ void split_bf16(float v, unsigned& h, unsigned& l) {
    __nv_bfloat16 hb = __float2bfloat16(v);
    h = (unsigned)__bfloat16_as_ushort(hb);
    l = (unsigned)__bfloat16_as_ushort(__float2bfloat16(v - __bfloat162float(hb)));
}

// split-bf16 GEMM core: rows m0..+15 x cols n0..+63, K=128; A/B ush stride 136 (272 B)
__device__ __forceinline__ void hmma_gemm(unsigned aH, unsigned aL, unsigned bH, unsigned bL,
                                          int m0, int n0, int lane, float acc[8][4]) {
    unsigned aoff = (unsigned)((m0 + (lane & 15))*272 + (lane >> 4)*16);
    unsigned boff = (unsigned)((n0 + (lane & 15))*272 + (lane >> 4)*16);
    #pragma unroll
    for (int kk = 0; kk < 8; kk++) {
        unsigned kb = kk*32;
        unsigned Ah[4], Al[4];
        ldsm4(aH + aoff + kb, Ah);
        ldsm4(aL + aoff + kb, Al);
        #pragma unroll
        for (int t = 0; t < 4; t++) {
            unsigned bo = boff + t*16*272 + kb;
            unsigned Bh[4], Bl[4];
            ldsm4(bH + bo, Bh);
            ldsm4(bL + bo, Bl);
            mma_bf16(acc[2*t],   Ah, Bh[0], Bh[2]);
            mma_bf16(acc[2*t],   Ah, Bl[0], Bl[2]);
            mma_bf16(acc[2*t],   Al, Bh[0], Bh[2]);
            mma_bf16(acc[2*t+1], Ah, Bh[1], Bh[3]);
            mma_bf16(acc[2*t+1], Ah, Bl[1], Bl[3]);
            mma_bf16(acc[2*t+1], Al, Bh[1], Bh[3]);
        }
    }
}

// weights -> split-bf16 [n][k] stride-136 tiles
// slot: 0 Wm2, 1 Wp1, 2 Ws1, 3 Wa, 4 Wb, 5 W5, 6 W6, 7 W7
__global__ void wprep_kernel(const float* __restrict__ Wm2, const float* __restrict__ Wp1,
                             const float* __restrict__ Ws1, const float* __restrict__ Wm1,
                             const float* __restrict__ Wn1, const float* __restrict__ Wn2) {
    int bid = blockIdx.x, l = bid >> 3, slot = bid & 7;
    const float* src;
    switch (slot) {
        case 0: src = Wm2 + (size_t)l*16384;              break;
        case 1: src = Wp1 + (size_t)l*16384;              break;
        case 2: src = Ws1 + (size_t)l*16384;              break;
        case 3: src = Wm1 + (size_t)l*260*128;            break;
        case 4: src = Wm1 + ((size_t)l*260 + 128)*128;    break;
        case 5: src = Wn1 + (size_t)l*256*128;            break;
        case 6: src = Wn1 + ((size_t)l*256 + 128)*128;    break;
        default:src = Wn2 + (size_t)l*16384;              break;
    }
    ush* dh = g_Wbh + (size_t)bid*17408;
    ush* dl = g_Wbl + (size_t)bid*17408;
    for (int o = threadIdx.x; o < 16384; o += 256) {
        int k = o >> 7, n = o & 127;
        unsigned h, lo;
        split_bf16(src[k*128 + n], h, lo);
        dh[n*136 + k] = (ush)h;
        dl[n*136 + k] = (ush)lo;
    }
}

// ---- init kernels ----
__global__ void node_init_kernel(const int* __restrict__ atoms, const float* __restrict__ emb) {
    int idx = blockIdx.x*256 + threadIdx.x;
    g_feat[idx] = emb[atoms[idx >> 7]*128 + (idx & 127)];
}
__global__ void com_kernel(const int* __restrict__ batch) {
    int i = blockIdx.x*256 + threadIdx.x;
    if (i >= Nn) return;
    int b = batch[i];
    atomicAdd(&g_com[b*3+0], g_pos[i*3+0]);
    atomicAdd(&g_com[b*3+1], g_pos[i*3+1]);
    atomicAdd(&g_com[b*3+2], g_pos[i*3+2]);
    atomicAdd(&g_cnt[b], 1.0f);
}
__global__ void deg_kernel(const int* __restrict__ ei) {
    int e = blockIdx.x*256 + threadIdx.x;
    if (e < Ee) atomicAdd(&g_deg[ei[e]], 1.0f);
}
__global__ void scan_kernel() {
    __shared__ int part[256];
    int tid = threadIdx.x;
    int lo = tid*40, hi = (lo + 40 < Nn) ? lo + 40 : Nn;
    int s = 0;
    for (int i = lo; i < hi; i++) s += (int)g_deg[i];
    part[tid] = s;
    __syncthreads();
    for (int off = 1; off < 256; off <<= 1) {
        int v = part[tid] + ((tid >= off) ? part[tid - off] : 0);
        __syncthreads(); part[tid] = v; __syncthreads();
    }
    int base = (tid > 0) ? part[tid - 1] : 0;
    for (int i = lo; i < hi; i++) { g_off[i] = base; base += (int)g_deg[i]; }
}
__global__ void sortscatter_kernel(const int* __restrict__ ei) {
    int e = blockIdx.x*256 + threadIdx.x;
    if (e >= Ee) return;
    int r = ei[e], c = ei[Ee + e];
    int p = g_off[r] + atomicAdd(&g_cursor[r], 1);
    g_er[p] = r; g_ec[p] = c;
}
__global__ void vocab_kernel(const float* __restrict__ emb, const float* __restrict__ Wsi1,
                             const float* __restrict__ WsiC1, const float* __restrict__ bsiC1,
                             const float* __restrict__ WsiC2, const float* __restrict__ bsiC2) {
    __shared__ float es[128], redv[128];
    int v = blockIdx.x, j = threadIdx.x;
    es[j] = emb[v*128 + j];
    __syncthreads();
    float p1 = 0.f, p2 = 0.f, hc = 0.f;
    for (int k = 0; k < 128; k++) {
        float e = es[k];
        p1 = fmaf(e, Wsi1[(1 + k)*128 + j], p1);
        p2 = fmaf(e, Wsi1[(129 + k)*128 + j], p2);
        hc = fmaf(e, WsiC1[k*128 + j], hc);
    }
    g_P1[v*128 + j] = p1; g_P2[v*128 + j] = p2;
    redv[j] = silu_f(hc + bsiC1[j]) * WsiC2[j*3 + 2];
    __syncthreads();
    for (int s = 64; s > 0; s >>= 1) {
        if (j < s) redv[j] += redv[j + s];
        __syncthreads();
    }
    if (j == 0) g_cmsg[v] = redv[0] + bsiC2[2];
}
__global__ void edge_init_kernel(const int* __restrict__ atoms,
                                 const float* __restrict__ Wsi1, const float* __restrict__ bsi1,
                                 const float* __restrict__ Wsi2, const float* __restrict__ bsi2) {
    int e = blockIdx.x*8 + (threadIdx.x >> 5);
    int lane = threadIdx.x & 31;
    int r = g_er[e], c = g_ec[e];
    float dp0 = g_pos[r*3+0] - g_pos[c*3+0];
    float dp1 = g_pos[r*3+1] - g_pos[c*3+1];
    float dp2 = g_pos[r*3+2] - g_pos[c*3+2];
    float dist = sqrtf(dp0*dp0 + dp1*dp1 + dp2*dp2);
    int ar = atoms[r], ac = atoms[c];
    float partial = 0.f;
    #pragma unroll
    for (int q = 0; q < 4; q++) {
        int d = lane + q*32;
        partial = fmaf(silu_f(dist*Wsi1[d] + g_P1[ar*128 + d] + g_P2[ac*128 + d] + bsi1[d]),
                       Wsi2[d*3 + 2], partial);
    }
    #pragma unroll
    for (int off = 16; off > 0; off >>= 1)
        partial += __shfl_xor_sync(0xffffffffu, partial, off);
    if (lane == 0) {
        float msg2 = partial + bsi2[2];
        float y2[5];
        sph2(dp0, dp1, dp2, y2);
        #pragma unroll
        for (int q = 0; q < 5; q++)
            atomicAdd(&g_ssum[r*9 + 4 + q], y2[q]*msg2);
    }
}
// sh_init also clears ssum for the first layer's edge pass
__global__ void sh_init_kernel(const int* __restrict__ atoms, const int* __restrict__ batch) {
    int i = blockIdx.x*256 + threadIdx.x;
    if (i >= Nn) return;
    float dg = fmaxf(g_deg[i], 1.0f);
    int b = batch[i];
    float cn = fmaxf(g_cnt[b], 1.0f);
    float y2[5];
    sph2(g_pos[i*3+0] - g_com[b*3+0]/cn, g_pos[i*3+1] - g_com[b*3+1]/cn,
         g_pos[i*3+2] - g_com[b*3+2]/cn, y2);
    float cm = g_cmsg[atoms[i]];
    #pragma unroll
    for (int q = 0; q < 4; q++) g_sh[i*9 + q] = 0.0f;
    #pragma unroll
    for (int q = 0; q < 5; q++)
        g_sh[i*9 + 4 + q] = g_ssum[i*9 + 4 + q]/dg + cm*y2[q];
    #pragma unroll
    for (int q = 0; q < 9; q++) g_ssum[i*9 + q] = 0.0f;
}

// ============ featAB via HMMA (layer 0 only) ============
#define FABM_SMEM 208896
__global__ void __launch_bounds__(512, 1)
featab_mma(int layer) {
    extern __shared__ char smc[];
    unsigned sb = smem_u32(smc);
    int tid = threadIdx.x, w = tid >> 5, lane = tid & 31;
    int row0 = blockIdx.x * 128;

    {
        const uint4* ah = (const uint4*)(g_Wbh + (size_t)(layer*8 + 3)*17408);
        const uint4* al = (const uint4*)(g_Wbl + (size_t)(layer*8 + 3)*17408);
        const uint4* bh = (const uint4*)(g_Wbh + (size_t)(layer*8 + 4)*17408);
        const uint4* bl = (const uint4*)(g_Wbl + (size_t)(layer*8 + 4)*17408);
        uint4* dah = (uint4*)(smc + 69632);
        uint4* dal = (uint4*)(smc + 104448);
        uint4* dbh = (uint4*)(smc + 139264);
        uint4* dbl = (uint4*)(smc + 174080);
        for (int i = tid; i < 2176; i += 512) {
            dah[i] = ah[i]; dal[i] = al[i]; dbh[i] = bh[i]; dbl[i] = bl[i];
        }
    }
    #pragma unroll
    for (int q = 0; q < 8; q++) {
        int idx = tid + q*512;
        int r = idx >> 5, c4 = (idx & 31)*4;
        float4 v = make_float4(0.f,0.f,0.f,0.f);
        if (row0 + r < Nn) v = *(const float4*)(g_feat + (size_t)(row0 + r)*128 + c4);
        unsigned h[4], l[4];
        split_bf16(v.x, h[0], l[0]); split_bf16(v.y, h[1], l[1]);
        split_bf16(v.z, h[2], l[2]); split_bf16(v.w, h[3], l[3]);
        unsigned off = (unsigned)(r*136 + c4)*2u;
        *(uint2*)(smc + off)         = make_uint2(h[0]|(h[1]<<16), h[2]|(h[3]<<16));
        *(uint2*)(smc + 34816 + off) = make_uint2(l[0]|(l[1]<<16), l[2]|(l[3]<<16));
    }
    __syncthreads();

    int m0 = (w & 7)*16, n0 = (w >> 3)*64;
    int rl = m0 + (lane >> 2);
    float acc[8][4];
    #pragma unroll
    for (int i = 0; i < 8; i++)
        #pragma unroll
        for (int j = 0; j < 4; j++) acc[i][j] = 0.f;
    hmma_gemm(sb, sb + 34816, sb + 69632, sb + 104448, m0, n0, lane, acc);
    #pragma unroll
    for (int s = 0; s < 8; s++) {
        int col = n0 + s*8 + (lane & 3)*2;
        int ra = row0 + rl, rb = ra + 8;
        if (ra < Nn) *(float2*)(g_featA + (size_t)ra*128 + col) = make_float2(acc[s][0], acc[s][1]);
        if (rb < Nn) *(float2*)(g_featA + (size_t)rb*128 + col) = make_float2(acc[s][2], acc[s][3]);
    }
    #pragma unroll
    for (int i = 0; i < 8; i++)
        #pragma unroll
        for (int j = 0; j < 4; j++) acc[i][j] = 0.f;
    hmma_gemm(sb, sb + 34816, sb + 139264, sb + 174080, m0, n0, lane, acc);
    #pragma unroll
    for (int s = 0; s < 8; s++) {
        int col = n0 + s*8 + (lane & 3)*2;
        int ra = row0 + rl, rb = ra + 8;
        if (ra < Nn) *(float2*)(g_featB + (size_t)ra*128 + col) = make_float2(acc[s][0], acc[s][1]);
        if (rb < Nn) *(float2*)(g_featB + (size_t)rb*128 + col) = make_float2(acc[s][2], acc[s][3]);
    }
}

// ============ node update via HMMA + fused featAB for next layer ============
#define NUM_SMEM 209920
__global__ void __launch_bounds__(512, 1)
nodeup_mma(const float* __restrict__ b1, const float* __restrict__ b2, int layer, int next) {
    extern __shared__ char smc[];
    unsigned sb = smem_u32(smc);
    float* bb = (float*)(smc + 208896);
    int tid = threadIdx.x, w = tid >> 5, lane = tid & 31;
    int row0 = blockIdx.x * 128;

    {
        const uint4* ah = (const uint4*)(g_Wbh + (size_t)(layer*8 + 5)*17408);
        const uint4* al = (const uint4*)(g_Wbl + (size_t)(layer*8 + 5)*17408);
        const uint4* bh = (const uint4*)(g_Wbh + (size_t)(layer*8 + 6)*17408);
        const uint4* bl = (const uint4*)(g_Wbl + (size_t)(layer*8 + 6)*17408);
        uint4* d1h = (uint4*)(smc + 69632);
        uint4* d1l = (uint4*)(smc + 104448);
        uint4* d2h = (uint4*)(smc + 139264);
        uint4* d2l = (uint4*)(smc + 174080);
        for (int i = tid; i < 2176; i += 512) {
            d1h[i] = ah[i]; d1l[i] = al[i]; d2h[i] = bh[i]; d2l[i] = bl[i];
        }
    }
    if (tid < 128) { bb[tid] = b1[tid]; bb[128 + tid] = b2[tid]; }
    #pragma unroll
    for (int q = 0; q < 8; q++) {
        int idx = tid + q*512;
        int r = idx >> 5, c4 = (idx & 31)*4;
        float4 v = make_float4(0.f,0.f,0.f,0.f);
        if (row0 + r < Nn) v = *(const float4*)(g_feat + (size_t)(row0 + r)*128 + c4);
        unsigned h[4], l[4];
        split_bf16(v.x, h[0], l[0]); split_bf16(v.y, h[1], l[1]);
        split_bf16(v.z, h[2], l[2]); split_bf16(v.w, h[3], l[3]);
        unsigned off = (unsigned)(r*136 + c4)*2u;
        *(uint2*)(smc + off)         = make_uint2(h[0]|(h[1]<<16), h[2]|(h[3]<<16));
        *(uint2*)(smc + 34816 + off) = make_uint2(l[0]|(l[1]<<16), l[2]|(l[3]<<16));
    }
    __syncthreads();

    int m0 = (w & 7)*16, n0 = (w >> 3)*64;
    int rl = m0 + (lane >> 2);
    float acc[8][4];
    #pragma unroll
    for (int i = 0; i < 8; i++)
        #pragma unroll
        for (int j = 0; j < 4; j++) acc[i][j] = 0.f;
    hmma_gemm(sb, sb + 34816, sb + 69632, sb + 104448, m0, n0, lane, acc);
    __syncthreads();

    {
        const uint4* ah = (const uint4*)(g_Wbh + (size_t)(layer*8 + 7)*17408);
        const uint4* al = (const uint4*)(g_Wbl + (size_t)(layer*8 + 7)*17408);
        uint4* d1h = (uint4*)(smc + 69632);
        uint4* d1l = (uint4*)(smc + 104448);
        for (int i = tid; i < 2176; i += 512) { d1h[i] = ah[i]; d1l[i] = al[i]; }
    }
    #pragma unroll
    for (int q = 0; q < 8; q++) {
        int idx = tid + q*512;
        int r = idx >> 5, c4 = (idx & 31)*4;
        float4 v = make_float4(0.f,0.f,0.f,0.f);
        if (row0 + r < Nn) {
            float* mp = g_msum + (size_t)(row0 + r)*128 + c4;
            v = *(const float4*)mp;
            *(float4*)mp = make_float4(0.f,0.f,0.f,0.f);
            float inv = 1.0f / fmaxf(g_deg[row0 + r], 1.0f);
            v.x *= inv; v.y *= inv; v.z *= inv; v.w *= inv;
        }
        unsigned h[4], l[4];
        split_bf16(v.x, h[0], l[0]); split_bf16(v.y, h[1], l[1]);
        split_bf16(v.z, h[2], l[2]); split_bf16(v.w, h[3], l[3]);
        unsigned off = (unsigned)(r*136 + c4)*2u;
        *(uint2*)(smc + off)         = make_uint2(h[0]|(h[1]<<16), h[2]|(h[3]<<16));
        *(uint2*)(smc + 34816 + off) = make_uint2(l[0]|(l[1]<<16), l[2]|(l[3]<<16));
    }
    __syncthreads();
    hmma_gemm(sb, sb + 34816, sb + 139264, sb + 174080, m0, n0, lane, acc);
    __syncthreads();

    #pragma unroll
    for (int s = 0; s < 8; s++) {
        int col = n0 + s*8 + (lane & 3)*2;
        float v00 = silu_f(acc[s][0] + bb[col]);
        float v01 = silu_f(acc[s][1] + bb[col+1]);
        float v10 = silu_f(acc[s][2] + bb[col]);
        float v11 = silu_f(acc[s][3] + bb[col+1]);
        unsigned h0, l0, h1, l1;
        split_bf16(v00, h0, l0); split_bf16(v01, h1, l1);
        *(unsigned*)(smc + (rl*136 + col)*2)         = h0 | (h1 << 16);
        *(unsigned*)(smc + 34816 + (rl*136 + col)*2) = l0 | (l1 << 16);
        split_bf16(v10, h0, l0); split_bf16(v11, h1, l1);
        *(unsigned*)(smc + ((rl+8)*136 + col)*2)         = h0 | (h1 << 16);
        *(unsigned*)(smc + 34816 + ((rl+8)*136 + col)*2) = l0 | (l1 << 16);
    }
    __syncthreads();
    #pragma unroll
    for (int i = 0; i < 8; i++)
        #pragma unroll
        for (int j = 0; j < 4; j++) acc[i][j] = 0.f;
    hmma_gemm(sb, sb + 34816, sb + 69632, sb + 104448, m0, n0, lane, acc);
    #pragma unroll
    for (int s = 0; s < 8; s++) {
        int col = n0 + s*8 + (lane & 3)*2;
        acc[s][0] += bb[128+col]; acc[s][1] += bb[128+col+1];
        acc[s][2] += bb[128+col]; acc[s][3] += bb[128+col+1];
        int ra = row0 + rl, rb = ra + 8;
        if (ra < Nn) *(float2*)(g_feat + (size_t)ra*128 + col) = make_float2(acc[s][0], acc[s][1]);
        if (rb < Nn) *(float2*)(g_feat + (size_t)rb*128 + col) = make_float2(acc[s][2], acc[s][3]);
    }
    if (next < 0) return;

    __syncthreads();
    {
        const char* ah = (const char*)(g_Wbh + (size_t)(next*8 + 3)*17408);
        const char* al = (const char*)(g_Wbl + (size_t)(next*8 + 3)*17408);
        const char* bh = (const char*)(g_Wbh + (size_t)(next*8 + 4)*17408);
        const char* bl = (const char*)(g_Wbl + (size_t)(next*8 + 4)*17408);
        for (int i = tid; i < 2176; i += 512) {
            asm volatile("cp.async.cg.shared.global [%0], [%1], 16;"
                :: "r"(sb + 69632u + (unsigned)i*16u), "l"(ah + (size_t)i*16) : "memory");
            asm volatile("cp.async.cg.shared.global [%0], [%1], 16;"
                :: "r"(sb + 104448u + (unsigned)i*16u), "l"(al + (size_t)i*16) : "memory");
            asm volatile("cp.async.cg.shared.global [%0], [%1], 16;"
                :: "r"(sb + 139264u + (unsigned)i*16u), "l"(bh + (size_t)i*16) : "memory");
            asm volatile("cp.async.cg.shared.global [%0], [%1], 16;"
                :: "r"(sb + 174080u + (unsigned)i*16u), "l"(bl + (size_t)i*16) : "memory");
        }
        asm volatile("cp.async.commit_group;" ::: "memory");
    }
    #pragma unroll
    for (int s = 0; s < 8; s++) {
        int col = n0 + s*8 + (lane & 3)*2;
        unsigned h0, l0, h1, l1;
        split_bf16(acc[s][0], h0, l0); split_bf16(acc[s][1], h1, l1);
        *(unsigned*)(smc + (rl*136 + col)*2)         = h0 | (h1 << 16);
        *(unsigned*)(smc + 34816 + (rl*136 + col)*2) = l0 | (l1 << 16);
        split_bf16(acc[s][2], h0, l0); split_bf16(acc[s][3], h1, l1);
        *(unsigned*)(smc + ((rl+8)*136 + col)*2)         = h0 | (h1 << 16);
        *(unsigned*)(smc + 34816 + ((rl+8)*136 + col)*2) = l0 | (l1 << 16);
    }
    asm volatile("cp.async.wait_group 0;" ::: "memory");
    __syncthreads();

    #pragma unroll
    for (int i = 0; i < 8; i++)
        #pragma unroll
        for (int j = 0; j < 4; j++) acc[i][j] = 0.f;
    hmma_gemm(sb, sb + 34816, sb + 69632, sb + 104448, m0, n0, lane, acc);
    #pragma unroll
    for (int s = 0; s < 8; s++) {
        int col = n0 + s*8 + (lane & 3)*2;
        int ra = row0 + rl, rb = ra + 8;
        if (ra < Nn) *(float2*)(g_featA + (size_t)ra*128 + col) = make_float2(acc[s][0], acc[s][1]);
        if (rb < Nn) *(float2*)(g_featA + (size_t)rb*128 + col) = make_float2(acc[s][2], acc[s][3]);
    }
    #pragma unroll
    for (int i = 0; i < 8; i++)
        #pragma unroll
        for (int j = 0; j < 4; j++) acc[i][j] = 0.f;
    hmma_gemm(sb, sb + 34816, sb + 139264, sb + 174080, m0, n0, lane, acc);
    #pragma unroll
    for (int s = 0; s < 8; s++) {
        int col = n0 + s*8 + (lane & 3)*2;
        int ra = row0 + rl, rb = ra + 8;
        if (ra < Nn) *(float2*)(g_featB + (size_t)ra*128 + col) = make_float2(acc[s][0], acc[s][1]);
        if (rb < Nn) *(float2*)(g_featB + (size_t)rb*128 + col) = make_float2(acc[s][2], acc[s][3]);
    }
}

// ============ FUSED edge kernel: Wm2 pinned, Wp1/Ws1 double-buffered ============
// bytes: Ah 0 | Al 34816 | W0h 69632 | W0l 104448 (Wm2 pinned) |
// W1h 139264 | W1l 174080 (Wp1/Ws1 cycled) | scal 208896 | bh 210944 | bhp 211456 |
// bhs 211968 | w2p 212480 | w2s 212992 | pd 214528 | ridx 218624 | cidx 219136 |
// wtl 219648 -> 222208
#define FU_SMEM 222208
__global__ void __launch_bounds__(512, 1)
edge_fused_mma(const float* __restrict__ bm2l,
               const float* __restrict__ Wm1tail, const float* __restrict__ bm1l,
               const float* __restrict__ bp1l, const float* __restrict__ Wp2l,
               const float* __restrict__ bp2l,
               const float* __restrict__ bs1l, const float* __restrict__ Ws2l,
               const float* __restrict__ bs2l, int layer) {
    extern __shared__ char smc[];
    unsigned sb = smem_u32(smc);
    float* scal = (float*)(smc + 208896);
    float* bh   = (float*)(smc + 210944);
    float* bhp  = (float*)(smc + 211456);
    float* bhs  = (float*)(smc + 211968);
    float* w2p  = (float*)(smc + 212480);
    float* w2s  = (float*)(smc + 212992);
    float* pd   = (float*)(smc + 214528);
    int* ridx   = (int*)(smc + 218624);
    int* cidx   = (int*)(smc + 219136);
    float* wtl  = (float*)(smc + 219648);
    int tid = threadIdx.x, w = tid >> 5, lane = tid & 31;

    const char* Wp1h = (const char*)(g_Wbh + (size_t)(layer*8 + 1)*17408);
    const char* Wp1l = (const char*)(g_Wbl + (size_t)(layer*8 + 1)*17408);
    const char* Ws1h = (const char*)(g_Wbh + (size_t)(layer*8 + 2)*17408);
    const char* Ws1l = (const char*)(g_Wbl + (size_t)(layer*8 + 2)*17408);

    // pin Wm2 in W0 for the whole layer
    {
        const uint4* mh = (const uint4*)(g_Wbh + (size_t)(layer*8 + 0)*17408);
        const uint4* ml = (const uint4*)(g_Wbl + (size_t)(layer*8 + 0)*17408);
        uint4* d0h = (uint4*)(smc + 69632);
        uint4* d0l = (uint4*)(smc + 104448);
        for (int i = tid; i < 2176; i += 512) { d0h[i] = mh[i]; d0l[i] = ml[i]; }
    }
    if (tid < 128) {
        bh[tid] = bm2l[tid]; bhp[tid] = bp1l[tid]; bhs[tid] = bs1l[tid];
        w2p[tid] = Wp2l[tid];
        w2s[tid*3+0] = Ws2l[tid*3+0]; w2s[tid*3+1] = Ws2l[tid*3+1]; w2s[tid*3+2] = Ws2l[tid*3+2];
    }
    for (int i = tid; i < 640; i += 512)
        wtl[i] = (i < 512) ? Wm1tail[i] : bm1l[i - 512];

    int m0 = (w & 7)*16, n0 = (w >> 3)*64;
    int chalf = w >> 3;
    int r0l = m0 + (lane >> 2), r1l = r0l + 8;

    for (int t = blockIdx.x; t < NT; t += gridDim.x) {
        int e0 = t*128;
        __syncthreads();   // prev tile fully done (A/W1/pd free), Wm2 fill visible
        // async-load Wp1 -> W1; hides under scal + h-build + GEMM1
        for (int i = tid; i < 2176; i += 512) {
            asm volatile("cp.async.cg.shared.global [%0], [%1], 16;"
                :: "r"(sb + 139264u + (unsigned)i*16u), "l"(Wp1h + (size_t)i*16) : "memory");
            asm volatile("cp.async.cg.shared.global [%0], [%1], 16;"
                :: "r"(sb + 174080u + (unsigned)i*16u), "l"(Wp1l + (size_t)i*16) : "memory");
        }
        asm volatile("cp.async.commit_group;" ::: "memory");
        if (tid < 128) {
            int r = g_er[e0 + tid], c = g_ec[e0 + tid];
            ridx[tid] = r; cidx[tid] = c;
            float dp0 = g_pos[r*3+0] - g_pos[c*3+0];
            float dp1 = g_pos[r*3+1] - g_pos[c*3+1];
            float dp2 = g_pos[r*3+2] - g_pos[c*3+2];
            float ip2 = 0.f;
            #pragma unroll
            for (int q = 4; q < 9; q++) ip2 += g_sh[r*9+q]*g_sh[c*9+q];
            scal[tid*4+0] = dp0*dp0 + dp1*dp1 + dp2*dp2;
            scal[tid*4+1] = g_sh[r*9+0]*g_sh[c*9+0];
            scal[tid*4+2] = g_sh[r*9+1]*g_sh[c*9+1] + g_sh[r*9+2]*g_sh[c*9+2] + g_sh[r*9+3]*g_sh[c*9+3];
            scal[tid*4+3] = ip2;
        }
        __syncthreads();
        #pragma unroll
        for (int q = 0; q < 8; q++) {
            int idx = tid + q*512;
            int e = idx >> 5, c4 = (idx & 31)*4;
            int r = ridx[e], c = cidx[e];
            float4 fa = *(const float4*)(g_featA + (size_t)r*128 + c4);
            float4 fb = *(const float4*)(g_featB + (size_t)c*128 + c4);
            float d2 = scal[e*4+0], i0 = scal[e*4+1], i1 = scal[e*4+2], i2 = scal[e*4+3];
            float hv[4];
            hv[0] = silu_f(fa.x + fb.x + d2*wtl[c4+0] + i0*wtl[128+c4+0] + i1*wtl[256+c4+0] + i2*wtl[384+c4+0] + wtl[512+c4+0]);
            hv[1] = silu_f(fa.y + fb.y + d2*wtl[c4+1] + i0*wtl[128+c4+1] + i1*wtl[256+c4+1] + i2*wtl[384+c4+1] + wtl[512+c4+1]);
            hv[2] = silu_f(fa.z + fb.z + d2*wtl[c4+2] + i0*wtl[128+c4+2] + i1*wtl[256+c4+2] + i2*wtl[384+c4+2] + wtl[512+c4+2]);
            hv[3] = silu_f(fa.w + fb.w + d2*wtl[c4+3] + i0*wtl[128+c4+3] + i1*wtl[256+c4+3] + i2*wtl[384+c4+3] + wtl[512+c4+3]);
            unsigned h[4], l[4];
            #pragma unroll
            for (int j = 0; j < 4; j++) split_bf16(hv[j], h[j], l[j]);
            unsigned off = (unsigned)(e*136 + c4)*2u;
            *(uint2*)(smc + off)         = make_uint2(h[0]|(h[1]<<16), h[2]|(h[3]<<16));
            *(uint2*)(smc + 34816 + off) = make_uint2(l[0]|(l[1]<<16), l[2]|(l[3]<<16));
        }
        __syncthreads();   // A(h) ready; Wm2 resident

        // GEMM1: m = h @ Wm2
        float acc[8][4];
        #pragma unroll
        for (int i = 0; i < 8; i++)
            #pragma unroll
            for (int j = 0; j < 4; j++) acc[i][j] = 0.f;
        hmma_gemm(sb, sb + 34816, sb + 69632, sb + 104448, m0, n0, lane, acc);
        __syncthreads();   // A reads done

        // m epilogue: split m directly into A (no fp32 staging)
        #pragma unroll
        for (int s = 0; s < 8; s++) {
            int col = n0 + s*8 + (lane & 3)*2;
            float v00 = silu_f(acc[s][0] + bh[col]);
            float v01 = silu_f(acc[s][1] + bh[col+1]);
            float v10 = silu_f(acc[s][2] + bh[col]);
            float v11 = silu_f(acc[s][3] + bh[col+1]);
            unsigned h0, l0, h1, l1;
            split_bf16(v00, h0, l0); split_bf16(v01, h1, l1);
            *(unsigned*)(smc + (r0l*136 + col)*2)         = h0 | (h1 << 16);
            *(unsigned*)(smc + 34816 + (r0l*136 + col)*2) = l0 | (l1 << 16);
            split_bf16(v10, h0, l0); split_bf16(v11, h1, l1);
            *(unsigned*)(smc + (r1l*136 + col)*2)         = h0 | (h1 << 16);
            *(unsigned*)(smc + 34816 + (r1l*136 + col)*2) = l0 | (l1 << 16);
        }
        asm volatile("cp.async.wait_group 0;" ::: "memory");   // Wp1 in W1
        __syncthreads();

        // GEMM2: p = m @ Wp1
        float accp[8][4];
        #pragma unroll
        for (int i = 0; i < 8; i++)
            #pragma unroll
            for (int j = 0; j < 4; j++) accp[i][j] = 0.f;
        hmma_gemm(sb, sb + 34816, sb + 139264, sb + 174080, m0, n0, lane, accp);
        __syncthreads();   // W1 reads done

        // async-load Ws1 -> W1; hides under p epilogue
        for (int i = tid; i < 2176; i += 512) {
            asm volatile("cp.async.cg.shared.global [%0], [%1], 16;"
                :: "r"(sb + 139264u + (unsigned)i*16u), "l"(Ws1h + (size_t)i*16) : "memory");
            asm volatile("cp.async.cg.shared.global [%0], [%1], 16;"
                :: "r"(sb + 174080u + (unsigned)i*16u), "l"(Ws1l + (size_t)i*16) : "memory");
        }
        asm volatile("cp.async.commit_group;" ::: "memory");
        {
            float pr0 = 0.f, pr1 = 0.f;
            #pragma unroll
            for (int s = 0; s < 8; s++) {
                int col = n0 + s*8 + (lane & 3)*2;
                pr0 = fmaf(silu_f(accp[s][0] + bhp[col]),   w2p[col],
                      fmaf(silu_f(accp[s][1] + bhp[col+1]), w2p[col+1], pr0));
                pr1 = fmaf(silu_f(accp[s][2] + bhp[col]),   w2p[col],
                      fmaf(silu_f(accp[s][3] + bhp[col+1]), w2p[col+1], pr1));
            }
            #pragma unroll
            for (int off = 1; off <= 2; off <<= 1) {
                pr0 += __shfl_xor_sync(0xffffffffu, pr0, off);
                pr1 += __shfl_xor_sync(0xffffffffu, pr1, off);
            }
            if ((lane & 3) == 0) {
                pd[chalf*512 + r0l*4 + 0] = pr0;
                pd[chalf*512 + r1l*4 + 0] = pr1;
            }
        }
        asm volatile("cp.async.wait_group 0;" ::: "memory");   // Ws1 in W1
        __syncthreads();

        // GEMM3: s = m @ Ws1
        float accs[8][4];
        #pragma unroll
        for (int i = 0; i < 8; i++)
            #pragma unroll
            for (int j = 0; j < 4; j++) accs[i][j] = 0.f;
        hmma_gemm(sb, sb + 34816, sb + 139264, sb + 174080, m0, n0, lane, accs);
        {
            float s0r0 = 0.f, s1r0 = 0.f, s2r0 = 0.f;
            float s0r1 = 0.f, s1r1 = 0.f, s2r1 = 0.f;
            #pragma unroll
            for (int s = 0; s < 8; s++) {
                int col = n0 + s*8 + (lane & 3)*2;
                float g00 = silu_f(accs[s][0] + bhs[col]);
                float g01 = silu_f(accs[s][1] + bhs[col+1]);
                float g10 = silu_f(accs[s][2] + bhs[col]);
                float g11 = silu_f(accs[s][3] + bhs[col+1]);
                s0r0 = fmaf(g00, w2s[col*3+0], fmaf(g01, w2s[(col+1)*3+0], s0r0));
                s1r0 = fmaf(g00, w2s[col*3+1], fmaf(g01, w2s[(col+1)*3+1], s1r0));
                s2r0 = fmaf(g00, w2s[col*3+2], fmaf(g01, w2s[(col+1)*3+2], s2r0));
                s0r1 = fmaf(g10, w2s[col*3+0], fmaf(g11, w2s[(col+1)*3+0], s0r1));
                s1r1 = fmaf(g10, w2s[col*3+1], fmaf(g11, w2s[(col+1)*3+1], s1r1));
                s2r1 = fmaf(g10, w2s[col*3+2], fmaf(g11, w2s[(col+1)*3+2], s2r1));
            }
            #pragma unroll
            for (int off = 1; off <= 2; off <<= 1) {
                s0r0 += __shfl_xor_sync(0xffffffffu, s0r0, off);
                s1r0 += __shfl_xor_sync(0xffffffffu, s1r0, off);
                s2r0 += __shfl_xor_sync(0xffffffffu, s2r0, off);
                s0r1 += __shfl_xor_sync(0xffffffffu, s0r1, off);
                s1r1 += __shfl_xor_sync(0xffffffffu, s1r1, off);
                s2r1 += __shfl_xor_sync(0xffffffffu, s2r1, off);
            }
            if ((lane & 3) == 0) {
                float* p0 = pd + chalf*512 + r0l*4;
                p0[1] = s0r0; p0[2] = s1r0; p0[3] = s2r0;
                float* p1 = pd + chalf*512 + r1l*4;
                p1[1] = s0r1; p1[2] = s1r1; p1[3] = s2r1;
            }
        }
        __syncthreads();
        // scatters (pd) + msum walk from split-bf16 A
        if (tid < 128) {
            int r = ridx[tid], c = cidx[tid];
            float psc = pd[tid*4+0] + pd[512 + tid*4+0] + bp2l[0];
            float s0  = pd[tid*4+1] + pd[512 + tid*4+1] + bs2l[0];
            float s1  = pd[tid*4+2] + pd[512 + tid*4+2] + bs2l[1];
            float s2  = pd[tid*4+3] + pd[512 + tid*4+3] + bs2l[2];
            float dp0 = g_pos[r*3+0] - g_pos[c*3+0];
            float dp1 = g_pos[r*3+1] - g_pos[c*3+1];
            float dp2 = g_pos[r*3+2] - g_pos[c*3+2];
            atomicAdd(&g_psum[r*3+0], dp0*psc);
            atomicAdd(&g_psum[r*3+1], dp1*psc);
            atomicAdd(&g_psum[r*3+2], dp2*psc);
            #pragma unroll
            for (int q = 0; q < 9; q++) {
                float diff = g_sh[r*9+q] - g_sh[c*9+q];
                atomicAdd(&g_ssum[r*9+q], diff * ((q == 0) ? s0 : (q < 4) ? s1 : s2));
            }
        }
        {
            int c = tid & 127, seg = tid >> 7;
            int eb = seg*32;
            float agg = 0.f;
            int ar = ridx[eb];
            for (int e = eb; e < eb + 32; e++) {
                ush hi = *(const ush*)(smc + (e*136 + c)*2);
                ush lo = *(const ush*)(smc + 34816 + (e*136 + c)*2);
                float v = __bfloat162float(__ushort_as_bfloat16(hi))
                        + __bfloat162float(__ushort_as_bfloat16(lo));
                int r = ridx[e];
                if (r != ar) { atomicAdd(&g_msum[(size_t)ar*128 + c], agg); agg = v; ar = r; }
                else agg += v;
            }
            atomicAdd(&g_msum[(size_t)ar*128 + c], agg);
        }
    }
}

// posh also zeroes psum/ssum for the next layer
__global__ void posh_kernel() {
    int i = blockIdx.x*256 + threadIdx.x;
    if (i >= Nn) return;
    float inv = 1.0f / fmaxf(g_deg[i], 1.0f);
    #pragma unroll
    for (int q = 0; q < 3; q++) {
        g_pos[i*3+q] += g_psum[i*3+q]*inv;
        g_psum[i*3+q] = 0.0f;
    }
    #pragma unroll
    for (int q = 0; q < 9; q++) {
        g_sh[i*9+q] += g_ssum[i*9+q]*inv;
        g_ssum[i*9+q] = 0.0f;
    }
}
__global__ void pool_kernel(const int* __restrict__ batch) {
    int idx = blockIdx.x*256 + threadIdx.x;
    if (idx >= Nn*140) return;
    int i = idx / 140, c = idx % 140;
    float v;
    if (c < 128)      v = g_feat[(size_t)i*128 + c];
    else if (c < 131) v = g_pos[i*3 + (c - 128)];
    else              v = g_sh[i*9 + (c - 131)];
    atomicAdd(&g_pool[batch[i]*140 + c], v);
}
__global__ void pred_kernel(const float* __restrict__ Wpred, const float* __restrict__ bpred,
                            float* __restrict__ out) {
    int g = blockIdx.x, lane = threadIdx.x;
    float s = 0.f;
    for (int c = lane; c < 140; c += 32)
        s = fmaf(g_pool[g*140 + c], Wpred[c], s);
    #pragma unroll
    for (int off = 16; off > 0; off >>= 1)
        s += __shfl_xor_sync(0xffffffffu, s, off);
    if (lane == 0) out[g] = s + bpred[0];
}

extern "C" void kernel_launch(void* const* d_in, const int* in_sizes, int n_in,
                              void* d_out, int out_size) {
    const int*   atoms = (const int*)d_in[0];
    const int*   ei    = (const int*)d_in[1];
    const int*   batch = (const int*)d_in[2];
    const float* pos   = (const float*)d_in[3];
    const float* emb   = (const float*)d_in[4];
    const float* Wsi1  = (const float*)d_in[5];  const float* bsi1  = (const float*)d_in[6];
    const float* Wsi2  = (const float*)d_in[7];  const float* bsi2  = (const float*)d_in[8];
    const float* WsiC1 = (const float*)d_in[9];  const float* bsiC1 = (const float*)d_in[10];
    const float* WsiC2 = (const float*)d_in[11]; const float* bsiC2 = (const float*)d_in[12];
    const float* Wm1   = (const float*)d_in[13]; const float* bm1   = (const float*)d_in[14];
    const float* Wm2   = (const float*)d_in[15]; const float* bm2   = (const float*)d_in[16];
    const float* Wp1   = (const float*)d_in[17]; const float* bp1   = (const float*)d_in[18];
    const float* Wp2   = (const float*)d_in[19]; const float* bp2   = (const float*)d_in[20];
    const float* Wn1   = (const float*)d_in[21]; const float* bn1   = (const float*)d_in[22];
    const float* Wn2   = (const float*)d_in[23]; const float* bn2   = (const float*)d_in[24];
    const float* Ws1   = (const float*)d_in[25]; const float* bs1   = (const float*)d_in[26];
    const float* Ws2   = (const float*)d_in[27]; const float* bs2   = (const float*)d_in[28];
    const float* Wpred = (const float*)d_in[29]; const float* bpred = (const float*)d_in[30];
    float* out = (float*)d_out;

    cudaFuncSetAttribute(featab_mma, cudaFuncAttributeMaxDynamicSharedMemorySize, FABM_SMEM);
    cudaFuncSetAttribute(nodeup_mma, cudaFuncAttributeMaxDynamicSharedMemorySize, NUM_SMEM);
    cudaFuncSetAttribute(edge_fused_mma, cudaFuncAttributeMaxDynamicSharedMemorySize, FU_SMEM);

    void *p_msum, *p_psum, *p_ssum, *p_deg, *p_com, *p_cnt, *p_pool, *p_pos, *p_cur;
    cudaGetSymbolAddress(&p_msum, g_msum);
    cudaGetSymbolAddress(&p_psum, g_psum);
    cudaGetSymbolAddress(&p_ssum, g_ssum);
    cudaGetSymbolAddress(&p_deg,  g_deg);
    cudaGetSymbolAddress(&p_com,  g_com);
    cudaGetSymbolAddress(&p_cnt,  g_cnt);
    cudaGetSymbolAddress(&p_pool, g_pool);
    cudaGetSymbolAddress(&p_pos,  g_pos);
    cudaGetSymbolAddress(&p_cur,  g_cursor);

    cudaMemsetAsync(p_deg,  0, Nn*4, 0);
    cudaMemsetAsync(p_com,  0, Gg*3*4, 0);
    cudaMemsetAsync(p_cnt,  0, Gg*4, 0);
    cudaMemsetAsync(p_ssum, 0, Nn*9*4, 0);
    cudaMemsetAsync(p_psum, 0, Nn*3*4, 0);
    cudaMemsetAsync(p_msum, 0, (size_t)Nn*128*4, 0);
    cudaMemsetAsync(p_pool, 0, Gg*140*4, 0);
    cudaMemsetAsync(p_cur,  0, Nn*4, 0);
    cudaMemcpyAsync(p_pos, pos, Nn*3*4, cudaMemcpyDeviceToDevice, 0);

    wprep_kernel<<<40, 256>>>(Wm2, Wp1, Ws1, Wm1, Wn1, Wn2);
    node_init_kernel<<<(Nn*128)/256, 256>>>(atoms, emb);
    com_kernel<<<(Nn + 255)/256, 256>>>(batch);
    deg_kernel<<<(Ee + 255)/256, 256>>>(ei);
    scan_kernel<<<1, 256>>>();
    sortscatter_kernel<<<(Ee + 255)/256, 256>>>(ei);
    vocab_kernel<<<10, 128>>>(emb, Wsi1, WsiC1, bsiC1, WsiC2, bsiC2);
    edge_init_kernel<<<Ee/8, 256>>>(atoms, Wsi1, bsi1, Wsi2, bsi2);
    sh_init_kernel<<<(Nn + 255)/256, 256>>>(atoms, batch);

    int gridNM = (Nn + 127)/128;   // 79

    featab_mma<<<gridNM, 512, FABM_SMEM>>>(0);

    for (int l = 0; l < Ll; l++) {
        edge_fused_mma<<<148, 512, FU_SMEM>>>(
            bm2 + l*128,
            Wm1 + ((size_t)l*260 + 256)*128, bm1 + l*128,
            bp1 + l*128, Wp2 + l*128, bp2 + l,
            bs1 + l*128, Ws2 + l*384, bs2 + l*3, l);

        posh_kernel<<<(Nn + 255)/256, 256>>>();

        nodeup_mma<<<gridNM, 512, NUM_SMEM>>>(bn1 + l*128, bn2 + l*128, l,
                                              (l + 1 < Ll) ? (l + 1) : -1);
    }

    pool_kernel<<<(Nn*140 + 255)/256, 256>>>(batch);
    pred_kernel<<<Gg, 32>>>(Wpred, bpred, out);
}